// round 9
// baseline (speedup 1.0000x reference)
#include <cuda_runtime.h>
#include <cuda_bf16.h>
#include <cstdint>

typedef unsigned long long ull_t;

// ---------- packed fp32x2 helpers ----------
__device__ __forceinline__ ull_t pk2(float x, float y){
    ull_t r; asm("mov.b64 %0, {%1,%2};" : "=l"(r) : "f"(x), "f"(y)); return r;
}
__device__ __forceinline__ void fma2(ull_t &d, ull_t a, ull_t b){
    asm("fma.rn.f32x2 %0, %1, %2, %0;" : "+l"(d) : "l"(a), "l"(b));
}
__device__ __forceinline__ float2 upk2(ull_t v){
    float lo, hi; asm("mov.b64 {%0,%1}, %2;" : "=f"(lo), "=f"(hi) : "l"(v));
    return make_float2(lo, hi);
}
__device__ __forceinline__ float elup1(float x){ return x > 0.f ? x + 1.f : __expf(x); }

#define FMA8x4(ACCROW, AV, B01, B23) do { ull_t ad_ = pk2((AV),(AV)); \
    fma2((ACCROW)[0], ad_, (B01).x); fma2((ACCROW)[1], ad_, (B01).y); \
    fma2((ACCROW)[2], ad_, (B23).x); fma2((ACCROW)[3], ad_, (B23).y); } while(0)

// ---------- warp MMA / async helpers ----------
__device__ __forceinline__ uint32_t smem_u32(const void* p){
    uint32_t a;
    asm("{ .reg .u64 t; cvta.to.shared.u64 t, %1; cvt.u32.u64 %0, t; }" : "=r"(a) : "l"(p));
    return a;
}
__device__ __forceinline__ void cpa16(uint32_t smaddr, const void* g){
    asm volatile("cp.async.cg.shared.global [%0], [%1], 16;" :: "r"(smaddr), "l"(g));
}
#define CP_COMMIT() asm volatile("cp.async.commit_group;" ::: "memory")
#define CP_WAIT1()  asm volatile("cp.async.wait_group 1;" ::: "memory")
__device__ __forceinline__ void ldsm_x4(uint32_t &r0, uint32_t &r1, uint32_t &r2, uint32_t &r3, uint32_t addr){
    asm volatile("ldmatrix.sync.aligned.m8n8.x4.shared.b16 {%0,%1,%2,%3}, [%4];"
        : "=r"(r0), "=r"(r1), "=r"(r2), "=r"(r3) : "r"(addr));
}
__device__ __forceinline__ void ldsm_x2(uint32_t &r0, uint32_t &r1, uint32_t addr){
    asm volatile("ldmatrix.sync.aligned.m8n8.x2.shared.b16 {%0,%1}, [%2];"
        : "=r"(r0), "=r"(r1) : "r"(addr));
}
__device__ __forceinline__ void ldsm_x2t(uint32_t &r0, uint32_t &r1, uint32_t addr){
    asm volatile("ldmatrix.sync.aligned.m8n8.x2.trans.shared.b16 {%0,%1}, [%2];"
        : "=r"(r0), "=r"(r1) : "r"(addr));
}
__device__ __forceinline__ void mma16816(float &c0, float &c1, float &c2, float &c3,
                                         uint32_t a0, uint32_t a1, uint32_t a2, uint32_t a3,
                                         uint32_t b0, uint32_t b1){
    asm volatile("mma.sync.aligned.m16n8k16.row.col.f32.bf16.bf16.f32 "
        "{%0,%1,%2,%3}, {%4,%5,%6,%7}, {%8,%9}, {%0,%1,%2,%3};"
        : "+f"(c0), "+f"(c1), "+f"(c2), "+f"(c3)
        : "r"(a0), "r"(a1), "r"(a2), "r"(a3), "r"(b0), "r"(b1));
}
__device__ __forceinline__ void mma1688tf(float &c0, float &c1, float &c2, float &c3,
                                          uint32_t a0, uint32_t a1, uint32_t a2, uint32_t a3,
                                          uint32_t b0, uint32_t b1){
    asm volatile("mma.sync.aligned.m16n8k8.row.col.f32.tf32.tf32.f32 "
        "{%0,%1,%2,%3}, {%4,%5,%6,%7}, {%8,%9}, {%0,%1,%2,%3};"
        : "+f"(c0), "+f"(c1), "+f"(c2), "+f"(c3)
        : "r"(a0), "r"(a1), "r"(a2), "r"(a3), "r"(b0), "r"(b1));
}
__device__ __forceinline__ float cvt_tf32(float x){
    float r; asm("cvt.rna.tf32.f32 %0, %1;" : "=f"(r) : "f"(x)); return r;
}
__device__ __forceinline__ uint32_t swu(int u, int r){ return (uint32_t)((u & 8) | ((u & 7) ^ (r & 7))); }
__device__ __forceinline__ uint32_t packh(float a, float b){
    __nv_bfloat162 t = __halves2bfloat162(__float2bfloat16_rn(a), __float2bfloat16_rn(b));
    return *(uint32_t*)&t;
}
__device__ __forceinline__ void bsplit2(__nv_bfloat16* H, __nv_bfloat16* L, size_t off, float2 v){
    __nv_bfloat16 hx = __float2bfloat16_rn(v.x), hy = __float2bfloat16_rn(v.y);
    __nv_bfloat16 lx = __float2bfloat16_rn(v.x - __bfloat162float(hx));
    __nv_bfloat16 ly = __float2bfloat16_rn(v.y - __bfloat162float(hy));
    *(__nv_bfloat162*)(H + off) = __halves2bfloat162(hx, hy);
    *(__nv_bfloat162*)(L + off) = __halves2bfloat162(lx, ly);
}
__device__ __forceinline__ float4 ld4hl(const __nv_bfloat16* H, const __nv_bfloat16* L, size_t off){
    uint2 h = *(const uint2*)(H + off), l = *(const uint2*)(L + off);
    float2 fh0 = __bfloat1622float2(*(__nv_bfloat162*)&h.x);
    float2 fh1 = __bfloat1622float2(*(__nv_bfloat162*)&h.y);
    float2 fl0 = __bfloat1622float2(*(__nv_bfloat162*)&l.x);
    float2 fl1 = __bfloat1622float2(*(__nv_bfloat162*)&l.y);
    return make_float4(fh0.x + fl0.x, fh0.y + fl0.y, fh1.x + fl1.x, fh1.y + fl1.y);
}

// ---------- dims: B=4, S=8192, D=1024, H=8, dk=dv=128, SEG=512, nseg=16 ----------

// ---------- device scratch ----------
__device__ float g_P[8388608];
__device__ float g_Zseg[65536];
__device__ float g_Z[65536];
__device__ float g_Xt[33554432];     // x pre-rounded to tf32
__device__ float g_Wt[3145728];      // W^T pre-rounded to tf32, [which][n][k]
__device__ __nv_bfloat16 g_Qh[33554432];
__device__ __nv_bfloat16 g_Ql[33554432];
__device__ __nv_bfloat16 g_Kh[33554432];
__device__ __nv_bfloat16 g_Kl[33554432];
__device__ __nv_bfloat16 g_Vh[33554432];
__device__ __nv_bfloat16 g_Vl[33554432];
__device__ __nv_bfloat16 g_Memh[8388608];
__device__ __nv_bfloat16 g_Meml[8388608];

// =====================================================================
// S1: X -> tf32-rounded fp32
// =====================================================================
__global__ __launch_bounds__(256) void k_prepX(const float* __restrict__ x)
{
    size_t i = ((size_t)blockIdx.x * 256 + threadIdx.x) * 4;
    float4 v = *(const float4*)(x + i);
    v.x = cvt_tf32(v.x); v.y = cvt_tf32(v.y);
    v.z = cvt_tf32(v.z); v.w = cvt_tf32(v.w);
    *(float4*)(g_Xt + i) = v;
}

// =====================================================================
// S2: transpose W[k][n] -> Wt[n][k], tf32-rounded
// =====================================================================
__global__ __launch_bounds__(256) void k_trW(const float* __restrict__ w, int which)
{
    __shared__ float t[32][33];
    const int bx = blockIdx.x << 5, by = blockIdx.y << 5;
    const int tx = threadIdx.x & 31, ty = threadIdx.x >> 5;
#pragma unroll
    for (int r = 0; r < 4; ++r)
        t[ty * 4 + r][tx] = w[(size_t)(by + ty * 4 + r) * 1024 + bx + tx];
    __syncthreads();
    float* Wt = g_Wt + (size_t)which * 1048576;
#pragma unroll
    for (int r = 0; r < 4; ++r) {
        int n = bx + ty * 4 + r, k = by + tx;
        Wt[(size_t)n * 1024 + k] = cvt_tf32(t[tx][ty * 4 + r]);
    }
}

// =====================================================================
// K1: fused projection GEMM, SINGLE-PASS tf32 mma (m16n8k8).
//     512 thr, 16 warps (4x4, warp tile 32x32), cp.async 3-stage.
//     Tiles fp32 [128][64] padded to ld=68 (conflict-free LDS.32 frags).
// =====================================================================
__global__ __launch_bounds__(512, 1) void k_proj_mma(const float* __restrict__ bq,
                                                     const float* __restrict__ bk,
                                                     const float* __restrict__ bv)
{
    extern __shared__ __align__(128) char sm_raw[];
    const uint32_t smbase = smem_u32(sm_raw);

    const int which = blockIdx.z;
    const float* bias = (which == 0) ? bq : ((which == 1) ? bk : bv);
    __nv_bfloat16* Hd = (which == 0) ? g_Qh : ((which == 1) ? g_Kh : g_Vh);
    __nv_bfloat16* Ld = (which == 0) ? g_Ql : ((which == 1) ? g_Kl : g_Vl);
    const float* Wt = g_Wt + (size_t)which * 1048576;

    const int tid = threadIdx.x, lane = tid & 31, wid = tid >> 5;
    const int wm = (wid >> 2) * 32, wn = (wid & 3) * 32;
    const int row0 = blockIdx.y << 7, col0 = blockIdx.x << 7;

    const int g4 = lane >> 2, t4 = lane & 3;      // groupID, threadID_in_group
    const int aRow = wm + g4;                     // + mt*16 (+8 for a1/a3)
    const int bRow = wn + g4;                     // + nt*8

    // loader: 512 threads; row = tid>>2 (128), 4 x 16B per tile per thread
    const int pr = tid >> 2, pu = tid & 3;

    float cf[2][4][4];
#pragma unroll
    for (int mt = 0; mt < 2; ++mt)
#pragma unroll
        for (int nt = 0; nt < 4; ++nt)
#pragma unroll
            for (int q = 0; q < 4; ++q) cf[mt][nt][q] = 0.f;

    // stage layout: X tile 128*272B = 34816, W tile 34816 -> 69632/stage
    auto load_chunk = [&](int c, int stage) {
        const int k0 = c << 6;
        const uint32_t stX = smbase + stage * 69632;
        const uint32_t stW = stX + 34816;
        const float* gx = g_Xt + (size_t)(row0 + pr) * 1024 + k0 + pu * 4;
        const float* gw = Wt + (size_t)(col0 + pr) * 1024 + k0 + pu * 4;
        const uint32_t so = pr * 272 + pu * 16;
#pragma unroll
        for (int i = 0; i < 4; ++i) {
            cpa16(stX + so + i * 64, gx + i * 16);
            cpa16(stW + so + i * 64, gw + i * 16);
        }
    };

    load_chunk(0, 0); CP_COMMIT();
    load_chunk(1, 1); CP_COMMIT();

    for (int c = 0; c < 16; ++c) {
        CP_WAIT1();
        __syncthreads();
        if (c + 2 < 16) load_chunk(c + 2, (c + 2) % 3);
        CP_COMMIT();
        const float* Xs = (const float*)(sm_raw + (c % 3) * 69632);
        const float* Ws = Xs + 8704;   // 34816 B
#pragma unroll
        for (int ks = 0; ks < 8; ++ks) {
            uint32_t a[2][4], bb[4][2];
            const int kc = ks * 8 + t4;
#pragma unroll
            for (int mt = 0; mt < 2; ++mt) {
                const float* p = Xs + (aRow + mt * 16) * 68 + kc;
                a[mt][0] = __float_as_uint(p[0]);
                a[mt][1] = __float_as_uint(p[8 * 68]);
                a[mt][2] = __float_as_uint(p[4]);
                a[mt][3] = __float_as_uint(p[8 * 68 + 4]);
            }
#pragma unroll
            for (int nt = 0; nt < 4; ++nt) {
                const float* p = Ws + (bRow + nt * 8) * 68 + kc;
                bb[nt][0] = __float_as_uint(p[0]);
                bb[nt][1] = __float_as_uint(p[4]);
            }
#pragma unroll
            for (int nt = 0; nt < 4; ++nt)
#pragma unroll
                for (int mt = 0; mt < 2; ++mt)
                    mma1688tf(cf[mt][nt][0], cf[mt][nt][1], cf[mt][nt][2], cf[mt][nt][3],
                              a[mt][0], a[mt][1], a[mt][2], a[mt][3],
                              bb[nt][0], bb[nt][1]);
        }
    }

    // epilogue: bias + bf16 hi/lo splits
#pragma unroll
    for (int mt = 0; mt < 2; ++mt) {
        const int r0 = row0 + wm + mt * 16 + g4;
#pragma unroll
        for (int nt = 0; nt < 4; ++nt) {
            const int ccol = col0 + wn + nt * 8 + (t4 << 1);
            const float2 bvv = *(const float2*)&bias[ccol];
            float2 v0 = make_float2(cf[mt][nt][0] + bvv.x, cf[mt][nt][1] + bvv.y);
            float2 v1 = make_float2(cf[mt][nt][2] + bvv.x, cf[mt][nt][3] + bvv.y);
            size_t o0 = (size_t)r0 * 1024 + ccol;
            size_t o1 = o0 + 8 * 1024;
            bsplit2(Hd, Ld, o0, v0);
            bsplit2(Hd, Ld, o1, v1);
        }
    }
}

// =====================================================================
// K2: per (b,h,seg): P = (elu(K)+1)^T @ V  [128x128], Zseg = 512*colsum
// =====================================================================
__global__ __launch_bounds__(256) void k_kvouter()
{
    const int idx = blockIdx.x;
    const int b = idx >> 7, h = (idx >> 4) & 7, seg = idx & 15;
    __shared__ __align__(16) float sks[16][128];
    __shared__ __align__(16) float vvs[16][128];
    const int tid = threadIdx.x, tx = tid & 15, ty = tid >> 4;
    const int lr = tid >> 5, c4 = (tid & 31) << 2;

    ull_t acc[8][4];
#pragma unroll
    for (int i = 0; i < 8; ++i)
#pragma unroll
        for (int j = 0; j < 4; ++j) acc[i][j] = 0ull;
    float zacc[8] = {0.f,0.f,0.f,0.f,0.f,0.f,0.f,0.f};

    const size_t rowbase = (size_t)(b * 8192 + seg * 512) * 1024 + h * 128;

    for (int l0 = 0; l0 < 512; l0 += 16) {
        float4 k0v = ld4hl(g_Kh, g_Kl, rowbase + (size_t)(l0 + lr) * 1024 + c4);
        float4 k1v = ld4hl(g_Kh, g_Kl, rowbase + (size_t)(l0 + lr + 8) * 1024 + c4);
        float4 v0v = ld4hl(g_Vh, g_Vl, rowbase + (size_t)(l0 + lr) * 1024 + c4);
        float4 v1v = ld4hl(g_Vh, g_Vl, rowbase + (size_t)(l0 + lr + 8) * 1024 + c4);
        k0v.x = elup1(k0v.x); k0v.y = elup1(k0v.y); k0v.z = elup1(k0v.z); k0v.w = elup1(k0v.w);
        k1v.x = elup1(k1v.x); k1v.y = elup1(k1v.y); k1v.z = elup1(k1v.z); k1v.w = elup1(k1v.w);
        __syncthreads();
        *(float4*)&sks[lr][c4]     = k0v;
        *(float4*)&sks[lr + 8][c4] = k1v;
        *(float4*)&vvs[lr][c4]     = v0v;
        *(float4*)&vvs[lr + 8][c4] = v1v;
        __syncthreads();
#pragma unroll
        for (int l = 0; l < 16; ++l) {
            float4 a0 = *(const float4*)&sks[l][ty * 8];
            float4 a1 = *(const float4*)&sks[l][ty * 8 + 4];
            ulonglong2 b01 = *(const ulonglong2*)&vvs[l][tx * 8];
            ulonglong2 b23 = *(const ulonglong2*)&vvs[l][tx * 8 + 4];
            if (tx == 0) {
                zacc[0] += a0.x; zacc[1] += a0.y; zacc[2] += a0.z; zacc[3] += a0.w;
                zacc[4] += a1.x; zacc[5] += a1.y; zacc[6] += a1.z; zacc[7] += a1.w;
            }
            FMA8x4(acc[0], a0.x, b01, b23);
            FMA8x4(acc[1], a0.y, b01, b23);
            FMA8x4(acc[2], a0.z, b01, b23);
            FMA8x4(acc[3], a0.w, b01, b23);
            FMA8x4(acc[4], a1.x, b01, b23);
            FMA8x4(acc[5], a1.y, b01, b23);
            FMA8x4(acc[6], a1.z, b01, b23);
            FMA8x4(acc[7], a1.w, b01, b23);
        }
    }
    const size_t pbase = (size_t)idx * 16384;
#pragma unroll
    for (int i = 0; i < 8; ++i) {
        size_t rb = pbase + (size_t)(ty * 8 + i) * 128 + tx * 8;
#pragma unroll
        for (int jp = 0; jp < 4; ++jp) {
            float2 v = upk2(acc[i][jp]);
            g_P[rb + jp * 2]     = v.x;
            g_P[rb + jp * 2 + 1] = v.y;
        }
    }
    if (tx == 0) {
#pragma unroll
        for (int i = 0; i < 8; ++i)
            g_Zseg[idx * 128 + ty * 8 + i] = 512.f * zacc[i];
    }
}

// =====================================================================
// K3: inclusive prefix over seg; writes bf16 hi/lo Mem splits + Z
// =====================================================================
__global__ __launch_bounds__(256) void k_prefix()
{
    const int bh = blockIdx.x;
    const int tid = threadIdx.x;
    float acc[64];
#pragma unroll
    for (int u = 0; u < 64; ++u) acc[u] = 0.f;
    float zacc = 0.f;
    for (int seg = 0; seg < 16; ++seg) {
        const size_t base = ((size_t)bh * 16 + seg) * 16384;
#pragma unroll
        for (int u = 0; u < 64; ++u) {
            acc[u] += g_P[base + u * 256 + tid];
            float v = acc[u];
            __nv_bfloat16 h = __float2bfloat16_rn(v);
            __nv_bfloat16 l = __float2bfloat16_rn(v - __bfloat162float(h));
            g_Memh[base + u * 256 + tid] = h;
            g_Meml[base + u * 256 + tid] = l;
        }
        if (tid < 128) {
            zacc += g_Zseg[(bh * 16 + seg) * 128 + tid];
            g_Z[(bh * 16 + seg) * 128 + tid] = zacc;
        }
    }
}

// =====================================================================
// K4: mma.sync attention. CTA=(b,seg,qt64), 8 warps, loops 8 heads.
// =====================================================================
__global__ __launch_bounds__(256, 1) void k_attn_mma(const float* __restrict__ beta,
                                                     float* __restrict__ out)
{
    extern __shared__ __align__(16) char smraw[];
    float* Sc = (float*)smraw;                       // 132096 B
    char* sAh = smraw + 132096;                      // 16384
    char* sAl = sAh + 16384;                         // 16384
    char* sBh = sAl + 16384;                         // 32768
    char* sBl = sBh + 32768;                         // 32768
    float* zs  = (float*)(sBl + 32768);              // 128
    float* rs  = zs + 128;                           // 64
    float* den = rs + 64;                            // 64
    const uint32_t aAh = smem_u32(sAh), aAl = smem_u32(sAl);
    const uint32_t aBh = smem_u32(sBh), aBl = smem_u32(sBl);

    const int idx = blockIdx.x;                      // b*128 + seg*8 + qt
    const int b = idx >> 7, seg = (idx >> 3) & 15, qt = idx & 7;
    const int tid = threadIdx.x, lane = tid & 31, wid = tid >> 5;
    const int wm2 = (wid >> 2) * 32, wn2 = (wid & 3) * 32;
    const int qrow0 = b * 8192 + seg * 512 + qt * 64;
    const int krow0 = b * 8192 + seg * 512;
    const float bsig = 1.f / (1.f + __expf(-beta[0]));
    const float bsig8 = bsig * 0.125f, obsig8 = (1.f - bsig) * 0.125f;
    const float scale = 0.088388347648318447f;

    const int rowA0 = wm2 + (lane & 15);
    const int unA = lane >> 4;
    const int rowBn = wn2 + (lane & 7);
    const int unB = (lane >> 3) & 1;
    const int rowKt = (lane & 7) + ((lane >> 3) & 1) * 8;
    const int srow = tid >> 2, spart = tid & 3;

    float facc[2][4][4];
#pragma unroll
    for (int mt = 0; mt < 2; ++mt)
#pragma unroll
        for (int nt = 0; nt < 4; ++nt)
#pragma unroll
            for (int q = 0; q < 4; ++q) facc[mt][nt][q] = 0.f;

    for (int h = 0; h < 8; ++h) {
        const int hc = h * 128;
        __syncthreads();
#pragma unroll
        for (int it = 0; it < 4; ++it) {
            int i2 = it * 256 + tid;
            int r = i2 >> 4, u = i2 & 15;
            size_t gs = (size_t)(qrow0 + r) * 1024 + hc + u * 8;
            uint32_t so = r * 256 + (swu(u, r) << 4);
            *(uint4*)(sAh + so) = *(const uint4*)(g_Qh + gs);
            *(uint4*)(sAl + so) = *(const uint4*)(g_Ql + gs);
        }
        if (tid < 128)
            zs[tid] = g_Z[((size_t)(b * 8 + h) * 16 + seg) * 128 + tid];

        // ---- scores: 4 key chunks of 128 ----
        for (int kc = 0; kc < 4; ++kc) {
            __syncthreads();
#pragma unroll
            for (int it = 0; it < 8; ++it) {
                int i2 = it * 256 + tid;
                int r = i2 >> 4, u = i2 & 15;
                size_t gs = (size_t)(krow0 + kc * 128 + r) * 1024 + hc + u * 8;
                uint32_t so = r * 256 + (swu(u, r) << 4);
                *(uint4*)(sBh + so) = *(const uint4*)(g_Kh + gs);
                *(uint4*)(sBl + so) = *(const uint4*)(g_Kl + gs);
            }
            __syncthreads();
            float acc[2][4][4];
#pragma unroll
            for (int mt = 0; mt < 2; ++mt)
#pragma unroll
                for (int nt = 0; nt < 4; ++nt)
#pragma unroll
                    for (int q = 0; q < 4; ++q) acc[mt][nt][q] = 0.f;
            for (int pass = 0; pass < 3; ++pass) {
                const uint32_t Ab = (pass < 2) ? aAh : aAl;
                const uint32_t Bb = (pass == 1) ? aBl : aBh;
#pragma unroll
                for (int ks = 0; ks < 8; ++ks) {
                    uint32_t af[2][4], bfr[4][2];
#pragma unroll
                    for (int mt = 0; mt < 2; ++mt)
                        ldsm_x4(af[mt][0], af[mt][1], af[mt][2], af[mt][3],
                                Ab + (rowA0 + mt * 16) * 256 + (swu(ks * 2 + unA, rowA0) << 4));
#pragma unroll
                    for (int nt = 0; nt < 4; ++nt)
                        ldsm_x2(bfr[nt][0], bfr[nt][1],
                                Bb + (rowBn + nt * 8) * 256 + (swu(ks * 2 + unB, rowBn) << 4));
#pragma unroll
                    for (int nt = 0; nt < 4; ++nt)
#pragma unroll
                        for (int mt = 0; mt < 2; ++mt)
                            mma16816(acc[mt][nt][0], acc[mt][nt][1], acc[mt][nt][2], acc[mt][nt][3],
                                     af[mt][0], af[mt][1], af[mt][2], af[mt][3],
                                     bfr[nt][0], bfr[nt][1]);
                }
            }
#pragma unroll
            for (int mt = 0; mt < 2; ++mt) {
                int r0 = wm2 + mt * 16 + (lane >> 2);
#pragma unroll
                for (int nt = 0; nt < 4; ++nt) {
                    int cc = kc * 128 + wn2 + nt * 8 + ((lane & 3) << 1);
                    *(float2*)&Sc[r0 * 516 + cc]       = make_float2(acc[mt][nt][0] * scale, acc[mt][nt][1] * scale);
                    *(float2*)&Sc[(r0 + 8) * 516 + cc] = make_float2(acc[mt][nt][2] * scale, acc[mt][nt][3] * scale);
                }
            }
        }
        __syncthreads();
        // ---- softmax ----
        {
            float* rowp = &Sc[srow * 516 + spart * 128];
            float m = -1e30f;
#pragma unroll 8
            for (int j = 0; j < 128; ++j) m = fmaxf(m, rowp[j]);
            m = fmaxf(m, __shfl_xor_sync(0xffffffffu, m, 1));
            m = fmaxf(m, __shfl_xor_sync(0xffffffffu, m, 2));
            float s = 0.f;
#pragma unroll 8
            for (int j = 0; j < 128; ++j) { float e = __expf(rowp[j] - m); rowp[j] = e; s += e; }
            s += __shfl_xor_sync(0xffffffffu, s, 1);
            s += __shfl_xor_sync(0xffffffffu, s, 2);
            if (spart == 0) rs[srow] = s;
        }
        // ---- sq transform + exact den ----
        {
            float da = 0.f;
#pragma unroll 4
            for (int j = 0; j < 32; ++j) {
                int c = spart * 32 + j;
                uint32_t bo = srow * 256 + (swu(c >> 3, srow) << 4) + ((c & 7) << 1);
                float qh = __bfloat162float(*(__nv_bfloat16*)(sAh + bo));
                float ql = __bfloat162float(*(__nv_bfloat16*)(sAl + bo));
                float sq = elup1(qh + ql);
                da += sq * zs[c];
                __nv_bfloat16 hh = __float2bfloat16_rn(sq);
                __nv_bfloat16 ll = __float2bfloat16_rn(sq - __bfloat162float(hh));
                *(__nv_bfloat16*)(sAh + bo) = hh;
                *(__nv_bfloat16*)(sAl + bo) = ll;
            }
            da += __shfl_xor_sync(0xffffffffu, da, 1);
            da += __shfl_xor_sync(0xffffffffu, da, 2);
            if (spart == 0) den[srow] = da;
        }
        __syncthreads();
        // ---- retrieval ----
#pragma unroll
        for (int it = 0; it < 8; ++it) {
            int i2 = it * 256 + tid;
            int r = i2 >> 4, u = i2 & 15;
            size_t ms = ((size_t)(b * 8 + h) * 16 + seg) * 16384 + r * 128 + u * 8;
            uint32_t so = r * 256 + (swu(u, r) << 4);
            *(uint4*)(sBh + so) = *(const uint4*)(g_Memh + ms);
            *(uint4*)(sBl + so) = *(const uint4*)(g_Meml + ms);
        }
        __syncthreads();
        {
            float acc[2][4][4];
#pragma unroll
            for (int mt = 0; mt < 2; ++mt)
#pragma unroll
                for (int nt = 0; nt < 4; ++nt)
#pragma unroll
                    for (int q = 0; q < 4; ++q) acc[mt][nt][q] = 0.f;
            for (int pass = 0; pass < 3; ++pass) {
                const uint32_t Ab = (pass < 2) ? aAh : aAl;
                const uint32_t Bb = (pass == 1) ? aBl : aBh;
#pragma unroll
                for (int ks = 0; ks < 8; ++ks) {
                    uint32_t af[2][4], bfr[4][2];
#pragma unroll
                    for (int mt = 0; mt < 2; ++mt)
                        ldsm_x4(af[mt][0], af[mt][1], af[mt][2], af[mt][3],
                                Ab + (rowA0 + mt * 16) * 256 + (swu(ks * 2 + unA, rowA0) << 4));
                    int rK = ks * 16 + rowKt;
#pragma unroll
                    for (int nt = 0; nt < 4; ++nt)
                        ldsm_x2t(bfr[nt][0], bfr[nt][1],
                                 Bb + rK * 256 + (swu((wn2 >> 3) + nt, rK) << 4));
#pragma unroll
                    for (int nt = 0; nt < 4; ++nt)
#pragma unroll
                        for (int mt = 0; mt < 2; ++mt)
                            mma16816(acc[mt][nt][0], acc[mt][nt][1], acc[mt][nt][2], acc[mt][nt][3],
                                     af[mt][0], af[mt][1], af[mt][2], af[mt][3],
                                     bfr[nt][0], bfr[nt][1]);
                }
            }
#pragma unroll
            for (int mt = 0; mt < 2; ++mt) {
                int r0 = wm2 + mt * 16 + (lane >> 2);
                float m0 = bsig8 / (den[r0] + 1e-5f);
                float m1 = bsig8 / (den[r0 + 8] + 1e-5f);
#pragma unroll
                for (int nt = 0; nt < 4; ++nt) {
                    facc[mt][nt][0] += acc[mt][nt][0] * m0;
                    facc[mt][nt][1] += acc[mt][nt][1] * m0;
                    facc[mt][nt][2] += acc[mt][nt][2] * m1;
                    facc[mt][nt][3] += acc[mt][nt][3] * m1;
                }
            }
        }
        // ---- PV ----
        float dacc[2][4][4];
#pragma unroll
        for (int mt = 0; mt < 2; ++mt)
#pragma unroll
            for (int nt = 0; nt < 4; ++nt)
#pragma unroll
                for (int q = 0; q < 4; ++q) dacc[mt][nt][q] = 0.f;
        for (int kc = 0; kc < 4; ++kc) {
            __syncthreads();
#pragma unroll
            for (int it = 0; it < 4; ++it) {
                int i2 = it * 256 + tid;
                int r = i2 >> 4, u = i2 & 15;
                const float* sp = &Sc[r * 516 + kc * 128 + u * 8];
                float4 p0 = *(const float4*)sp, p1 = *(const float4*)(sp + 4);
                uint4 hi, lo;
                hi.x = packh(p0.x, p0.y); hi.y = packh(p0.z, p0.w);
                hi.z = packh(p1.x, p1.y); hi.w = packh(p1.z, p1.w);
                lo.x = packh(p0.x - __bfloat162float(__float2bfloat16_rn(p0.x)),
                             p0.y - __bfloat162float(__float2bfloat16_rn(p0.y)));
                lo.y = packh(p0.z - __bfloat162float(__float2bfloat16_rn(p0.z)),
                             p0.w - __bfloat162float(__float2bfloat16_rn(p0.w)));
                lo.z = packh(p1.x - __bfloat162float(__float2bfloat16_rn(p1.x)),
                             p1.y - __bfloat162float(__float2bfloat16_rn(p1.y)));
                lo.w = packh(p1.z - __bfloat162float(__float2bfloat16_rn(p1.z)),
                             p1.w - __bfloat162float(__float2bfloat16_rn(p1.w)));
                uint32_t so = r * 256 + (swu(u, r) << 4);
                *(uint4*)(sAh + so) = hi;
                *(uint4*)(sAl + so) = lo;
            }
#pragma unroll
            for (int it = 0; it < 8; ++it) {
                int i2 = it * 256 + tid;
                int r = i2 >> 4, u = i2 & 15;
                size_t gs = (size_t)(krow0 + kc * 128 + r) * 1024 + hc + u * 8;
                uint32_t so = r * 256 + (swu(u, r) << 4);
                *(uint4*)(sBh + so) = *(const uint4*)(g_Vh + gs);
                *(uint4*)(sBl + so) = *(const uint4*)(g_Vl + gs);
            }
            __syncthreads();
            for (int pass = 0; pass < 3; ++pass) {
                const uint32_t Ab = (pass < 2) ? aAh : aAl;
                const uint32_t Bb = (pass == 1) ? aBl : aBh;
#pragma unroll
                for (int ks = 0; ks < 8; ++ks) {
                    uint32_t af[2][4], bfr[4][2];
#pragma unroll
                    for (int mt = 0; mt < 2; ++mt)
                        ldsm_x4(af[mt][0], af[mt][1], af[mt][2], af[mt][3],
                                Ab + (rowA0 + mt * 16) * 256 + (swu(ks * 2 + unA, rowA0) << 4));
                    int rK = ks * 16 + rowKt;
#pragma unroll
                    for (int nt = 0; nt < 4; ++nt)
                        ldsm_x2t(bfr[nt][0], bfr[nt][1],
                                 Bb + rK * 256 + (swu((wn2 >> 3) + nt, rK) << 4));
#pragma unroll
                    for (int nt = 0; nt < 4; ++nt)
#pragma unroll
                        for (int mt = 0; mt < 2; ++mt)
                            mma16816(dacc[mt][nt][0], dacc[mt][nt][1], dacc[mt][nt][2], dacc[mt][nt][3],
                                     af[mt][0], af[mt][1], af[mt][2], af[mt][3],
                                     bfr[nt][0], bfr[nt][1]);
                }
            }
        }
#pragma unroll
        for (int mt = 0; mt < 2; ++mt) {
            int r0 = wm2 + mt * 16 + (lane >> 2);
            float d0 = obsig8 / rs[r0];
            float d1 = obsig8 / rs[r0 + 8];
#pragma unroll
            for (int nt = 0; nt < 4; ++nt) {
                facc[mt][nt][0] += dacc[mt][nt][0] * d0;
                facc[mt][nt][1] += dacc[mt][nt][1] * d0;
                facc[mt][nt][2] += dacc[mt][nt][2] * d1;
                facc[mt][nt][3] += dacc[mt][nt][3] * d1;
            }
        }
    }

#pragma unroll
    for (int mt = 0; mt < 2; ++mt) {
        int r0 = wm2 + mt * 16 + (lane >> 2);
#pragma unroll
        for (int nt = 0; nt < 4; ++nt) {
            int col = wn2 + nt * 8 + ((lane & 3) << 1);
            *(float2*)&out[(size_t)(qrow0 + r0) * 128 + col]     = make_float2(facc[mt][nt][0], facc[mt][nt][1]);
            *(float2*)&out[(size_t)(qrow0 + r0 + 8) * 128 + col] = make_float2(facc[mt][nt][2], facc[mt][nt][3]);
        }
    }
}

// =====================================================================
extern "C" void kernel_launch(void* const* d_in, const int* in_sizes, int n_in,
                              void* d_out, int out_size)
{
    const float* x    = (const float*)d_in[0];
    const float* wq   = (const float*)d_in[1];
    const float* bq   = (const float*)d_in[2];
    const float* wk   = (const float*)d_in[3];
    const float* bk   = (const float*)d_in[4];
    const float* wv   = (const float*)d_in[5];
    const float* bv   = (const float*)d_in[6];
    const float* beta = (const float*)d_in[7];
    float* out = (float*)d_out;

    static int attr_set = 0;
    if (!attr_set) {
        cudaFuncSetAttribute(k_attn_mma, cudaFuncAttributeMaxDynamicSharedMemorySize, 231424);
        cudaFuncSetAttribute(k_proj_mma, cudaFuncAttributeMaxDynamicSharedMemorySize, 208896);
        attr_set = 1;
    }

    k_prepX<<<32768, 256>>>(x);
    k_trW<<<dim3(32, 32), 256>>>(wq, 0);
    k_trW<<<dim3(32, 32), 256>>>(wk, 1);
    k_trW<<<dim3(32, 32), 256>>>(wv, 2);
    k_proj_mma<<<dim3(8, 256, 3), 512, 208896>>>(bq, bk, bv);
    k_kvouter<<<512, 256>>>();
    k_prefix<<<32, 256>>>();
    k_attn_mma<<<512, 256, 231424>>>(beta, out);
}

// round 10
// speedup vs baseline: 1.1840x; 1.1840x over previous
#include <cuda_runtime.h>
#include <cuda_bf16.h>
#include <cuda_fp16.h>
#include <cstdint>

typedef unsigned long long ull_t;

// ---------- packed fp32x2 helpers ----------
__device__ __forceinline__ ull_t pk2(float x, float y){
    ull_t r; asm("mov.b64 %0, {%1,%2};" : "=l"(r) : "f"(x), "f"(y)); return r;
}
__device__ __forceinline__ void fma2(ull_t &d, ull_t a, ull_t b){
    asm("fma.rn.f32x2 %0, %1, %2, %0;" : "+l"(d) : "l"(a), "l"(b));
}
__device__ __forceinline__ float2 upk2(ull_t v){
    float lo, hi; asm("mov.b64 {%0,%1}, %2;" : "=f"(lo), "=f"(hi) : "l"(v));
    return make_float2(lo, hi);
}
__device__ __forceinline__ float elup1(float x){ return x > 0.f ? x + 1.f : __expf(x); }

#define FMA8x4(ACCROW, AV, B01, B23) do { ull_t ad_ = pk2((AV),(AV)); \
    fma2((ACCROW)[0], ad_, (B01).x); fma2((ACCROW)[1], ad_, (B01).y); \
    fma2((ACCROW)[2], ad_, (B23).x); fma2((ACCROW)[3], ad_, (B23).y); } while(0)

// ---------- warp MMA / async helpers ----------
__device__ __forceinline__ uint32_t smem_u32(const void* p){
    uint32_t a;
    asm("{ .reg .u64 t; cvta.to.shared.u64 t, %1; cvt.u32.u64 %0, t; }" : "=r"(a) : "l"(p));
    return a;
}
__device__ __forceinline__ void cpa16(uint32_t smaddr, const void* g){
    asm volatile("cp.async.cg.shared.global [%0], [%1], 16;" :: "r"(smaddr), "l"(g));
}
#define CP_COMMIT() asm volatile("cp.async.commit_group;" ::: "memory")
#define CP_WAIT1()  asm volatile("cp.async.wait_group 1;" ::: "memory")
__device__ __forceinline__ void ldsm_x4(uint32_t &r0, uint32_t &r1, uint32_t &r2, uint32_t &r3, uint32_t addr){
    asm volatile("ldmatrix.sync.aligned.m8n8.x4.shared.b16 {%0,%1,%2,%3}, [%4];"
        : "=r"(r0), "=r"(r1), "=r"(r2), "=r"(r3) : "r"(addr));
}
__device__ __forceinline__ void ldsm_x2(uint32_t &r0, uint32_t &r1, uint32_t addr){
    asm volatile("ldmatrix.sync.aligned.m8n8.x2.shared.b16 {%0,%1}, [%2];"
        : "=r"(r0), "=r"(r1) : "r"(addr));
}
__device__ __forceinline__ void ldsm_x2t(uint32_t &r0, uint32_t &r1, uint32_t addr){
    asm volatile("ldmatrix.sync.aligned.m8n8.x2.trans.shared.b16 {%0,%1}, [%2];"
        : "=r"(r0), "=r"(r1) : "r"(addr));
}
__device__ __forceinline__ void mma16816(float &c0, float &c1, float &c2, float &c3,
                                         uint32_t a0, uint32_t a1, uint32_t a2, uint32_t a3,
                                         uint32_t b0, uint32_t b1){
    asm volatile("mma.sync.aligned.m16n8k16.row.col.f32.bf16.bf16.f32 "
        "{%0,%1,%2,%3}, {%4,%5,%6,%7}, {%8,%9}, {%0,%1,%2,%3};"
        : "+f"(c0), "+f"(c1), "+f"(c2), "+f"(c3)
        : "r"(a0), "r"(a1), "r"(a2), "r"(a3), "r"(b0), "r"(b1));
}
__device__ __forceinline__ void mma16816h(float &c0, float &c1, float &c2, float &c3,
                                          uint32_t a0, uint32_t a1, uint32_t a2, uint32_t a3,
                                          uint32_t b0, uint32_t b1){
    asm volatile("mma.sync.aligned.m16n8k16.row.col.f32.f16.f16.f32 "
        "{%0,%1,%2,%3}, {%4,%5,%6,%7}, {%8,%9}, {%0,%1,%2,%3};"
        : "+f"(c0), "+f"(c1), "+f"(c2), "+f"(c3)
        : "r"(a0), "r"(a1), "r"(a2), "r"(a3), "r"(b0), "r"(b1));
}
__device__ __forceinline__ uint32_t swu(int u, int r){ return (uint32_t)((u & 8) | ((u & 7) ^ (r & 7))); }
__device__ __forceinline__ uint32_t packh(float a, float b){
    __nv_bfloat162 t = __halves2bfloat162(__float2bfloat16_rn(a), __float2bfloat16_rn(b));
    return *(uint32_t*)&t;
}
__device__ __forceinline__ void bsplit2(__nv_bfloat16* H, __nv_bfloat16* L, size_t off, float2 v){
    __nv_bfloat16 hx = __float2bfloat16_rn(v.x), hy = __float2bfloat16_rn(v.y);
    __nv_bfloat16 lx = __float2bfloat16_rn(v.x - __bfloat162float(hx));
    __nv_bfloat16 ly = __float2bfloat16_rn(v.y - __bfloat162float(hy));
    *(__nv_bfloat162*)(H + off) = __halves2bfloat162(hx, hy);
    *(__nv_bfloat162*)(L + off) = __halves2bfloat162(lx, ly);
}
__device__ __forceinline__ float4 ld4hl(const __nv_bfloat16* H, const __nv_bfloat16* L, size_t off){
    uint2 h = *(const uint2*)(H + off), l = *(const uint2*)(L + off);
    float2 fh0 = __bfloat1622float2(*(__nv_bfloat162*)&h.x);
    float2 fh1 = __bfloat1622float2(*(__nv_bfloat162*)&h.y);
    float2 fl0 = __bfloat1622float2(*(__nv_bfloat162*)&l.x);
    float2 fl1 = __bfloat1622float2(*(__nv_bfloat162*)&l.y);
    return make_float4(fh0.x + fl0.x, fh0.y + fl0.y, fh1.x + fl1.x, fh1.y + fl1.y);
}

// ---------- dims: B=4, S=8192, D=1024, H=8, dk=dv=128, SEG=512, nseg=16 ----------

// ---------- device scratch ----------
__device__ float g_P[8388608];
__device__ float g_Zseg[65536];
__device__ float g_Z[65536];
__device__ __half g_Xh[33554432];    // fp16 split of x (hi)
__device__ __half g_Xl[33554432];    // fp16 split of x (lo)
__device__ __half g_Wh[3145728];     // W^T fp16, [which][n][k]
__device__ __nv_bfloat16 g_Qh[33554432];
__device__ __nv_bfloat16 g_Ql[33554432];
__device__ __nv_bfloat16 g_Kh[33554432];
__device__ __nv_bfloat16 g_Kl[33554432];
__device__ __nv_bfloat16 g_Vh[33554432];
__device__ __nv_bfloat16 g_Vl[33554432];
__device__ __nv_bfloat16 g_Memh[8388608];
__device__ __nv_bfloat16 g_Meml[8388608];

// =====================================================================
// S1: split X into fp16 hi/lo
// =====================================================================
__global__ __launch_bounds__(256) void k_splitX(const float* __restrict__ x)
{
    size_t i = ((size_t)blockIdx.x * 256 + threadIdx.x) * 4;
    float4 v = *(const float4*)(x + i);
    __half hx = __float2half_rn(v.x), hy = __float2half_rn(v.y);
    __half hz = __float2half_rn(v.z), hw = __float2half_rn(v.w);
    __half lx = __float2half_rn(v.x - __half2float(hx));
    __half ly = __float2half_rn(v.y - __half2float(hy));
    __half lz = __float2half_rn(v.z - __half2float(hz));
    __half lw = __float2half_rn(v.w - __half2float(hw));
    *(__half2*)(g_Xh + i)     = __halves2half2(hx, hy);
    *(__half2*)(g_Xh + i + 2) = __halves2half2(hz, hw);
    *(__half2*)(g_Xl + i)     = __halves2half2(lx, ly);
    *(__half2*)(g_Xl + i + 2) = __halves2half2(lz, lw);
}

// =====================================================================
// S2: transpose W[k][n] -> Wt[n][k], fp16
// =====================================================================
__global__ __launch_bounds__(256) void k_trW(const float* __restrict__ w, int which)
{
    __shared__ float t[32][33];
    const int bx = blockIdx.x << 5, by = blockIdx.y << 5;
    const int tx = threadIdx.x & 31, ty = threadIdx.x >> 5;
#pragma unroll
    for (int r = 0; r < 4; ++r)
        t[ty * 4 + r][tx] = w[(size_t)(by + ty * 4 + r) * 1024 + bx + tx];
    __syncthreads();
    __half* Wt = g_Wh + (size_t)which * 1048576;
#pragma unroll
    for (int r = 0; r < 4; ++r) {
        int n = bx + ty * 4 + r, k = by + tx;
        Wt[(size_t)n * 1024 + k] = __float2half_rn(t[tx][ty * 4 + r]);
    }
}

// =====================================================================
// K1: fused projection GEMM, fp16 asymmetric 2-pass (XhWh + XlWh).
//     512 thr, 16 warps (4x4, warp tile 32x32), cp.async 3-stage,
//     3 tiles/chunk (Xh, Xl, Wh) = 48KB/stage.
// =====================================================================
__global__ __launch_bounds__(512, 1) void k_proj_mma(const float* __restrict__ bq,
                                                     const float* __restrict__ bk,
                                                     const float* __restrict__ bv)
{
    extern __shared__ __align__(128) char sm_raw[];
    const uint32_t smbase = smem_u32(sm_raw);

    const int which = blockIdx.z;
    const float* bias = (which == 0) ? bq : ((which == 1) ? bk : bv);
    __nv_bfloat16* Hd = (which == 0) ? g_Qh : ((which == 1) ? g_Kh : g_Vh);
    __nv_bfloat16* Ld = (which == 0) ? g_Ql : ((which == 1) ? g_Kl : g_Vl);
    const __half* Wt = g_Wh + (size_t)which * 1048576;

    const int tid = threadIdx.x, lane = tid & 31, wid = tid >> 5;
    const int wm = (wid >> 2) * 32, wn = (wid & 3) * 32;
    const int row0 = blockIdx.y << 7, col0 = blockIdx.x << 7;

    const int rowA = wm + (lane & 15);
    const int rA7 = rowA & 7;
    const int unA = lane >> 4;
    const int rowB = wn + (lane & 7);
    const int rB7 = lane & 7;
    const int unB = (lane >> 3) & 1;

    // loader: rows lr + {0,64}, unit lu (16B)
    const int lr = tid >> 3, lu = tid & 7;

    float cf[2][4][4];
#pragma unroll
    for (int mt = 0; mt < 2; ++mt)
#pragma unroll
        for (int nt = 0; nt < 4; ++nt)
#pragma unroll
            for (int q = 0; q < 4; ++q) cf[mt][nt][q] = 0.f;

    // stage: Xh @0, Xl @16384, Wh @32768 -> 49152 B/stage
    auto load_chunk = [&](int c, int stage) {
        const int k0 = c << 6;
        const uint32_t st = smbase + stage * 49152;
#pragma unroll
        for (int it = 0; it < 2; ++it) {
            int r = lr + it * 64;
            size_t ga = (size_t)(row0 + r) * 1024 + k0 + lu * 8;
            size_t gb = (size_t)(col0 + r) * 1024 + k0 + lu * 8;
            uint32_t so = r * 128 + ((lu ^ (r & 7)) << 4);
            cpa16(st + so,         g_Xh + ga);
            cpa16(st + 16384 + so, g_Xl + ga);
            cpa16(st + 32768 + so, Wt + gb);
        }
    };

    load_chunk(0, 0); CP_COMMIT();
    load_chunk(1, 1); CP_COMMIT();

    for (int c = 0; c < 16; ++c) {
        CP_WAIT1();
        __syncthreads();
        if (c + 2 < 16) load_chunk(c + 2, (c + 2) % 3);
        CP_COMMIT();
        const uint32_t st = smbase + (c % 3) * 49152;
#pragma unroll
        for (int ks = 0; ks < 4; ++ks) {
            uint32_t ah[2][4], al[2][4], bh[4][2];
#pragma unroll
            for (int mt = 0; mt < 2; ++mt) {
                uint32_t off = (rowA + mt * 16) * 128 + ((((ks << 1) + unA) ^ rA7) << 4);
                ldsm_x4(ah[mt][0], ah[mt][1], ah[mt][2], ah[mt][3], st + off);
                ldsm_x4(al[mt][0], al[mt][1], al[mt][2], al[mt][3], st + 16384 + off);
            }
#pragma unroll
            for (int nt = 0; nt < 4; ++nt) {
                uint32_t off = (rowB + nt * 8) * 128 + ((((ks << 1) + unB) ^ rB7) << 4);
                ldsm_x2(bh[nt][0], bh[nt][1], st + 32768 + off);
            }
#pragma unroll
            for (int nt = 0; nt < 4; ++nt)
#pragma unroll
                for (int mt = 0; mt < 2; ++mt)
                    mma16816h(cf[mt][nt][0], cf[mt][nt][1], cf[mt][nt][2], cf[mt][nt][3],
                              ah[mt][0], ah[mt][1], ah[mt][2], ah[mt][3], bh[nt][0], bh[nt][1]);
#pragma unroll
            for (int nt = 0; nt < 4; ++nt)
#pragma unroll
                for (int mt = 0; mt < 2; ++mt)
                    mma16816h(cf[mt][nt][0], cf[mt][nt][1], cf[mt][nt][2], cf[mt][nt][3],
                              al[mt][0], al[mt][1], al[mt][2], al[mt][3], bh[nt][0], bh[nt][1]);
        }
    }

    // epilogue: bias + bf16 hi/lo splits
#pragma unroll
    for (int mt = 0; mt < 2; ++mt) {
        const int r0 = row0 + wm + mt * 16 + (lane >> 2);
#pragma unroll
        for (int nt = 0; nt < 4; ++nt) {
            const int ccol = col0 + wn + nt * 8 + ((lane & 3) << 1);
            const float2 bvv = *(const float2*)&bias[ccol];
            float2 v0 = make_float2(cf[mt][nt][0] + bvv.x, cf[mt][nt][1] + bvv.y);
            float2 v1 = make_float2(cf[mt][nt][2] + bvv.x, cf[mt][nt][3] + bvv.y);
            size_t o0 = (size_t)r0 * 1024 + ccol;
            size_t o1 = o0 + 8 * 1024;
            bsplit2(Hd, Ld, o0, v0);
            bsplit2(Hd, Ld, o1, v1);
        }
    }
}

// =====================================================================
// K2: per (b,h,seg): P = (elu(K)+1)^T @ V  [128x128], Zseg = 512*colsum
// =====================================================================
__global__ __launch_bounds__(256) void k_kvouter()
{
    const int idx = blockIdx.x;
    const int b = idx >> 7, h = (idx >> 4) & 7, seg = idx & 15;
    __shared__ __align__(16) float sks[16][128];
    __shared__ __align__(16) float vvs[16][128];
    const int tid = threadIdx.x, tx = tid & 15, ty = tid >> 4;
    const int lr = tid >> 5, c4 = (tid & 31) << 2;

    ull_t acc[8][4];
#pragma unroll
    for (int i = 0; i < 8; ++i)
#pragma unroll
        for (int j = 0; j < 4; ++j) acc[i][j] = 0ull;
    float zacc[8] = {0.f,0.f,0.f,0.f,0.f,0.f,0.f,0.f};

    const size_t rowbase = (size_t)(b * 8192 + seg * 512) * 1024 + h * 128;

    for (int l0 = 0; l0 < 512; l0 += 16) {
        float4 k0v = ld4hl(g_Kh, g_Kl, rowbase + (size_t)(l0 + lr) * 1024 + c4);
        float4 k1v = ld4hl(g_Kh, g_Kl, rowbase + (size_t)(l0 + lr + 8) * 1024 + c4);
        float4 v0v = ld4hl(g_Vh, g_Vl, rowbase + (size_t)(l0 + lr) * 1024 + c4);
        float4 v1v = ld4hl(g_Vh, g_Vl, rowbase + (size_t)(l0 + lr + 8) * 1024 + c4);
        k0v.x = elup1(k0v.x); k0v.y = elup1(k0v.y); k0v.z = elup1(k0v.z); k0v.w = elup1(k0v.w);
        k1v.x = elup1(k1v.x); k1v.y = elup1(k1v.y); k1v.z = elup1(k1v.z); k1v.w = elup1(k1v.w);
        __syncthreads();
        *(float4*)&sks[lr][c4]     = k0v;
        *(float4*)&sks[lr + 8][c4] = k1v;
        *(float4*)&vvs[lr][c4]     = v0v;
        *(float4*)&vvs[lr + 8][c4] = v1v;
        __syncthreads();
#pragma unroll
        for (int l = 0; l < 16; ++l) {
            float4 a0 = *(const float4*)&sks[l][ty * 8];
            float4 a1 = *(const float4*)&sks[l][ty * 8 + 4];
            ulonglong2 b01 = *(const ulonglong2*)&vvs[l][tx * 8];
            ulonglong2 b23 = *(const ulonglong2*)&vvs[l][tx * 8 + 4];
            if (tx == 0) {
                zacc[0] += a0.x; zacc[1] += a0.y; zacc[2] += a0.z; zacc[3] += a0.w;
                zacc[4] += a1.x; zacc[5] += a1.y; zacc[6] += a1.z; zacc[7] += a1.w;
            }
            FMA8x4(acc[0], a0.x, b01, b23);
            FMA8x4(acc[1], a0.y, b01, b23);
            FMA8x4(acc[2], a0.z, b01, b23);
            FMA8x4(acc[3], a0.w, b01, b23);
            FMA8x4(acc[4], a1.x, b01, b23);
            FMA8x4(acc[5], a1.y, b01, b23);
            FMA8x4(acc[6], a1.z, b01, b23);
            FMA8x4(acc[7], a1.w, b01, b23);
        }
    }
    const size_t pbase = (size_t)idx * 16384;
#pragma unroll
    for (int i = 0; i < 8; ++i) {
        size_t rb = pbase + (size_t)(ty * 8 + i) * 128 + tx * 8;
#pragma unroll
        for (int jp = 0; jp < 4; ++jp) {
            float2 v = upk2(acc[i][jp]);
            g_P[rb + jp * 2]     = v.x;
            g_P[rb + jp * 2 + 1] = v.y;
        }
    }
    if (tx == 0) {
#pragma unroll
        for (int i = 0; i < 8; ++i)
            g_Zseg[idx * 128 + ty * 8 + i] = 512.f * zacc[i];
    }
}

// =====================================================================
// K3: inclusive prefix over seg; writes bf16 hi/lo Mem splits + Z
// =====================================================================
__global__ __launch_bounds__(256) void k_prefix()
{
    const int bh = blockIdx.x;
    const int tid = threadIdx.x;
    float acc[64];
#pragma unroll
    for (int u = 0; u < 64; ++u) acc[u] = 0.f;
    float zacc = 0.f;
    for (int seg = 0; seg < 16; ++seg) {
        const size_t base = ((size_t)bh * 16 + seg) * 16384;
#pragma unroll
        for (int u = 0; u < 64; ++u) {
            acc[u] += g_P[base + u * 256 + tid];
            float v = acc[u];
            __nv_bfloat16 h = __float2bfloat16_rn(v);
            __nv_bfloat16 l = __float2bfloat16_rn(v - __bfloat162float(h));
            g_Memh[base + u * 256 + tid] = h;
            g_Meml[base + u * 256 + tid] = l;
        }
        if (tid < 128) {
            zacc += g_Zseg[(bh * 16 + seg) * 128 + tid];
            g_Z[(bh * 16 + seg) * 128 + tid] = zacc;
        }
    }
}

// =====================================================================
// K4: mma.sync attention. CTA=(b,seg,qt64), 8 warps, loops 8 heads.
// =====================================================================
__global__ __launch_bounds__(256, 1) void k_attn_mma(const float* __restrict__ beta,
                                                     float* __restrict__ out)
{
    extern __shared__ __align__(16) char smraw[];
    float* Sc = (float*)smraw;                       // 132096 B
    char* sAh = smraw + 132096;                      // 16384
    char* sAl = sAh + 16384;                         // 16384
    char* sBh = sAl + 16384;                         // 32768
    char* sBl = sBh + 32768;                         // 32768
    float* zs  = (float*)(sBl + 32768);              // 128
    float* rs  = zs + 128;                           // 64
    float* den = rs + 64;                            // 64
    const uint32_t aAh = smem_u32(sAh), aAl = smem_u32(sAl);
    const uint32_t aBh = smem_u32(sBh), aBl = smem_u32(sBl);

    const int idx = blockIdx.x;                      // b*128 + seg*8 + qt
    const int b = idx >> 7, seg = (idx >> 3) & 15, qt = idx & 7;
    const int tid = threadIdx.x, lane = tid & 31, wid = tid >> 5;
    const int wm2 = (wid >> 2) * 32, wn2 = (wid & 3) * 32;
    const int qrow0 = b * 8192 + seg * 512 + qt * 64;
    const int krow0 = b * 8192 + seg * 512;
    const float bsig = 1.f / (1.f + __expf(-beta[0]));
    const float bsig8 = bsig * 0.125f, obsig8 = (1.f - bsig) * 0.125f;
    const float scale = 0.088388347648318447f;

    const int rowA0 = wm2 + (lane & 15);
    const int unA = lane >> 4;
    const int rowBn = wn2 + (lane & 7);
    const int unB = (lane >> 3) & 1;
    const int rowKt = (lane & 7) + ((lane >> 3) & 1) * 8;
    const int srow = tid >> 2, spart = tid & 3;

    float facc[2][4][4];
#pragma unroll
    for (int mt = 0; mt < 2; ++mt)
#pragma unroll
        for (int nt = 0; nt < 4; ++nt)
#pragma unroll
            for (int q = 0; q < 4; ++q) facc[mt][nt][q] = 0.f;

    for (int h = 0; h < 8; ++h) {
        const int hc = h * 128;
        __syncthreads();
#pragma unroll
        for (int it = 0; it < 4; ++it) {
            int i2 = it * 256 + tid;
            int r = i2 >> 4, u = i2 & 15;
            size_t gs = (size_t)(qrow0 + r) * 1024 + hc + u * 8;
            uint32_t so = r * 256 + (swu(u, r) << 4);
            *(uint4*)(sAh + so) = *(const uint4*)(g_Qh + gs);
            *(uint4*)(sAl + so) = *(const uint4*)(g_Ql + gs);
        }
        if (tid < 128)
            zs[tid] = g_Z[((size_t)(b * 8 + h) * 16 + seg) * 128 + tid];

        // ---- scores: 4 key chunks of 128 ----
        for (int kc = 0; kc < 4; ++kc) {
            __syncthreads();
#pragma unroll
            for (int it = 0; it < 8; ++it) {
                int i2 = it * 256 + tid;
                int r = i2 >> 4, u = i2 & 15;
                size_t gs = (size_t)(krow0 + kc * 128 + r) * 1024 + hc + u * 8;
                uint32_t so = r * 256 + (swu(u, r) << 4);
                *(uint4*)(sBh + so) = *(const uint4*)(g_Kh + gs);
                *(uint4*)(sBl + so) = *(const uint4*)(g_Kl + gs);
            }
            __syncthreads();
            float acc[2][4][4];
#pragma unroll
            for (int mt = 0; mt < 2; ++mt)
#pragma unroll
                for (int nt = 0; nt < 4; ++nt)
#pragma unroll
                    for (int q = 0; q < 4; ++q) acc[mt][nt][q] = 0.f;
            for (int pass = 0; pass < 3; ++pass) {
                const uint32_t Ab = (pass < 2) ? aAh : aAl;
                const uint32_t Bb = (pass == 1) ? aBl : aBh;
#pragma unroll
                for (int ks = 0; ks < 8; ++ks) {
                    uint32_t af[2][4], bfr[4][2];
#pragma unroll
                    for (int mt = 0; mt < 2; ++mt)
                        ldsm_x4(af[mt][0], af[mt][1], af[mt][2], af[mt][3],
                                Ab + (rowA0 + mt * 16) * 256 + (swu(ks * 2 + unA, rowA0) << 4));
#pragma unroll
                    for (int nt = 0; nt < 4; ++nt)
                        ldsm_x2(bfr[nt][0], bfr[nt][1],
                                Bb + (rowBn + nt * 8) * 256 + (swu(ks * 2 + unB, rowBn) << 4));
#pragma unroll
                    for (int nt = 0; nt < 4; ++nt)
#pragma unroll
                        for (int mt = 0; mt < 2; ++mt)
                            mma16816(acc[mt][nt][0], acc[mt][nt][1], acc[mt][nt][2], acc[mt][nt][3],
                                     af[mt][0], af[mt][1], af[mt][2], af[mt][3],
                                     bfr[nt][0], bfr[nt][1]);
                }
            }
#pragma unroll
            for (int mt = 0; mt < 2; ++mt) {
                int r0 = wm2 + mt * 16 + (lane >> 2);
#pragma unroll
                for (int nt = 0; nt < 4; ++nt) {
                    int cc = kc * 128 + wn2 + nt * 8 + ((lane & 3) << 1);
                    *(float2*)&Sc[r0 * 516 + cc]       = make_float2(acc[mt][nt][0] * scale, acc[mt][nt][1] * scale);
                    *(float2*)&Sc[(r0 + 8) * 516 + cc] = make_float2(acc[mt][nt][2] * scale, acc[mt][nt][3] * scale);
                }
            }
        }
        __syncthreads();
        // ---- softmax ----
        {
            float* rowp = &Sc[srow * 516 + spart * 128];
            float m = -1e30f;
#pragma unroll 8
            for (int j = 0; j < 128; ++j) m = fmaxf(m, rowp[j]);
            m = fmaxf(m, __shfl_xor_sync(0xffffffffu, m, 1));
            m = fmaxf(m, __shfl_xor_sync(0xffffffffu, m, 2));
            float s = 0.f;
#pragma unroll 8
            for (int j = 0; j < 128; ++j) { float e = __expf(rowp[j] - m); rowp[j] = e; s += e; }
            s += __shfl_xor_sync(0xffffffffu, s, 1);
            s += __shfl_xor_sync(0xffffffffu, s, 2);
            if (spart == 0) rs[srow] = s;
        }
        // ---- sq transform + exact den ----
        {
            float da = 0.f;
#pragma unroll 4
            for (int j = 0; j < 32; ++j) {
                int c = spart * 32 + j;
                uint32_t bo = srow * 256 + (swu(c >> 3, srow) << 4) + ((c & 7) << 1);
                float qh = __bfloat162float(*(__nv_bfloat16*)(sAh + bo));
                float ql = __bfloat162float(*(__nv_bfloat16*)(sAl + bo));
                float sq = elup1(qh + ql);
                da += sq * zs[c];
                __nv_bfloat16 hh = __float2bfloat16_rn(sq);
                __nv_bfloat16 ll = __float2bfloat16_rn(sq - __bfloat162float(hh));
                *(__nv_bfloat16*)(sAh + bo) = hh;
                *(__nv_bfloat16*)(sAl + bo) = ll;
            }
            da += __shfl_xor_sync(0xffffffffu, da, 1);
            da += __shfl_xor_sync(0xffffffffu, da, 2);
            if (spart == 0) den[srow] = da;
        }
        __syncthreads();
        // ---- retrieval ----
#pragma unroll
        for (int it = 0; it < 8; ++it) {
            int i2 = it * 256 + tid;
            int r = i2 >> 4, u = i2 & 15;
            size_t ms = ((size_t)(b * 8 + h) * 16 + seg) * 16384 + r * 128 + u * 8;
            uint32_t so = r * 256 + (swu(u, r) << 4);
            *(uint4*)(sBh + so) = *(const uint4*)(g_Memh + ms);
            *(uint4*)(sBl + so) = *(const uint4*)(g_Meml + ms);
        }
        __syncthreads();
        {
            float acc[2][4][4];
#pragma unroll
            for (int mt = 0; mt < 2; ++mt)
#pragma unroll
                for (int nt = 0; nt < 4; ++nt)
#pragma unroll
                    for (int q = 0; q < 4; ++q) acc[mt][nt][q] = 0.f;
            for (int pass = 0; pass < 3; ++pass) {
                const uint32_t Ab = (pass < 2) ? aAh : aAl;
                const uint32_t Bb = (pass == 1) ? aBl : aBh;
#pragma unroll
                for (int ks = 0; ks < 8; ++ks) {
                    uint32_t af[2][4], bfr[4][2];
#pragma unroll
                    for (int mt = 0; mt < 2; ++mt)
                        ldsm_x4(af[mt][0], af[mt][1], af[mt][2], af[mt][3],
                                Ab + (rowA0 + mt * 16) * 256 + (swu(ks * 2 + unA, rowA0) << 4));
                    int rK = ks * 16 + rowKt;
#pragma unroll
                    for (int nt = 0; nt < 4; ++nt)
                        ldsm_x2t(bfr[nt][0], bfr[nt][1],
                                 Bb + rK * 256 + (swu((wn2 >> 3) + nt, rK) << 4));
#pragma unroll
                    for (int nt = 0; nt < 4; ++nt)
#pragma unroll
                        for (int mt = 0; mt < 2; ++mt)
                            mma16816(acc[mt][nt][0], acc[mt][nt][1], acc[mt][nt][2], acc[mt][nt][3],
                                     af[mt][0], af[mt][1], af[mt][2], af[mt][3],
                                     bfr[nt][0], bfr[nt][1]);
                }
            }
#pragma unroll
            for (int mt = 0; mt < 2; ++mt) {
                int r0 = wm2 + mt * 16 + (lane >> 2);
                float m0 = bsig8 / (den[r0] + 1e-5f);
                float m1 = bsig8 / (den[r0 + 8] + 1e-5f);
#pragma unroll
                for (int nt = 0; nt < 4; ++nt) {
                    facc[mt][nt][0] += acc[mt][nt][0] * m0;
                    facc[mt][nt][1] += acc[mt][nt][1] * m0;
                    facc[mt][nt][2] += acc[mt][nt][2] * m1;
                    facc[mt][nt][3] += acc[mt][nt][3] * m1;
                }
            }
        }
        // ---- PV ----
        float dacc[2][4][4];
#pragma unroll
        for (int mt = 0; mt < 2; ++mt)
#pragma unroll
            for (int nt = 0; nt < 4; ++nt)
#pragma unroll
                for (int q = 0; q < 4; ++q) dacc[mt][nt][q] = 0.f;
        for (int kc = 0; kc < 4; ++kc) {
            __syncthreads();
#pragma unroll
            for (int it = 0; it < 4; ++it) {
                int i2 = it * 256 + tid;
                int r = i2 >> 4, u = i2 & 15;
                const float* sp = &Sc[r * 516 + kc * 128 + u * 8];
                float4 p0 = *(const float4*)sp, p1 = *(const float4*)(sp + 4);
                uint4 hi, lo;
                hi.x = packh(p0.x, p0.y); hi.y = packh(p0.z, p0.w);
                hi.z = packh(p1.x, p1.y); hi.w = packh(p1.z, p1.w);
                lo.x = packh(p0.x - __bfloat162float(__float2bfloat16_rn(p0.x)),
                             p0.y - __bfloat162float(__float2bfloat16_rn(p0.y)));
                lo.y = packh(p0.z - __bfloat162float(__float2bfloat16_rn(p0.z)),
                             p0.w - __bfloat162float(__float2bfloat16_rn(p0.w)));
                lo.z = packh(p1.x - __bfloat162float(__float2bfloat16_rn(p1.x)),
                             p1.y - __bfloat162float(__float2bfloat16_rn(p1.y)));
                lo.w = packh(p1.z - __bfloat162float(__float2bfloat16_rn(p1.z)),
                             p1.w - __bfloat162float(__float2bfloat16_rn(p1.w)));
                uint32_t so = r * 256 + (swu(u, r) << 4);
                *(uint4*)(sAh + so) = hi;
                *(uint4*)(sAl + so) = lo;
            }
#pragma unroll
            for (int it = 0; it < 8; ++it) {
                int i2 = it * 256 + tid;
                int r = i2 >> 4, u = i2 & 15;
                size_t gs = (size_t)(krow0 + kc * 128 + r) * 1024 + hc + u * 8;
                uint32_t so = r * 256 + (swu(u, r) << 4);
                *(uint4*)(sBh + so) = *(const uint4*)(g_Vh + gs);
                *(uint4*)(sBl + so) = *(const uint4*)(g_Vl + gs);
            }
            __syncthreads();
            for (int pass = 0; pass < 3; ++pass) {
                const uint32_t Ab = (pass < 2) ? aAh : aAl;
                const uint32_t Bb = (pass == 1) ? aBl : aBh;
#pragma unroll
                for (int ks = 0; ks < 8; ++ks) {
                    uint32_t af[2][4], bfr[4][2];
#pragma unroll
                    for (int mt = 0; mt < 2; ++mt)
                        ldsm_x4(af[mt][0], af[mt][1], af[mt][2], af[mt][3],
                                Ab + (rowA0 + mt * 16) * 256 + (swu(ks * 2 + unA, rowA0) << 4));
                    int rK = ks * 16 + rowKt;
#pragma unroll
                    for (int nt = 0; nt < 4; ++nt)
                        ldsm_x2t(bfr[nt][0], bfr[nt][1],
                                 Bb + rK * 256 + (swu((wn2 >> 3) + nt, rK) << 4));
#pragma unroll
                    for (int nt = 0; nt < 4; ++nt)
#pragma unroll
                        for (int mt = 0; mt < 2; ++mt)
                            mma16816(dacc[mt][nt][0], dacc[mt][nt][1], dacc[mt][nt][2], dacc[mt][nt][3],
                                     af[mt][0], af[mt][1], af[mt][2], af[mt][3],
                                     bfr[nt][0], bfr[nt][1]);
                }
            }
        }
#pragma unroll
        for (int mt = 0; mt < 2; ++mt) {
            int r0 = wm2 + mt * 16 + (lane >> 2);
            float d0 = obsig8 / rs[r0];
            float d1 = obsig8 / rs[r0 + 8];
#pragma unroll
            for (int nt = 0; nt < 4; ++nt) {
                facc[mt][nt][0] += dacc[mt][nt][0] * d0;
                facc[mt][nt][1] += dacc[mt][nt][1] * d0;
                facc[mt][nt][2] += dacc[mt][nt][2] * d1;
                facc[mt][nt][3] += dacc[mt][nt][3] * d1;
            }
        }
    }

#pragma unroll
    for (int mt = 0; mt < 2; ++mt) {
        int r0 = wm2 + mt * 16 + (lane >> 2);
#pragma unroll
        for (int nt = 0; nt < 4; ++nt) {
            int col = wn2 + nt * 8 + ((lane & 3) << 1);
            *(float2*)&out[(size_t)(qrow0 + r0) * 128 + col]     = make_float2(facc[mt][nt][0], facc[mt][nt][1]);
            *(float2*)&out[(size_t)(qrow0 + r0 + 8) * 128 + col] = make_float2(facc[mt][nt][2], facc[mt][nt][3]);
        }
    }
}

// =====================================================================
extern "C" void kernel_launch(void* const* d_in, const int* in_sizes, int n_in,
                              void* d_out, int out_size)
{
    const float* x    = (const float*)d_in[0];
    const float* wq   = (const float*)d_in[1];
    const float* bq   = (const float*)d_in[2];
    const float* wk   = (const float*)d_in[3];
    const float* bk   = (const float*)d_in[4];
    const float* wv   = (const float*)d_in[5];
    const float* bv   = (const float*)d_in[6];
    const float* beta = (const float*)d_in[7];
    float* out = (float*)d_out;

    static int attr_set = 0;
    if (!attr_set) {
        cudaFuncSetAttribute(k_attn_mma, cudaFuncAttributeMaxDynamicSharedMemorySize, 231424);
        cudaFuncSetAttribute(k_proj_mma, cudaFuncAttributeMaxDynamicSharedMemorySize, 147456);
        attr_set = 1;
    }

    k_splitX<<<32768, 256>>>(x);
    k_trW<<<dim3(32, 32), 256>>>(wq, 0);
    k_trW<<<dim3(32, 32), 256>>>(wk, 1);
    k_trW<<<dim3(32, 32), 256>>>(wv, 2);
    k_proj_mma<<<dim3(8, 256, 3), 512, 147456>>>(bq, bk, bv);
    k_kvouter<<<512, 256>>>();
    k_prefix<<<32, 256>>>();
    k_attn_mma<<<512, 256, 231424>>>(beta, out);
}

// round 11
// speedup vs baseline: 1.4108x; 1.1916x over previous
#include <cuda_runtime.h>
#include <cuda_bf16.h>
#include <cuda_fp16.h>
#include <cstdint>

typedef unsigned long long ull_t;

// ---------- packed fp32x2 helpers ----------
__device__ __forceinline__ ull_t pk2(float x, float y){
    ull_t r; asm("mov.b64 %0, {%1,%2};" : "=l"(r) : "f"(x), "f"(y)); return r;
}
__device__ __forceinline__ void fma2(ull_t &d, ull_t a, ull_t b){
    asm("fma.rn.f32x2 %0, %1, %2, %0;" : "+l"(d) : "l"(a), "l"(b));
}
__device__ __forceinline__ float2 upk2(ull_t v){
    float lo, hi; asm("mov.b64 {%0,%1}, %2;" : "=f"(lo), "=f"(hi) : "l"(v));
    return make_float2(lo, hi);
}
__device__ __forceinline__ float elup1(float x){ return x > 0.f ? x + 1.f : __expf(x); }

#define FMA8x4(ACCROW, AV, B01, B23) do { ull_t ad_ = pk2((AV),(AV)); \
    fma2((ACCROW)[0], ad_, (B01).x); fma2((ACCROW)[1], ad_, (B01).y); \
    fma2((ACCROW)[2], ad_, (B23).x); fma2((ACCROW)[3], ad_, (B23).y); } while(0)

// ---------- warp MMA / async helpers ----------
__device__ __forceinline__ uint32_t smem_u32(const void* p){
    uint32_t a;
    asm("{ .reg .u64 t; cvta.to.shared.u64 t, %1; cvt.u32.u64 %0, t; }" : "=r"(a) : "l"(p));
    return a;
}
__device__ __forceinline__ void cpa16(uint32_t smaddr, const void* g){
    asm volatile("cp.async.cg.shared.global [%0], [%1], 16;" :: "r"(smaddr), "l"(g));
}
#define CP_COMMIT() asm volatile("cp.async.commit_group;" ::: "memory")
#define CP_WAIT1()  asm volatile("cp.async.wait_group 1;" ::: "memory")
__device__ __forceinline__ void ldsm_x4(uint32_t &r0, uint32_t &r1, uint32_t &r2, uint32_t &r3, uint32_t addr){
    asm volatile("ldmatrix.sync.aligned.m8n8.x4.shared.b16 {%0,%1,%2,%3}, [%4];"
        : "=r"(r0), "=r"(r1), "=r"(r2), "=r"(r3) : "r"(addr));
}
__device__ __forceinline__ void ldsm_x2(uint32_t &r0, uint32_t &r1, uint32_t addr){
    asm volatile("ldmatrix.sync.aligned.m8n8.x2.shared.b16 {%0,%1}, [%2];"
        : "=r"(r0), "=r"(r1) : "r"(addr));
}
__device__ __forceinline__ void ldsm_x2t(uint32_t &r0, uint32_t &r1, uint32_t addr){
    asm volatile("ldmatrix.sync.aligned.m8n8.x2.trans.shared.b16 {%0,%1}, [%2];"
        : "=r"(r0), "=r"(r1) : "r"(addr));
}
__device__ __forceinline__ void mma16816h(float &c0, float &c1, float &c2, float &c3,
                                          uint32_t a0, uint32_t a1, uint32_t a2, uint32_t a3,
                                          uint32_t b0, uint32_t b1){
    asm volatile("mma.sync.aligned.m16n8k16.row.col.f32.f16.f16.f32 "
        "{%0,%1,%2,%3}, {%4,%5,%6,%7}, {%8,%9}, {%0,%1,%2,%3};"
        : "+f"(c0), "+f"(c1), "+f"(c2), "+f"(c3)
        : "r"(a0), "r"(a1), "r"(a2), "r"(a3), "r"(b0), "r"(b1));
}
__device__ __forceinline__ uint32_t swu(int u, int r){ return (uint32_t)((u & 8) | ((u & 7) ^ (r & 7))); }
__device__ __forceinline__ uint32_t packhf(float a, float b){
    __half2 t = __halves2half2(__float2half_rn(a), __float2half_rn(b));
    return *(uint32_t*)&t;
}
__device__ __forceinline__ void hsplit2(__half* H, __half* L, size_t off, float2 v){
    __half hx = __float2half_rn(v.x), hy = __float2half_rn(v.y);
    __half lx = __float2half_rn(v.x - __half2float(hx));
    __half ly = __float2half_rn(v.y - __half2float(hy));
    *(__half2*)(H + off) = __halves2half2(hx, hy);
    *(__half2*)(L + off) = __halves2half2(lx, ly);
}
__device__ __forceinline__ float4 ld4hl(const __half* H, const __half* L, size_t off){
    uint2 h = *(const uint2*)(H + off), l = *(const uint2*)(L + off);
    float2 fh0 = __half22float2(*(__half2*)&h.x);
    float2 fh1 = __half22float2(*(__half2*)&h.y);
    float2 fl0 = __half22float2(*(__half2*)&l.x);
    float2 fl1 = __half22float2(*(__half2*)&l.y);
    return make_float4(fh0.x + fl0.x, fh0.y + fl0.y, fh1.x + fl1.x, fh1.y + fl1.y);
}

// ---------- dims: B=4, S=8192, D=1024, H=8, dk=dv=128, SEG=512, nseg=16 ----------

// ---------- device scratch ----------
__device__ float g_P[8388608];
__device__ float g_Zseg[65536];
__device__ float g_Z[65536];
__device__ __half g_Xh[33554432];    // fp16 split of x (hi)
__device__ __half g_Xl[33554432];    // fp16 split of x (lo)
__device__ __half g_Wh[3145728];     // W^T fp16, [which][n][k]
__device__ __half g_Qh[33554432];    // fp16 hi/lo splits of Q, K, V
__device__ __half g_Ql[33554432];
__device__ __half g_Kh[33554432];
__device__ __half g_Kl[33554432];
__device__ __half g_Vh[33554432];
__device__ __half g_Vl[33554432];
__device__ __half g_Memh[8388608];
__device__ __half g_Meml[8388608];

// =====================================================================
// S1: split X into fp16 hi/lo
// =====================================================================
__global__ __launch_bounds__(256) void k_splitX(const float* __restrict__ x)
{
    size_t i = ((size_t)blockIdx.x * 256 + threadIdx.x) * 4;
    float4 v = *(const float4*)(x + i);
    hsplit2(g_Xh, g_Xl, i,     make_float2(v.x, v.y));
    hsplit2(g_Xh, g_Xl, i + 2, make_float2(v.z, v.w));
}

// =====================================================================
// S2: transpose W[k][n] -> Wt[n][k], fp16
// =====================================================================
__global__ __launch_bounds__(256) void k_trW(const float* __restrict__ w, int which)
{
    __shared__ float t[32][33];
    const int bx = blockIdx.x << 5, by = blockIdx.y << 5;
    const int tx = threadIdx.x & 31, ty = threadIdx.x >> 5;
#pragma unroll
    for (int r = 0; r < 4; ++r)
        t[ty * 4 + r][tx] = w[(size_t)(by + ty * 4 + r) * 1024 + bx + tx];
    __syncthreads();
    __half* Wt = g_Wh + (size_t)which * 1048576;
#pragma unroll
    for (int r = 0; r < 4; ++r) {
        int n = bx + ty * 4 + r, k = by + tx;
        Wt[(size_t)n * 1024 + k] = __float2half_rn(t[tx][ty * 4 + r]);
    }
}

// =====================================================================
// K1: fused projection GEMM, fp16 asymmetric 2-pass (XhWh + XlWh).
// =====================================================================
__global__ __launch_bounds__(512, 1) void k_proj_mma(const float* __restrict__ bq,
                                                     const float* __restrict__ bk,
                                                     const float* __restrict__ bv)
{
    extern __shared__ __align__(128) char sm_raw[];
    const uint32_t smbase = smem_u32(sm_raw);

    const int which = blockIdx.z;
    const float* bias = (which == 0) ? bq : ((which == 1) ? bk : bv);
    __half* Hd = (which == 0) ? g_Qh : ((which == 1) ? g_Kh : g_Vh);
    __half* Ld = (which == 0) ? g_Ql : ((which == 1) ? g_Kl : g_Vl);
    const __half* Wt = g_Wh + (size_t)which * 1048576;

    const int tid = threadIdx.x, lane = tid & 31, wid = tid >> 5;
    const int wm = (wid >> 2) * 32, wn = (wid & 3) * 32;
    const int row0 = blockIdx.y << 7, col0 = blockIdx.x << 7;

    const int rowA = wm + (lane & 15);
    const int rA7 = rowA & 7;
    const int unA = lane >> 4;
    const int rowB = wn + (lane & 7);
    const int rB7 = lane & 7;
    const int unB = (lane >> 3) & 1;

    const int lr = tid >> 3, lu = tid & 7;

    float cf[2][4][4];
#pragma unroll
    for (int mt = 0; mt < 2; ++mt)
#pragma unroll
        for (int nt = 0; nt < 4; ++nt)
#pragma unroll
            for (int q = 0; q < 4; ++q) cf[mt][nt][q] = 0.f;

    auto load_chunk = [&](int c, int stage) {
        const int k0 = c << 6;
        const uint32_t st = smbase + stage * 49152;
#pragma unroll
        for (int it = 0; it < 2; ++it) {
            int r = lr + it * 64;
            size_t ga = (size_t)(row0 + r) * 1024 + k0 + lu * 8;
            size_t gb = (size_t)(col0 + r) * 1024 + k0 + lu * 8;
            uint32_t so = r * 128 + ((lu ^ (r & 7)) << 4);
            cpa16(st + so,         g_Xh + ga);
            cpa16(st + 16384 + so, g_Xl + ga);
            cpa16(st + 32768 + so, Wt + gb);
        }
    };

    load_chunk(0, 0); CP_COMMIT();
    load_chunk(1, 1); CP_COMMIT();

    for (int c = 0; c < 16; ++c) {
        CP_WAIT1();
        __syncthreads();
        if (c + 2 < 16) load_chunk(c + 2, (c + 2) % 3);
        CP_COMMIT();
        const uint32_t st = smbase + (c % 3) * 49152;
#pragma unroll
        for (int ks = 0; ks < 4; ++ks) {
            uint32_t ah[2][4], al[2][4], bh[4][2];
#pragma unroll
            for (int mt = 0; mt < 2; ++mt) {
                uint32_t off = (rowA + mt * 16) * 128 + ((((ks << 1) + unA) ^ rA7) << 4);
                ldsm_x4(ah[mt][0], ah[mt][1], ah[mt][2], ah[mt][3], st + off);
                ldsm_x4(al[mt][0], al[mt][1], al[mt][2], al[mt][3], st + 16384 + off);
            }
#pragma unroll
            for (int nt = 0; nt < 4; ++nt) {
                uint32_t off = (rowB + nt * 8) * 128 + ((((ks << 1) + unB) ^ rB7) << 4);
                ldsm_x2(bh[nt][0], bh[nt][1], st + 32768 + off);
            }
#pragma unroll
            for (int nt = 0; nt < 4; ++nt)
#pragma unroll
                for (int mt = 0; mt < 2; ++mt)
                    mma16816h(cf[mt][nt][0], cf[mt][nt][1], cf[mt][nt][2], cf[mt][nt][3],
                              ah[mt][0], ah[mt][1], ah[mt][2], ah[mt][3], bh[nt][0], bh[nt][1]);
#pragma unroll
            for (int nt = 0; nt < 4; ++nt)
#pragma unroll
                for (int mt = 0; mt < 2; ++mt)
                    mma16816h(cf[mt][nt][0], cf[mt][nt][1], cf[mt][nt][2], cf[mt][nt][3],
                              al[mt][0], al[mt][1], al[mt][2], al[mt][3], bh[nt][0], bh[nt][1]);
        }
    }

    // epilogue: bias + fp16 hi/lo splits
#pragma unroll
    for (int mt = 0; mt < 2; ++mt) {
        const int r0 = row0 + wm + mt * 16 + (lane >> 2);
#pragma unroll
        for (int nt = 0; nt < 4; ++nt) {
            const int ccol = col0 + wn + nt * 8 + ((lane & 3) << 1);
            const float2 bvv = *(const float2*)&bias[ccol];
            float2 v0 = make_float2(cf[mt][nt][0] + bvv.x, cf[mt][nt][1] + bvv.y);
            float2 v1 = make_float2(cf[mt][nt][2] + bvv.x, cf[mt][nt][3] + bvv.y);
            size_t o0 = (size_t)r0 * 1024 + ccol;
            size_t o1 = o0 + 8 * 1024;
            hsplit2(Hd, Ld, o0, v0);
            hsplit2(Hd, Ld, o1, v1);
        }
    }
}

// =====================================================================
// K2: per (b,h,seg): P = (elu(K)+1)^T @ V  [128x128], Zseg = 512*colsum
// =====================================================================
__global__ __launch_bounds__(256) void k_kvouter()
{
    const int idx = blockIdx.x;
    const int b = idx >> 7, h = (idx >> 4) & 7, seg = idx & 15;
    __shared__ __align__(16) float sks[16][128];
    __shared__ __align__(16) float vvs[16][128];
    const int tid = threadIdx.x, tx = tid & 15, ty = tid >> 4;
    const int lr = tid >> 5, c4 = (tid & 31) << 2;

    ull_t acc[8][4];
#pragma unroll
    for (int i = 0; i < 8; ++i)
#pragma unroll
        for (int j = 0; j < 4; ++j) acc[i][j] = 0ull;
    float zacc[8] = {0.f,0.f,0.f,0.f,0.f,0.f,0.f,0.f};

    const size_t rowbase = (size_t)(b * 8192 + seg * 512) * 1024 + h * 128;

    for (int l0 = 0; l0 < 512; l0 += 16) {
        float4 k0v = ld4hl(g_Kh, g_Kl, rowbase + (size_t)(l0 + lr) * 1024 + c4);
        float4 k1v = ld4hl(g_Kh, g_Kl, rowbase + (size_t)(l0 + lr + 8) * 1024 + c4);
        float4 v0v = ld4hl(g_Vh, g_Vl, rowbase + (size_t)(l0 + lr) * 1024 + c4);
        float4 v1v = ld4hl(g_Vh, g_Vl, rowbase + (size_t)(l0 + lr + 8) * 1024 + c4);
        k0v.x = elup1(k0v.x); k0v.y = elup1(k0v.y); k0v.z = elup1(k0v.z); k0v.w = elup1(k0v.w);
        k1v.x = elup1(k1v.x); k1v.y = elup1(k1v.y); k1v.z = elup1(k1v.z); k1v.w = elup1(k1v.w);
        __syncthreads();
        *(float4*)&sks[lr][c4]     = k0v;
        *(float4*)&sks[lr + 8][c4] = k1v;
        *(float4*)&vvs[lr][c4]     = v0v;
        *(float4*)&vvs[lr + 8][c4] = v1v;
        __syncthreads();
#pragma unroll
        for (int l = 0; l < 16; ++l) {
            float4 a0 = *(const float4*)&sks[l][ty * 8];
            float4 a1 = *(const float4*)&sks[l][ty * 8 + 4];
            ulonglong2 b01 = *(const ulonglong2*)&vvs[l][tx * 8];
            ulonglong2 b23 = *(const ulonglong2*)&vvs[l][tx * 8 + 4];
            if (tx == 0) {
                zacc[0] += a0.x; zacc[1] += a0.y; zacc[2] += a0.z; zacc[3] += a0.w;
                zacc[4] += a1.x; zacc[5] += a1.y; zacc[6] += a1.z; zacc[7] += a1.w;
            }
            FMA8x4(acc[0], a0.x, b01, b23);
            FMA8x4(acc[1], a0.y, b01, b23);
            FMA8x4(acc[2], a0.z, b01, b23);
            FMA8x4(acc[3], a0.w, b01, b23);
            FMA8x4(acc[4], a1.x, b01, b23);
            FMA8x4(acc[5], a1.y, b01, b23);
            FMA8x4(acc[6], a1.z, b01, b23);
            FMA8x4(acc[7], a1.w, b01, b23);
        }
    }
    const size_t pbase = (size_t)idx * 16384;
#pragma unroll
    for (int i = 0; i < 8; ++i) {
        size_t rb = pbase + (size_t)(ty * 8 + i) * 128 + tx * 8;
#pragma unroll
        for (int jp = 0; jp < 4; ++jp) {
            float2 v = upk2(acc[i][jp]);
            g_P[rb + jp * 2]     = v.x;
            g_P[rb + jp * 2 + 1] = v.y;
        }
    }
    if (tx == 0) {
#pragma unroll
        for (int i = 0; i < 8; ++i)
            g_Zseg[idx * 128 + ty * 8 + i] = 512.f * zacc[i];
    }
}

// =====================================================================
// K3: inclusive prefix over seg; writes fp16 hi/lo Mem splits + Z
// =====================================================================
__global__ __launch_bounds__(256) void k_prefix()
{
    const int bh = blockIdx.x;
    const int tid = threadIdx.x;
    float acc[64];
#pragma unroll
    for (int u = 0; u < 64; ++u) acc[u] = 0.f;
    float zacc = 0.f;
    for (int seg = 0; seg < 16; ++seg) {
        const size_t base = ((size_t)bh * 16 + seg) * 16384;
#pragma unroll
        for (int u = 0; u < 64; ++u) {
            acc[u] += g_P[base + u * 256 + tid];
            float v = acc[u];
            __half h = __float2half_rn(v);
            __half l = __float2half_rn(v - __half2float(h));
            g_Memh[base + u * 256 + tid] = h;
            g_Meml[base + u * 256 + tid] = l;
        }
        if (tid < 128) {
            zacc += g_Zseg[(bh * 16 + seg) * 128 + tid];
            g_Z[(bh * 16 + seg) * 128 + tid] = zacc;
        }
    }
}

// =====================================================================
// K4: fp16 mma.sync attention. scores 2-pass, retrieval 2-pass, PV 1-pass.
// smem: Sc 132096 | sAh 16384 | sAl 16384 | sBh 32768 | ctl 1024
// =====================================================================
__global__ __launch_bounds__(256, 1) void k_attn_mma(const float* __restrict__ beta,
                                                     float* __restrict__ out)
{
    extern __shared__ __align__(16) char smraw[];
    float* Sc = (float*)smraw;                       // 132096 B
    char* sAh = smraw + 132096;                      // 16384
    char* sAl = sAh + 16384;                         // 16384
    char* sBh = sAl + 16384;                         // 32768
    float* zs  = (float*)(sBh + 32768);              // 128
    float* rs  = zs + 128;                           // 64
    float* den = rs + 64;                            // 64
    const uint32_t aAh = smem_u32(sAh), aAl = smem_u32(sAl);
    const uint32_t aBh = smem_u32(sBh);

    const int idx = blockIdx.x;                      // b*128 + seg*8 + qt
    const int b = idx >> 7, seg = (idx >> 3) & 15, qt = idx & 7;
    const int tid = threadIdx.x, lane = tid & 31, wid = tid >> 5;
    const int wm2 = (wid >> 2) * 32, wn2 = (wid & 3) * 32;
    const int qrow0 = b * 8192 + seg * 512 + qt * 64;
    const int krow0 = b * 8192 + seg * 512;
    const float bsig = 1.f / (1.f + __expf(-beta[0]));
    const float bsig8 = bsig * 0.125f, obsig8 = (1.f - bsig) * 0.125f;
    const float scale = 0.088388347648318447f;

    const int rowA0 = wm2 + (lane & 15);
    const int unA = lane >> 4;
    const int rowBn = wn2 + (lane & 7);
    const int unB = (lane >> 3) & 1;
    const int rowKt = (lane & 7) + ((lane >> 3) & 1) * 8;
    const int srow = tid >> 2, spart = tid & 3;

    float facc[2][4][4];
#pragma unroll
    for (int mt = 0; mt < 2; ++mt)
#pragma unroll
        for (int nt = 0; nt < 4; ++nt)
#pragma unroll
            for (int q = 0; q < 4; ++q) facc[mt][nt][q] = 0.f;

    for (int h = 0; h < 8; ++h) {
        const int hc = h * 128;
        __syncthreads();
#pragma unroll
        for (int it = 0; it < 4; ++it) {
            int i2 = it * 256 + tid;
            int r = i2 >> 4, u = i2 & 15;
            size_t gs = (size_t)(qrow0 + r) * 1024 + hc + u * 8;
            uint32_t so = r * 256 + (swu(u, r) << 4);
            *(uint4*)(sAh + so) = *(const uint4*)(g_Qh + gs);
            *(uint4*)(sAl + so) = *(const uint4*)(g_Ql + gs);
        }
        if (tid < 128)
            zs[tid] = g_Z[((size_t)(b * 8 + h) * 16 + seg) * 128 + tid];

        // ---- scores: 4 key chunks of 128, 2-pass (Qh,Ql) x Kh ----
        for (int kc = 0; kc < 4; ++kc) {
            __syncthreads();
#pragma unroll
            for (int it = 0; it < 8; ++it) {
                int i2 = it * 256 + tid;
                int r = i2 >> 4, u = i2 & 15;
                size_t gs = (size_t)(krow0 + kc * 128 + r) * 1024 + hc + u * 8;
                uint32_t so = r * 256 + (swu(u, r) << 4);
                *(uint4*)(sBh + so) = *(const uint4*)(g_Kh + gs);
            }
            __syncthreads();
            float acc[2][4][4];
#pragma unroll
            for (int mt = 0; mt < 2; ++mt)
#pragma unroll
                for (int nt = 0; nt < 4; ++nt)
#pragma unroll
                    for (int q = 0; q < 4; ++q) acc[mt][nt][q] = 0.f;
            for (int pass = 0; pass < 2; ++pass) {
                const uint32_t Ab = pass ? aAl : aAh;
#pragma unroll
                for (int ks = 0; ks < 8; ++ks) {
                    uint32_t af[2][4], bfr[4][2];
#pragma unroll
                    for (int mt = 0; mt < 2; ++mt)
                        ldsm_x4(af[mt][0], af[mt][1], af[mt][2], af[mt][3],
                                Ab + (rowA0 + mt * 16) * 256 + (swu(ks * 2 + unA, rowA0) << 4));
#pragma unroll
                    for (int nt = 0; nt < 4; ++nt)
                        ldsm_x2(bfr[nt][0], bfr[nt][1],
                                aBh + (rowBn + nt * 8) * 256 + (swu(ks * 2 + unB, rowBn) << 4));
#pragma unroll
                    for (int nt = 0; nt < 4; ++nt)
#pragma unroll
                        for (int mt = 0; mt < 2; ++mt)
                            mma16816h(acc[mt][nt][0], acc[mt][nt][1], acc[mt][nt][2], acc[mt][nt][3],
                                      af[mt][0], af[mt][1], af[mt][2], af[mt][3],
                                      bfr[nt][0], bfr[nt][1]);
                }
            }
#pragma unroll
            for (int mt = 0; mt < 2; ++mt) {
                int r0 = wm2 + mt * 16 + (lane >> 2);
#pragma unroll
                for (int nt = 0; nt < 4; ++nt) {
                    int cc = kc * 128 + wn2 + nt * 8 + ((lane & 3) << 1);
                    *(float2*)&Sc[r0 * 516 + cc]       = make_float2(acc[mt][nt][0] * scale, acc[mt][nt][1] * scale);
                    *(float2*)&Sc[(r0 + 8) * 516 + cc] = make_float2(acc[mt][nt][2] * scale, acc[mt][nt][3] * scale);
                }
            }
        }
        __syncthreads();
        // ---- softmax ----
        {
            float* rowp = &Sc[srow * 516 + spart * 128];
            float m = -1e30f;
#pragma unroll 8
            for (int j = 0; j < 128; ++j) m = fmaxf(m, rowp[j]);
            m = fmaxf(m, __shfl_xor_sync(0xffffffffu, m, 1));
            m = fmaxf(m, __shfl_xor_sync(0xffffffffu, m, 2));
            float s = 0.f;
#pragma unroll 8
            for (int j = 0; j < 128; ++j) { float e = __expf(rowp[j] - m); rowp[j] = e; s += e; }
            s += __shfl_xor_sync(0xffffffffu, s, 1);
            s += __shfl_xor_sync(0xffffffffu, s, 2);
            if (spart == 0) rs[srow] = s;
        }
        // ---- sq transform (fp16 hi/lo into sA) + exact den ----
        {
            float da = 0.f;
#pragma unroll 4
            for (int j = 0; j < 32; ++j) {
                int c = spart * 32 + j;
                uint32_t bo = srow * 256 + (swu(c >> 3, srow) << 4) + ((c & 7) << 1);
                float qh = __half2float(*(__half*)(sAh + bo));
                float ql = __half2float(*(__half*)(sAl + bo));
                float sq = elup1(qh + ql);
                da += sq * zs[c];
                __half hh = __float2half_rn(sq);
                __half ll = __float2half_rn(sq - __half2float(hh));
                *(__half*)(sAh + bo) = hh;
                *(__half*)(sAl + bo) = ll;
            }
            da += __shfl_xor_sync(0xffffffffu, da, 1);
            da += __shfl_xor_sync(0xffffffffu, da, 2);
            if (spart == 0) den[srow] = da;
        }
        __syncthreads();
        // ---- retrieval: Mem hi only, 2-pass (sqh, sql) ----
#pragma unroll
        for (int it = 0; it < 8; ++it) {
            int i2 = it * 256 + tid;
            int r = i2 >> 4, u = i2 & 15;
            size_t ms = ((size_t)(b * 8 + h) * 16 + seg) * 16384 + r * 128 + u * 8;
            uint32_t so = r * 256 + (swu(u, r) << 4);
            *(uint4*)(sBh + so) = *(const uint4*)(g_Memh + ms);
        }
        __syncthreads();
        {
            float acc[2][4][4];
#pragma unroll
            for (int mt = 0; mt < 2; ++mt)
#pragma unroll
                for (int nt = 0; nt < 4; ++nt)
#pragma unroll
                    for (int q = 0; q < 4; ++q) acc[mt][nt][q] = 0.f;
            for (int pass = 0; pass < 2; ++pass) {
                const uint32_t Ab = pass ? aAl : aAh;
#pragma unroll
                for (int ks = 0; ks < 8; ++ks) {
                    uint32_t af[2][4], bfr[4][2];
#pragma unroll
                    for (int mt = 0; mt < 2; ++mt)
                        ldsm_x4(af[mt][0], af[mt][1], af[mt][2], af[mt][3],
                                Ab + (rowA0 + mt * 16) * 256 + (swu(ks * 2 + unA, rowA0) << 4));
                    int rK = ks * 16 + rowKt;
#pragma unroll
                    for (int nt = 0; nt < 4; ++nt)
                        ldsm_x2t(bfr[nt][0], bfr[nt][1],
                                 aBh + rK * 256 + (swu((wn2 >> 3) + nt, rK) << 4));
#pragma unroll
                    for (int nt = 0; nt < 4; ++nt)
#pragma unroll
                        for (int mt = 0; mt < 2; ++mt)
                            mma16816h(acc[mt][nt][0], acc[mt][nt][1], acc[mt][nt][2], acc[mt][nt][3],
                                      af[mt][0], af[mt][1], af[mt][2], af[mt][3],
                                      bfr[nt][0], bfr[nt][1]);
                }
            }
#pragma unroll
            for (int mt = 0; mt < 2; ++mt) {
                int r0 = wm2 + mt * 16 + (lane >> 2);
                float m0 = bsig8 / (den[r0] + 1e-5f);
                float m1 = bsig8 / (den[r0 + 8] + 1e-5f);
#pragma unroll
                for (int nt = 0; nt < 4; ++nt) {
                    facc[mt][nt][0] += acc[mt][nt][0] * m0;
                    facc[mt][nt][1] += acc[mt][nt][1] * m0;
                    facc[mt][nt][2] += acc[mt][nt][2] * m1;
                    facc[mt][nt][3] += acc[mt][nt][3] * m1;
                }
            }
        }
        // ---- PV: single-pass fp16 P x Vh ----
        float dacc[2][4][4];
#pragma unroll
        for (int mt = 0; mt < 2; ++mt)
#pragma unroll
            for (int nt = 0; nt < 4; ++nt)
#pragma unroll
                for (int q = 0; q < 4; ++q) dacc[mt][nt][q] = 0.f;
        for (int kc = 0; kc < 4; ++kc) {
            __syncthreads();
#pragma unroll
            for (int it = 0; it < 4; ++it) {
                int i2 = it * 256 + tid;
                int r = i2 >> 4, u = i2 & 15;
                const float* sp = &Sc[r * 516 + kc * 128 + u * 8];
                float4 p0 = *(const float4*)sp, p1 = *(const float4*)(sp + 4);
                uint4 hi;
                hi.x = packhf(p0.x, p0.y); hi.y = packhf(p0.z, p0.w);
                hi.z = packhf(p1.x, p1.y); hi.w = packhf(p1.z, p1.w);
                uint32_t so = r * 256 + (swu(u, r) << 4);
                *(uint4*)(sAh + so) = hi;
            }
#pragma unroll
            for (int it = 0; it < 8; ++it) {
                int i2 = it * 256 + tid;
                int r = i2 >> 4, u = i2 & 15;
                size_t gs = (size_t)(krow0 + kc * 128 + r) * 1024 + hc + u * 8;
                uint32_t so = r * 256 + (swu(u, r) << 4);
                *(uint4*)(sBh + so) = *(const uint4*)(g_Vh + gs);
            }
            __syncthreads();
#pragma unroll
            for (int ks = 0; ks < 8; ++ks) {
                uint32_t af[2][4], bfr[4][2];
#pragma unroll
                for (int mt = 0; mt < 2; ++mt)
                    ldsm_x4(af[mt][0], af[mt][1], af[mt][2], af[mt][3],
                            aAh + (rowA0 + mt * 16) * 256 + (swu(ks * 2 + unA, rowA0) << 4));
                int rK = ks * 16 + rowKt;
#pragma unroll
                for (int nt = 0; nt < 4; ++nt)
                    ldsm_x2t(bfr[nt][0], bfr[nt][1],
                             aBh + rK * 256 + (swu((wn2 >> 3) + nt, rK) << 4));
#pragma unroll
                for (int nt = 0; nt < 4; ++nt)
#pragma unroll
                    for (int mt = 0; mt < 2; ++mt)
                        mma16816h(dacc[mt][nt][0], dacc[mt][nt][1], dacc[mt][nt][2], dacc[mt][nt][3],
                                  af[mt][0], af[mt][1], af[mt][2], af[mt][3],
                                  bfr[nt][0], bfr[nt][1]);
            }
        }
#pragma unroll
        for (int mt = 0; mt < 2; ++mt) {
            int r0 = wm2 + mt * 16 + (lane >> 2);
            float d0 = obsig8 / rs[r0];
            float d1 = obsig8 / rs[r0 + 8];
#pragma unroll
            for (int nt = 0; nt < 4; ++nt) {
                facc[mt][nt][0] += dacc[mt][nt][0] * d0;
                facc[mt][nt][1] += dacc[mt][nt][1] * d0;
                facc[mt][nt][2] += dacc[mt][nt][2] * d1;
                facc[mt][nt][3] += dacc[mt][nt][3] * d1;
            }
        }
    }

#pragma unroll
    for (int mt = 0; mt < 2; ++mt) {
        int r0 = wm2 + mt * 16 + (lane >> 2);
#pragma unroll
        for (int nt = 0; nt < 4; ++nt) {
            int col = wn2 + nt * 8 + ((lane & 3) << 1);
            *(float2*)&out[(size_t)(qrow0 + r0) * 128 + col]     = make_float2(facc[mt][nt][0], facc[mt][nt][1]);
            *(float2*)&out[(size_t)(qrow0 + r0 + 8) * 128 + col] = make_float2(facc[mt][nt][2], facc[mt][nt][3]);
        }
    }
}

// =====================================================================
extern "C" void kernel_launch(void* const* d_in, const int* in_sizes, int n_in,
                              void* d_out, int out_size)
{
    const float* x    = (const float*)d_in[0];
    const float* wq   = (const float*)d_in[1];
    const float* bq   = (const float*)d_in[2];
    const float* wk   = (const float*)d_in[3];
    const float* bk   = (const float*)d_in[4];
    const float* wv   = (const float*)d_in[5];
    const float* bv   = (const float*)d_in[6];
    const float* beta = (const float*)d_in[7];
    float* out = (float*)d_out;

    static int attr_set = 0;
    if (!attr_set) {
        cudaFuncSetAttribute(k_attn_mma, cudaFuncAttributeMaxDynamicSharedMemorySize, 198656);
        cudaFuncSetAttribute(k_proj_mma, cudaFuncAttributeMaxDynamicSharedMemorySize, 147456);
        attr_set = 1;
    }

    k_splitX<<<32768, 256>>>(x);
    k_trW<<<dim3(32, 32), 256>>>(wq, 0);
    k_trW<<<dim3(32, 32), 256>>>(wk, 1);
    k_trW<<<dim3(32, 32), 256>>>(wv, 2);
    k_proj_mma<<<dim3(8, 256, 3), 512, 147456>>>(bq, bk, bv);
    k_kvouter<<<512, 256>>>();
    k_prefix<<<32, 256>>>();
    k_attn_mma<<<512, 256, 198656>>>(beta, out);
}

// round 12
// speedup vs baseline: 1.4843x; 1.0521x over previous
#include <cuda_runtime.h>
#include <cuda_fp16.h>
#include <cstdint>

// ---------- helpers ----------
__device__ __forceinline__ float elup1(float x){ return x > 0.f ? x + 1.f : __expf(x); }
__device__ __forceinline__ uint32_t smem_u32(const void* p){
    uint32_t a;
    asm("{ .reg .u64 t; cvta.to.shared.u64 t, %1; cvt.u32.u64 %0, t; }" : "=r"(a) : "l"(p));
    return a;
}
__device__ __forceinline__ void cpa16(uint32_t smaddr, const void* g){
    asm volatile("cp.async.cg.shared.global [%0], [%1], 16;" :: "r"(smaddr), "l"(g));
}
#define CP_COMMIT() asm volatile("cp.async.commit_group;" ::: "memory")
#define CP_WAIT0()  asm volatile("cp.async.wait_group 0;" ::: "memory")
#define CP_WAIT1()  asm volatile("cp.async.wait_group 1;" ::: "memory")
__device__ __forceinline__ void ldsm_x4(uint32_t &r0, uint32_t &r1, uint32_t &r2, uint32_t &r3, uint32_t addr){
    asm volatile("ldmatrix.sync.aligned.m8n8.x4.shared.b16 {%0,%1,%2,%3}, [%4];"
        : "=r"(r0), "=r"(r1), "=r"(r2), "=r"(r3) : "r"(addr));
}
__device__ __forceinline__ void ldsm_x4t(uint32_t &r0, uint32_t &r1, uint32_t &r2, uint32_t &r3, uint32_t addr){
    asm volatile("ldmatrix.sync.aligned.m8n8.x4.trans.shared.b16 {%0,%1,%2,%3}, [%4];"
        : "=r"(r0), "=r"(r1), "=r"(r2), "=r"(r3) : "r"(addr));
}
__device__ __forceinline__ void ldsm_x2(uint32_t &r0, uint32_t &r1, uint32_t addr){
    asm volatile("ldmatrix.sync.aligned.m8n8.x2.shared.b16 {%0,%1}, [%2];"
        : "=r"(r0), "=r"(r1) : "r"(addr));
}
__device__ __forceinline__ void ldsm_x2t(uint32_t &r0, uint32_t &r1, uint32_t addr){
    asm volatile("ldmatrix.sync.aligned.m8n8.x2.trans.shared.b16 {%0,%1}, [%2];"
        : "=r"(r0), "=r"(r1) : "r"(addr));
}
__device__ __forceinline__ void mma16816h(float &c0, float &c1, float &c2, float &c3,
                                          uint32_t a0, uint32_t a1, uint32_t a2, uint32_t a3,
                                          uint32_t b0, uint32_t b1){
    asm volatile("mma.sync.aligned.m16n8k16.row.col.f32.f16.f16.f32 "
        "{%0,%1,%2,%3}, {%4,%5,%6,%7}, {%8,%9}, {%0,%1,%2,%3};"
        : "+f"(c0), "+f"(c1), "+f"(c2), "+f"(c3)
        : "r"(a0), "r"(a1), "r"(a2), "r"(a3), "r"(b0), "r"(b1));
}
__device__ __forceinline__ uint32_t swu(int u, int r){ return (uint32_t)((u & 8) | ((u & 7) ^ (r & 7))); }
__device__ __forceinline__ uint32_t packhf(float a, float b){
    __half2 t = __halves2half2(__float2half_rn(a), __float2half_rn(b));
    return *(uint32_t*)&t;
}
__device__ __forceinline__ void hsplit2(__half* H, __half* L, size_t off, float2 v){
    __half hx = __float2half_rn(v.x), hy = __float2half_rn(v.y);
    __half lx = __float2half_rn(v.x - __half2float(hx));
    __half ly = __float2half_rn(v.y - __half2float(hy));
    *(__half2*)(H + off) = __halves2half2(hx, hy);
    *(__half2*)(L + off) = __halves2half2(lx, ly);
}

// ---------- dims: B=4, S=8192, D=1024, H=8, dk=dv=128, SEG=512, nseg=16 ----------

// ---------- device scratch ----------
__device__ float g_P[8388608];
__device__ float g_Zseg[65536];
__device__ float g_Z[65536];
__device__ __half g_Xh[33554432];
__device__ __half g_Xl[33554432];
__device__ __half g_Wh[3145728];
__device__ __half g_Qh[33554432];
__device__ __half g_Ql[33554432];
__device__ __half g_Kh[33554432];
__device__ __half g_Kl[33554432];
__device__ __half g_Vh[33554432];
__device__ __half g_Vl[33554432];
__device__ __half g_Memh[8388608];
__device__ __half g_Meml[8388608];

// =====================================================================
// S1: split X into fp16 hi/lo
// =====================================================================
__global__ __launch_bounds__(256) void k_splitX(const float* __restrict__ x)
{
    size_t i = ((size_t)blockIdx.x * 256 + threadIdx.x) * 4;
    float4 v = *(const float4*)(x + i);
    hsplit2(g_Xh, g_Xl, i,     make_float2(v.x, v.y));
    hsplit2(g_Xh, g_Xl, i + 2, make_float2(v.z, v.w));
}

// =====================================================================
// S2: transpose W[k][n] -> Wt[n][k], fp16
// =====================================================================
__global__ __launch_bounds__(256) void k_trW(const float* __restrict__ w, int which)
{
    __shared__ float t[32][33];
    const int bx = blockIdx.x << 5, by = blockIdx.y << 5;
    const int tx = threadIdx.x & 31, ty = threadIdx.x >> 5;
#pragma unroll
    for (int r = 0; r < 4; ++r)
        t[ty * 4 + r][tx] = w[(size_t)(by + ty * 4 + r) * 1024 + bx + tx];
    __syncthreads();
    __half* Wt = g_Wh + (size_t)which * 1048576;
#pragma unroll
    for (int r = 0; r < 4; ++r) {
        int n = bx + ty * 4 + r, k = by + tx;
        Wt[(size_t)n * 1024 + k] = __float2half_rn(t[tx][ty * 4 + r]);
    }
}

// =====================================================================
// K1: fused projection GEMM, fp16 asymmetric 2-pass (XhWh + XlWh).
// =====================================================================
__global__ __launch_bounds__(512, 1) void k_proj_mma(const float* __restrict__ bq,
                                                     const float* __restrict__ bk,
                                                     const float* __restrict__ bv)
{
    extern __shared__ __align__(128) char sm_raw[];
    const uint32_t smbase = smem_u32(sm_raw);

    const int which = blockIdx.z;
    const float* bias = (which == 0) ? bq : ((which == 1) ? bk : bv);
    __half* Hd = (which == 0) ? g_Qh : ((which == 1) ? g_Kh : g_Vh);
    __half* Ld = (which == 0) ? g_Ql : ((which == 1) ? g_Kl : g_Vl);
    const __half* Wt = g_Wh + (size_t)which * 1048576;

    const int tid = threadIdx.x, lane = tid & 31, wid = tid >> 5;
    const int wm = (wid >> 2) * 32, wn = (wid & 3) * 32;
    const int row0 = blockIdx.y << 7, col0 = blockIdx.x << 7;

    const int rowA = wm + (lane & 15);
    const int rA7 = rowA & 7;
    const int unA = lane >> 4;
    const int rowB = wn + (lane & 7);
    const int rB7 = lane & 7;
    const int unB = (lane >> 3) & 1;
    const int lr = tid >> 3, lu = tid & 7;

    float cf[2][4][4];
#pragma unroll
    for (int mt = 0; mt < 2; ++mt)
#pragma unroll
        for (int nt = 0; nt < 4; ++nt)
#pragma unroll
            for (int q = 0; q < 4; ++q) cf[mt][nt][q] = 0.f;

    auto load_chunk = [&](int c, int stage) {
        const int k0 = c << 6;
        const uint32_t st = smbase + stage * 49152;
#pragma unroll
        for (int it = 0; it < 2; ++it) {
            int r = lr + it * 64;
            size_t ga = (size_t)(row0 + r) * 1024 + k0 + lu * 8;
            size_t gb = (size_t)(col0 + r) * 1024 + k0 + lu * 8;
            uint32_t so = r * 128 + ((lu ^ (r & 7)) << 4);
            cpa16(st + so,         g_Xh + ga);
            cpa16(st + 16384 + so, g_Xl + ga);
            cpa16(st + 32768 + so, Wt + gb);
        }
    };

    load_chunk(0, 0); CP_COMMIT();
    load_chunk(1, 1); CP_COMMIT();

    for (int c = 0; c < 16; ++c) {
        CP_WAIT1();
        __syncthreads();
        if (c + 2 < 16) load_chunk(c + 2, (c + 2) % 3);
        CP_COMMIT();
        const uint32_t st = smbase + (c % 3) * 49152;
#pragma unroll
        for (int ks = 0; ks < 4; ++ks) {
            uint32_t ah[2][4], al[2][4], bh[4][2];
#pragma unroll
            for (int mt = 0; mt < 2; ++mt) {
                uint32_t off = (rowA + mt * 16) * 128 + ((((ks << 1) + unA) ^ rA7) << 4);
                ldsm_x4(ah[mt][0], ah[mt][1], ah[mt][2], ah[mt][3], st + off);
                ldsm_x4(al[mt][0], al[mt][1], al[mt][2], al[mt][3], st + 16384 + off);
            }
#pragma unroll
            for (int nt = 0; nt < 4; ++nt) {
                uint32_t off = (rowB + nt * 8) * 128 + ((((ks << 1) + unB) ^ rB7) << 4);
                ldsm_x2(bh[nt][0], bh[nt][1], st + 32768 + off);
            }
#pragma unroll
            for (int nt = 0; nt < 4; ++nt)
#pragma unroll
                for (int mt = 0; mt < 2; ++mt)
                    mma16816h(cf[mt][nt][0], cf[mt][nt][1], cf[mt][nt][2], cf[mt][nt][3],
                              ah[mt][0], ah[mt][1], ah[mt][2], ah[mt][3], bh[nt][0], bh[nt][1]);
#pragma unroll
            for (int nt = 0; nt < 4; ++nt)
#pragma unroll
                for (int mt = 0; mt < 2; ++mt)
                    mma16816h(cf[mt][nt][0], cf[mt][nt][1], cf[mt][nt][2], cf[mt][nt][3],
                              al[mt][0], al[mt][1], al[mt][2], al[mt][3], bh[nt][0], bh[nt][1]);
        }
    }

#pragma unroll
    for (int mt = 0; mt < 2; ++mt) {
        const int r0 = row0 + wm + mt * 16 + (lane >> 2);
#pragma unroll
        for (int nt = 0; nt < 4; ++nt) {
            const int ccol = col0 + wn + nt * 8 + ((lane & 3) << 1);
            const float2 bvv = *(const float2*)&bias[ccol];
            float2 v0 = make_float2(cf[mt][nt][0] + bvv.x, cf[mt][nt][1] + bvv.y);
            float2 v1 = make_float2(cf[mt][nt][2] + bvv.x, cf[mt][nt][3] + bvv.y);
            size_t o0 = (size_t)r0 * 1024 + ccol;
            size_t o1 = o0 + 8 * 1024;
            hsplit2(Hd, Ld, o0, v0);
            hsplit2(Hd, Ld, o1, v1);
        }
    }
}

// =====================================================================
// K2: kvouter via fp16 mma. P = sk^T @ V, sk = elu(Kh+Kl)+1 (exact),
//     split fp16 hi/lo; A via trans-ldmatrix x4, B = Vh via trans x2.
//     Z col-sums exact fp32 during transform.
// smem: skh 32K | skl 32K | sv 32K | zsm 8K = 106496
// =====================================================================
__global__ __launch_bounds__(256, 1) void k_kvouter_mma()
{
    extern __shared__ __align__(16) char km[];
    char* skh = km;
    char* skl = km + 32768;
    char* sv  = km + 65536;
    float* zsm = (float*)(km + 98304);
    const uint32_t aH = smem_u32(skh), aL = smem_u32(skl), aV = smem_u32(sv);

    const int idx = blockIdx.x;                  // b*128 + h*16 + seg
    const int b = idx >> 7, h = (idx >> 4) & 7, seg = idx & 15;
    const int tid = threadIdx.x, lane = tid & 31, wid = tid >> 5;
    const int wm = (wid & 3) * 32, wn = (wid >> 2) * 64;
    const int krow = b * 8192 + seg * 512;
    const int hc = h * 128;

    // A trans lane mapping (m=dk from stored [L][dk])
    const int rLa = (lane & 7) + ((lane >> 4) & 1) * 8;   // + ks*16
    const int uAd = (lane >> 3) & 1;                      // + (wm+mt*16)>>3
    // B trans lane mapping
    const int rKt = (lane & 7) + ((lane >> 3) & 1) * 8;   // + ks*16
    // transform mapping (u fixed per thread)
    const int tr = tid >> 4, tu = tid & 15;

    float acc[2][8][4];
#pragma unroll
    for (int mt = 0; mt < 2; ++mt)
#pragma unroll
        for (int nt = 0; nt < 8; ++nt)
#pragma unroll
            for (int q = 0; q < 4; ++q) acc[mt][nt][q] = 0.f;
    float zacc[8] = {0.f,0.f,0.f,0.f,0.f,0.f,0.f,0.f};

    for (int ch = 0; ch < 4; ++ch) {
        __syncthreads();   // prev chunk mma done
        // V tile via cp.async
#pragma unroll
        for (int it = 0; it < 8; ++it) {
            int i2 = it * 256 + tid;
            int r = i2 >> 4, u = i2 & 15;
            cpa16(aV + r * 256 + (swu(u, r) << 4),
                  g_Vh + (size_t)(krow + ch * 128 + r) * 1024 + hc + u * 8);
        }
        CP_COMMIT();
        // K load + sk transform (two batches of 4 rows to bound registers)
#pragma unroll
        for (int half = 0; half < 2; ++half) {
            uint4 kh[4], kl[4];
#pragma unroll
            for (int it = 0; it < 4; ++it) {
                int r = tr + (half * 4 + it) * 16;
                size_t gs = (size_t)(krow + ch * 128 + r) * 1024 + hc + tu * 8;
                kh[it] = *(const uint4*)(g_Kh + gs);
                kl[it] = *(const uint4*)(g_Kl + gs);
            }
#pragma unroll
            for (int it = 0; it < 4; ++it) {
                int r = tr + (half * 4 + it) * 16;
                uint4 oh, ol;
                uint32_t* ph = (uint32_t*)&kh[it];
                uint32_t* pl = (uint32_t*)&kl[it];
                uint32_t* qh = (uint32_t*)&oh;
                uint32_t* ql = (uint32_t*)&ol;
#pragma unroll
                for (int w2 = 0; w2 < 4; ++w2) {
                    float2 fh = __half22float2(*(__half2*)&ph[w2]);
                    float2 fl = __half22float2(*(__half2*)&pl[w2]);
                    float s0 = elup1(fh.x + fl.x);
                    float s1 = elup1(fh.y + fl.y);
                    zacc[w2 * 2]     += s0;
                    zacc[w2 * 2 + 1] += s1;
                    __half h0 = __float2half_rn(s0), h1 = __float2half_rn(s1);
                    __half l0 = __float2half_rn(s0 - __half2float(h0));
                    __half l1 = __float2half_rn(s1 - __half2float(h1));
                    qh[w2] = (uint32_t)(*(uint16_t*)&h0) | ((uint32_t)(*(uint16_t*)&h1) << 16);
                    ql[w2] = (uint32_t)(*(uint16_t*)&l0) | ((uint32_t)(*(uint16_t*)&l1) << 16);
                }
                uint32_t so = r * 256 + (swu(tu, r) << 4);
                *(uint4*)(skh + so) = oh;
                *(uint4*)(skl + so) = ol;
            }
        }
        CP_WAIT0();
        __syncthreads();
        // mma: 2 passes (skh, skl) x Vh
        for (int pass = 0; pass < 2; ++pass) {
            const uint32_t Ab = pass ? aL : aH;
#pragma unroll
            for (int ks = 0; ks < 8; ++ks) {
                uint32_t af[2][4], bf[8][2];
#pragma unroll
                for (int mt = 0; mt < 2; ++mt) {
                    int rr = ks * 16 + rLa;
                    int uu = ((wm + mt * 16) >> 3) + uAd;
                    ldsm_x4t(af[mt][0], af[mt][1], af[mt][2], af[mt][3],
                             Ab + rr * 256 + (swu(uu, rr) << 4));
                }
                int rB = ks * 16 + rKt;
#pragma unroll
                for (int nt = 0; nt < 8; ++nt)
                    ldsm_x2t(bf[nt][0], bf[nt][1],
                             aV + rB * 256 + (swu((wn >> 3) + nt, rB) << 4));
#pragma unroll
                for (int nt = 0; nt < 8; ++nt)
#pragma unroll
                    for (int mt = 0; mt < 2; ++mt)
                        mma16816h(acc[mt][nt][0], acc[mt][nt][1], acc[mt][nt][2], acc[mt][nt][3],
                                  af[mt][0], af[mt][1], af[mt][2], af[mt][3],
                                  bf[nt][0], bf[nt][1]);
            }
        }
    }

    // epilogue: P
    const size_t pbase = (size_t)idx * 16384;
#pragma unroll
    for (int mt = 0; mt < 2; ++mt) {
        int r0 = wm + mt * 16 + (lane >> 2);
#pragma unroll
        for (int nt = 0; nt < 8; ++nt) {
            int col = wn + nt * 8 + ((lane & 3) << 1);
            *(float2*)&g_P[pbase + (size_t)r0 * 128 + col]       = make_float2(acc[mt][nt][0], acc[mt][nt][1]);
            *(float2*)&g_P[pbase + (size_t)(r0 + 8) * 128 + col] = make_float2(acc[mt][nt][2], acc[mt][nt][3]);
        }
    }
    // Z reduce
#pragma unroll
    for (int j = 0; j < 8; ++j) zsm[tr * 128 + tu * 8 + j] = zacc[j];
    __syncthreads();
    if (tid < 128) {
        float s = 0.f;
#pragma unroll
        for (int g = 0; g < 16; ++g) s += zsm[g * 128 + tid];
        g_Zseg[idx * 128 + tid] = 512.f * s;
    }
}

// =====================================================================
// K3: inclusive prefix over seg; writes fp16 hi/lo Mem splits + Z
// =====================================================================
__global__ __launch_bounds__(256) void k_prefix()
{
    const int bh = blockIdx.x;
    const int tid = threadIdx.x;
    float acc[64];
#pragma unroll
    for (int u = 0; u < 64; ++u) acc[u] = 0.f;
    float zacc = 0.f;
    for (int seg = 0; seg < 16; ++seg) {
        const size_t base = ((size_t)bh * 16 + seg) * 16384;
#pragma unroll
        for (int u = 0; u < 64; ++u) {
            acc[u] += g_P[base + u * 256 + tid];
            float v = acc[u];
            __half h = __float2half_rn(v);
            __half l = __float2half_rn(v - __half2float(h));
            g_Memh[base + u * 256 + tid] = h;
            g_Meml[base + u * 256 + tid] = l;
        }
        if (tid < 128) {
            zacc += g_Zseg[(bh * 16 + seg) * 128 + tid];
            g_Z[(bh * 16 + seg) * 128 + tid] = zacc;
        }
    }
}

// =====================================================================
// K4: fp16 mma attention, cp.async double-buffered tiles.
// smem: Sc 132096 | sAh 16384 | sAl 16384 | sB0 32768 | sB1 32768 | ctl
// =====================================================================
__global__ __launch_bounds__(256, 1) void k_attn_mma(const float* __restrict__ beta,
                                                     float* __restrict__ out)
{
    extern __shared__ __align__(16) char smraw[];
    float* Sc = (float*)smraw;                       // 132096
    char* sAh = smraw + 132096;
    char* sAl = sAh + 16384;
    char* sB0 = sAl + 16384;
    char* sB1 = sB0 + 32768;
    float* zs  = (float*)(sB1 + 32768);              // 128
    float* rs  = zs + 128;                           // 64
    float* den = rs + 64;                            // 64
    const uint32_t aAh = smem_u32(sAh), aAl = smem_u32(sAl);
    const uint32_t aB0 = smem_u32(sB0), aB1 = smem_u32(sB1);

    const int idx = blockIdx.x;                      // b*128 + seg*8 + qt
    const int b = idx >> 7, seg = (idx >> 3) & 15, qt = idx & 7;
    const int tid = threadIdx.x, lane = tid & 31, wid = tid >> 5;
    const int wm2 = (wid >> 2) * 32, wn2 = (wid & 3) * 32;
    const int qrow0 = b * 8192 + seg * 512 + qt * 64;
    const int krow0 = b * 8192 + seg * 512;
    const float bsig = 1.f / (1.f + __expf(-beta[0]));
    const float bsig8 = bsig * 0.125f, obsig8 = (1.f - bsig) * 0.125f;
    const float scale = 0.088388347648318447f;

    const int rowA0 = wm2 + (lane & 15);
    const int unA = lane >> 4;
    const int rowBn = wn2 + (lane & 7);
    const int unB = (lane >> 3) & 1;
    const int rowKt = (lane & 7) + ((lane >> 3) & 1) * 8;
    const int srow = tid >> 2, spart = tid & 3;

    // tile-load helper: 8x cpa16 per thread (32KB tile, rows [base..base+128))
    auto issue_tile = [&](uint32_t dst, const __half* src, int rowbase, int hcc) {
#pragma unroll
        for (int it = 0; it < 8; ++it) {
            int i2 = it * 256 + tid;
            int r = i2 >> 4, u = i2 & 15;
            cpa16(dst + r * 256 + (swu(u, r) << 4),
                  src + (size_t)(rowbase + r) * 1024 + hcc + u * 8);
        }
    };

    float facc[2][4][4];
#pragma unroll
    for (int mt = 0; mt < 2; ++mt)
#pragma unroll
        for (int nt = 0; nt < 4; ++nt)
#pragma unroll
            for (int q = 0; q < 4; ++q) facc[mt][nt][q] = 0.f;

    for (int h = 0; h < 8; ++h) {
        const int hc = h * 128;
        __syncthreads();   // prev head done; sA, sB free
        // prefetch K chunk0
        issue_tile(aB0, g_Kh, krow0, hc);
        CP_COMMIT();
        // Q load (direct) into sA
#pragma unroll
        for (int it = 0; it < 4; ++it) {
            int i2 = it * 256 + tid;
            int r = i2 >> 4, u = i2 & 15;
            size_t gs = (size_t)(qrow0 + r) * 1024 + hc + u * 8;
            uint32_t so = r * 256 + (swu(u, r) << 4);
            *(uint4*)(sAh + so) = *(const uint4*)(g_Qh + gs);
            *(uint4*)(sAl + so) = *(const uint4*)(g_Ql + gs);
        }
        if (tid < 128)
            zs[tid] = g_Z[((size_t)(b * 8 + h) * 16 + seg) * 128 + tid];

        // ---- scores: 4 chunks, double-buffered K; chunk3 also prefetches Mem ----
        for (int kc = 0; kc < 4; ++kc) {
            CP_WAIT0();
            __syncthreads();   // chunk kc data + Q stores (kc==0) + prev mma done
            if (kc < 3) { issue_tile((kc & 1) ? aB0 : aB1, g_Kh, krow0 + (kc + 1) * 128, hc); CP_COMMIT(); }
            else {
                // prefetch Mem into buf0 (buf0 free: chunk2 mma done)
#pragma unroll
                for (int it = 0; it < 8; ++it) {
                    int i2 = it * 256 + tid;
                    int r = i2 >> 4, u = i2 & 15;
                    size_t ms = ((size_t)(b * 8 + h) * 16 + seg) * 16384 + r * 128 + u * 8;
                    cpa16(aB0 + r * 256 + (swu(u, r) << 4), g_Memh + ms);
                }
                CP_COMMIT();
            }
            const uint32_t Bb = (kc & 1) ? aB1 : aB0;
            float acc[2][4][4];
#pragma unroll
            for (int mt = 0; mt < 2; ++mt)
#pragma unroll
                for (int nt = 0; nt < 4; ++nt)
#pragma unroll
                    for (int q = 0; q < 4; ++q) acc[mt][nt][q] = 0.f;
            for (int pass = 0; pass < 2; ++pass) {
                const uint32_t Ab = pass ? aAl : aAh;
#pragma unroll
                for (int ks = 0; ks < 8; ++ks) {
                    uint32_t af[2][4], bfr[4][2];
#pragma unroll
                    for (int mt = 0; mt < 2; ++mt)
                        ldsm_x4(af[mt][0], af[mt][1], af[mt][2], af[mt][3],
                                Ab + (rowA0 + mt * 16) * 256 + (swu(ks * 2 + unA, rowA0) << 4));
#pragma unroll
                    for (int nt = 0; nt < 4; ++nt)
                        ldsm_x2(bfr[nt][0], bfr[nt][1],
                                Bb + (rowBn + nt * 8) * 256 + (swu(ks * 2 + unB, rowBn) << 4));
#pragma unroll
                    for (int nt = 0; nt < 4; ++nt)
#pragma unroll
                        for (int mt = 0; mt < 2; ++mt)
                            mma16816h(acc[mt][nt][0], acc[mt][nt][1], acc[mt][nt][2], acc[mt][nt][3],
                                      af[mt][0], af[mt][1], af[mt][2], af[mt][3],
                                      bfr[nt][0], bfr[nt][1]);
                }
            }
#pragma unroll
            for (int mt = 0; mt < 2; ++mt) {
                int r0 = wm2 + mt * 16 + (lane >> 2);
#pragma unroll
                for (int nt = 0; nt < 4; ++nt) {
                    int cc = kc * 128 + wn2 + nt * 8 + ((lane & 3) << 1);
                    *(float2*)&Sc[r0 * 516 + cc]       = make_float2(acc[mt][nt][0] * scale, acc[mt][nt][1] * scale);
                    *(float2*)&Sc[(r0 + 8) * 516 + cc] = make_float2(acc[mt][nt][2] * scale, acc[mt][nt][3] * scale);
                }
            }
        }
        __syncthreads();   // Sc complete; chunk3 mma done by all
        // prefetch V chunk0 into buf1
        issue_tile(aB1, g_Vh, krow0, hc);
        CP_COMMIT();
        // ---- softmax (bank-rotated scan) ----
        {
            float* rowp = &Sc[srow * 516 + spart * 128];
            const int rot = spart * 8;
            float m = -1e30f;
#pragma unroll 8
            for (int j = 0; j < 128; ++j) m = fmaxf(m, rowp[(j + rot) & 127]);
            m = fmaxf(m, __shfl_xor_sync(0xffffffffu, m, 1));
            m = fmaxf(m, __shfl_xor_sync(0xffffffffu, m, 2));
            float s = 0.f;
#pragma unroll 8
            for (int j = 0; j < 128; ++j) {
                int jj = (j + rot) & 127;
                float e = __expf(rowp[jj] - m); rowp[jj] = e; s += e;
            }
            s += __shfl_xor_sync(0xffffffffu, s, 1);
            s += __shfl_xor_sync(0xffffffffu, s, 2);
            if (spart == 0) rs[srow] = s;
        }
        // ---- sq transform + exact den ----
        {
            float da = 0.f;
#pragma unroll 4
            for (int j = 0; j < 32; ++j) {
                int c = spart * 32 + j;
                uint32_t bo = srow * 256 + (swu(c >> 3, srow) << 4) + ((c & 7) << 1);
                float qh = __half2float(*(__half*)(sAh + bo));
                float ql = __half2float(*(__half*)(sAl + bo));
                float sq = elup1(qh + ql);
                da += sq * zs[c];
                __half hh = __float2half_rn(sq);
                __half ll = __float2half_rn(sq - __half2float(hh));
                *(__half*)(sAh + bo) = hh;
                *(__half*)(sAl + bo) = ll;
            }
            da += __shfl_xor_sync(0xffffffffu, da, 1);
            da += __shfl_xor_sync(0xffffffffu, da, 2);
            if (spart == 0) den[srow] = da;
        }
        CP_WAIT1();        // Mem (older group) complete; V0 may be pending
        __syncthreads();   // transform + Mem visible to all
        // ---- retrieval: 2-pass (sqh, sql) x Memh (buf0) ----
        {
            float acc[2][4][4];
#pragma unroll
            for (int mt = 0; mt < 2; ++mt)
#pragma unroll
                for (int nt = 0; nt < 4; ++nt)
#pragma unroll
                    for (int q = 0; q < 4; ++q) acc[mt][nt][q] = 0.f;
            for (int pass = 0; pass < 2; ++pass) {
                const uint32_t Ab = pass ? aAl : aAh;
#pragma unroll
                for (int ks = 0; ks < 8; ++ks) {
                    uint32_t af[2][4], bfr[4][2];
#pragma unroll
                    for (int mt = 0; mt < 2; ++mt)
                        ldsm_x4(af[mt][0], af[mt][1], af[mt][2], af[mt][3],
                                Ab + (rowA0 + mt * 16) * 256 + (swu(ks * 2 + unA, rowA0) << 4));
                    int rK = ks * 16 + rowKt;
#pragma unroll
                    for (int nt = 0; nt < 4; ++nt)
                        ldsm_x2t(bfr[nt][0], bfr[nt][1],
                                 aB0 + rK * 256 + (swu((wn2 >> 3) + nt, rK) << 4));
#pragma unroll
                    for (int nt = 0; nt < 4; ++nt)
#pragma unroll
                        for (int mt = 0; mt < 2; ++mt)
                            mma16816h(acc[mt][nt][0], acc[mt][nt][1], acc[mt][nt][2], acc[mt][nt][3],
                                      af[mt][0], af[mt][1], af[mt][2], af[mt][3],
                                      bfr[nt][0], bfr[nt][1]);
                }
            }
#pragma unroll
            for (int mt = 0; mt < 2; ++mt) {
                int r0 = wm2 + mt * 16 + (lane >> 2);
                float m0 = bsig8 / (den[r0] + 1e-5f);
                float m1 = bsig8 / (den[r0 + 8] + 1e-5f);
#pragma unroll
                for (int nt = 0; nt < 4; ++nt) {
                    facc[mt][nt][0] += acc[mt][nt][0] * m0;
                    facc[mt][nt][1] += acc[mt][nt][1] * m0;
                    facc[mt][nt][2] += acc[mt][nt][2] * m1;
                    facc[mt][nt][3] += acc[mt][nt][3] * m1;
                }
            }
        }
        // ---- PV: double-buffered V, single-pass P x Vh ----
        float dacc[2][4][4];
#pragma unroll
        for (int mt = 0; mt < 2; ++mt)
#pragma unroll
            for (int nt = 0; nt < 4; ++nt)
#pragma unroll
                for (int q = 0; q < 4; ++q) dacc[mt][nt][q] = 0.f;
        for (int kc = 0; kc < 4; ++kc) {
            __syncthreads();   // prev mma done; sA pack & buffer reuse safe
#pragma unroll
            for (int it = 0; it < 4; ++it) {
                int i2 = it * 256 + tid;
                int r = i2 >> 4, u = i2 & 15;
                const float* sp = &Sc[r * 516 + kc * 128 + u * 8];
                float4 p0 = *(const float4*)sp, p1 = *(const float4*)(sp + 4);
                uint4 hi;
                hi.x = packhf(p0.x, p0.y); hi.y = packhf(p0.z, p0.w);
                hi.z = packhf(p1.x, p1.y); hi.w = packhf(p1.z, p1.w);
                uint32_t so = r * 256 + (swu(u, r) << 4);
                *(uint4*)(sAh + so) = hi;
            }
            if (kc < 3) {
                issue_tile((kc & 1) ? aB1 : aB0, g_Vh, krow0 + (kc + 1) * 128, hc);
                CP_COMMIT();
                CP_WAIT1();    // V_kc (older) complete
            } else {
                CP_WAIT0();
            }
            __syncthreads();   // pack + V_kc visible
            const uint32_t vB = (kc & 1) ? aB0 : aB1;
#pragma unroll
            for (int ks = 0; ks < 8; ++ks) {
                uint32_t af[2][4], bfr[4][2];
#pragma unroll
                for (int mt = 0; mt < 2; ++mt)
                    ldsm_x4(af[mt][0], af[mt][1], af[mt][2], af[mt][3],
                            aAh + (rowA0 + mt * 16) * 256 + (swu(ks * 2 + unA, rowA0) << 4));
                int rK = ks * 16 + rowKt;
#pragma unroll
                for (int nt = 0; nt < 4; ++nt)
                    ldsm_x2t(bfr[nt][0], bfr[nt][1],
                             vB + rK * 256 + (swu((wn2 >> 3) + nt, rK) << 4));
#pragma unroll
                for (int nt = 0; nt < 4; ++nt)
#pragma unroll
                    for (int mt = 0; mt < 2; ++mt)
                        mma16816h(dacc[mt][nt][0], dacc[mt][nt][1], dacc[mt][nt][2], dacc[mt][nt][3],
                                  af[mt][0], af[mt][1], af[mt][2], af[mt][3],
                                  bfr[nt][0], bfr[nt][1]);
            }
        }
#pragma unroll
        for (int mt = 0; mt < 2; ++mt) {
            int r0 = wm2 + mt * 16 + (lane >> 2);
            float d0 = obsig8 / rs[r0];
            float d1 = obsig8 / rs[r0 + 8];
#pragma unroll
            for (int nt = 0; nt < 4; ++nt) {
                facc[mt][nt][0] += dacc[mt][nt][0] * d0;
                facc[mt][nt][1] += dacc[mt][nt][1] * d0;
                facc[mt][nt][2] += dacc[mt][nt][2] * d1;
                facc[mt][nt][3] += dacc[mt][nt][3] * d1;
            }
        }
    }

#pragma unroll
    for (int mt = 0; mt < 2; ++mt) {
        int r0 = wm2 + mt * 16 + (lane >> 2);
#pragma unroll
        for (int nt = 0; nt < 4; ++nt) {
            int col = wn2 + nt * 8 + ((lane & 3) << 1);
            *(float2*)&out[(size_t)(qrow0 + r0) * 128 + col]     = make_float2(facc[mt][nt][0], facc[mt][nt][1]);
            *(float2*)&out[(size_t)(qrow0 + r0 + 8) * 128 + col] = make_float2(facc[mt][nt][2], facc[mt][nt][3]);
        }
    }
}

// =====================================================================
extern "C" void kernel_launch(void* const* d_in, const int* in_sizes, int n_in,
                              void* d_out, int out_size)
{
    const float* x    = (const float*)d_in[0];
    const float* wq   = (const float*)d_in[1];
    const float* bq   = (const float*)d_in[2];
    const float* wk   = (const float*)d_in[3];
    const float* bk   = (const float*)d_in[4];
    const float* wv   = (const float*)d_in[5];
    const float* bv   = (const float*)d_in[6];
    const float* beta = (const float*)d_in[7];
    float* out = (float*)d_out;

    static int attr_set = 0;
    if (!attr_set) {
        cudaFuncSetAttribute(k_attn_mma, cudaFuncAttributeMaxDynamicSharedMemorySize, 231424);
        cudaFuncSetAttribute(k_proj_mma, cudaFuncAttributeMaxDynamicSharedMemorySize, 147456);
        cudaFuncSetAttribute(k_kvouter_mma, cudaFuncAttributeMaxDynamicSharedMemorySize, 106496);
        attr_set = 1;
    }

    k_splitX<<<32768, 256>>>(x);
    k_trW<<<dim3(32, 32), 256>>>(wq, 0);
    k_trW<<<dim3(32, 32), 256>>>(wk, 1);
    k_trW<<<dim3(32, 32), 256>>>(wv, 2);
    k_proj_mma<<<dim3(8, 256, 3), 512, 147456>>>(bq, bk, bv);
    k_kvouter_mma<<<512, 256, 106496>>>();
    k_prefix<<<32, 256>>>();
    k_attn_mma<<<512, 256, 231424>>>(beta, out);
}

// round 13
// speedup vs baseline: 1.7430x; 1.1743x over previous
#include <cuda_runtime.h>
#include <cuda_fp16.h>
#include <cstdint>

// ---------- helpers ----------
__device__ __forceinline__ float elup1(float x){ return x > 0.f ? x + 1.f : __expf(x); }
__device__ __forceinline__ uint32_t smem_u32(const void* p){
    uint32_t a;
    asm("{ .reg .u64 t; cvta.to.shared.u64 t, %1; cvt.u32.u64 %0, t; }" : "=r"(a) : "l"(p));
    return a;
}
__device__ __forceinline__ void cpa16(uint32_t smaddr, const void* g){
    asm volatile("cp.async.cg.shared.global [%0], [%1], 16;" :: "r"(smaddr), "l"(g));
}
#define CP_COMMIT() asm volatile("cp.async.commit_group;" ::: "memory")
#define CP_WAIT0()  asm volatile("cp.async.wait_group 0;" ::: "memory")
#define CP_WAIT1()  asm volatile("cp.async.wait_group 1;" ::: "memory")
__device__ __forceinline__ void ldsm_x4(uint32_t &r0, uint32_t &r1, uint32_t &r2, uint32_t &r3, uint32_t addr){
    asm volatile("ldmatrix.sync.aligned.m8n8.x4.shared.b16 {%0,%1,%2,%3}, [%4];"
        : "=r"(r0), "=r"(r1), "=r"(r2), "=r"(r3) : "r"(addr));
}
__device__ __forceinline__ void ldsm_x4t(uint32_t &r0, uint32_t &r1, uint32_t &r2, uint32_t &r3, uint32_t addr){
    asm volatile("ldmatrix.sync.aligned.m8n8.x4.trans.shared.b16 {%0,%1,%2,%3}, [%4];"
        : "=r"(r0), "=r"(r1), "=r"(r2), "=r"(r3) : "r"(addr));
}
__device__ __forceinline__ void ldsm_x2(uint32_t &r0, uint32_t &r1, uint32_t addr){
    asm volatile("ldmatrix.sync.aligned.m8n8.x2.shared.b16 {%0,%1}, [%2];"
        : "=r"(r0), "=r"(r1) : "r"(addr));
}
__device__ __forceinline__ void ldsm_x2t(uint32_t &r0, uint32_t &r1, uint32_t addr){
    asm volatile("ldmatrix.sync.aligned.m8n8.x2.trans.shared.b16 {%0,%1}, [%2];"
        : "=r"(r0), "=r"(r1) : "r"(addr));
}
__device__ __forceinline__ void mma16816h(float &c0, float &c1, float &c2, float &c3,
                                          uint32_t a0, uint32_t a1, uint32_t a2, uint32_t a3,
                                          uint32_t b0, uint32_t b1){
    asm volatile("mma.sync.aligned.m16n8k16.row.col.f32.f16.f16.f32 "
        "{%0,%1,%2,%3}, {%4,%5,%6,%7}, {%8,%9}, {%0,%1,%2,%3};"
        : "+f"(c0), "+f"(c1), "+f"(c2), "+f"(c3)
        : "r"(a0), "r"(a1), "r"(a2), "r"(a3), "r"(b0), "r"(b1));
}
__device__ __forceinline__ uint32_t swu(int u, int r){ return (uint32_t)((u & 8) | ((u & 7) ^ (r & 7))); }
__device__ __forceinline__ uint32_t packhf(float a, float b){
    __half2 t = __halves2half2(__float2half_rn(a), __float2half_rn(b));
    return *(uint32_t*)&t;
}
__device__ __forceinline__ void hsplit2(__half* H, __half* L, size_t off, float2 v){
    __half hx = __float2half_rn(v.x), hy = __float2half_rn(v.y);
    __half lx = __float2half_rn(v.x - __half2float(hx));
    __half ly = __float2half_rn(v.y - __half2float(hy));
    *(__half2*)(H + off) = __halves2half2(hx, hy);
    *(__half2*)(L + off) = __halves2half2(lx, ly);
}

// ---------- dims: B=4, S=8192, D=1024, H=8, dk=dv=128, SEG=512, nseg=16 ----------

// ---------- device scratch ----------
__device__ float g_P[8388608];
__device__ float g_Zseg[65536];
__device__ float g_Z[65536];
__device__ __half g_Xh[33554432];
__device__ __half g_Wh[3145728];
__device__ __half g_Qh[33554432];
__device__ __half g_Ql[33554432];
__device__ __half g_Kh[33554432];
__device__ __half g_Kl[33554432];
__device__ __half g_Vh[33554432];
__device__ __half g_Vl[33554432];
__device__ __half g_Memh[8388608];
__device__ __half g_Meml[8388608];

// =====================================================================
// S1: X -> fp16 (hi only; single-pass projection)
// =====================================================================
__global__ __launch_bounds__(256) void k_splitX(const float* __restrict__ x)
{
    size_t i = ((size_t)blockIdx.x * 256 + threadIdx.x) * 4;
    float4 v = *(const float4*)(x + i);
    __half2 a = __halves2half2(__float2half_rn(v.x), __float2half_rn(v.y));
    __half2 b = __halves2half2(__float2half_rn(v.z), __float2half_rn(v.w));
    *(__half2*)(g_Xh + i)     = a;
    *(__half2*)(g_Xh + i + 2) = b;
}

// =====================================================================
// S2: transpose W[k][n] -> Wt[n][k], fp16
// =====================================================================
__global__ __launch_bounds__(256) void k_trW(const float* __restrict__ w, int which)
{
    __shared__ float t[32][33];
    const int bx = blockIdx.x << 5, by = blockIdx.y << 5;
    const int tx = threadIdx.x & 31, ty = threadIdx.x >> 5;
#pragma unroll
    for (int r = 0; r < 4; ++r)
        t[ty * 4 + r][tx] = w[(size_t)(by + ty * 4 + r) * 1024 + bx + tx];
    __syncthreads();
    __half* Wt = g_Wh + (size_t)which * 1048576;
#pragma unroll
    for (int r = 0; r < 4; ++r) {
        int n = bx + ty * 4 + r, k = by + tx;
        Wt[(size_t)n * 1024 + k] = __float2half_rn(t[tx][ty * 4 + r]);
    }
}

// =====================================================================
// K1: fused projection GEMM, fp16 SINGLE-PASS (Xh x Wh).
//     512 thr, 16 warps (4x4, warp tile 32x32), cp.async 3-stage (32KB).
// =====================================================================
__global__ __launch_bounds__(512, 1) void k_proj_mma(const float* __restrict__ bq,
                                                     const float* __restrict__ bk,
                                                     const float* __restrict__ bv)
{
    extern __shared__ __align__(128) char sm_raw[];
    const uint32_t smbase = smem_u32(sm_raw);

    const int which = blockIdx.z;
    const float* bias = (which == 0) ? bq : ((which == 1) ? bk : bv);
    __half* Hd = (which == 0) ? g_Qh : ((which == 1) ? g_Kh : g_Vh);
    __half* Ld = (which == 0) ? g_Ql : ((which == 1) ? g_Kl : g_Vl);
    const __half* Wt = g_Wh + (size_t)which * 1048576;

    const int tid = threadIdx.x, lane = tid & 31, wid = tid >> 5;
    const int wm = (wid >> 2) * 32, wn = (wid & 3) * 32;
    const int row0 = blockIdx.y << 7, col0 = blockIdx.x << 7;

    const int rowA = wm + (lane & 15);
    const int rA7 = rowA & 7;
    const int unA = lane >> 4;
    const int rowB = wn + (lane & 7);
    const int rB7 = lane & 7;
    const int unB = (lane >> 3) & 1;
    const int lr = tid >> 3, lu = tid & 7;

    float cf[2][4][4];
#pragma unroll
    for (int mt = 0; mt < 2; ++mt)
#pragma unroll
        for (int nt = 0; nt < 4; ++nt)
#pragma unroll
            for (int q = 0; q < 4; ++q) cf[mt][nt][q] = 0.f;

    // stage: Xh @0 (16KB), Wh @16384 -> 32768 B/stage
    auto load_chunk = [&](int c, int stage) {
        const int k0 = c << 6;
        const uint32_t st = smbase + stage * 32768;
#pragma unroll
        for (int it = 0; it < 2; ++it) {
            int r = lr + it * 64;
            size_t ga = (size_t)(row0 + r) * 1024 + k0 + lu * 8;
            size_t gb = (size_t)(col0 + r) * 1024 + k0 + lu * 8;
            uint32_t so = r * 128 + ((lu ^ (r & 7)) << 4);
            cpa16(st + so,         g_Xh + ga);
            cpa16(st + 16384 + so, Wt + gb);
        }
    };

    load_chunk(0, 0); CP_COMMIT();
    load_chunk(1, 1); CP_COMMIT();

    for (int c = 0; c < 16; ++c) {
        CP_WAIT1();
        __syncthreads();
        if (c + 2 < 16) load_chunk(c + 2, (c + 2) % 3);
        CP_COMMIT();
        const uint32_t st = smbase + (c % 3) * 32768;
#pragma unroll
        for (int ks = 0; ks < 4; ++ks) {
            uint32_t ah[2][4], bh[4][2];
#pragma unroll
            for (int mt = 0; mt < 2; ++mt) {
                uint32_t off = (rowA + mt * 16) * 128 + ((((ks << 1) + unA) ^ rA7) << 4);
                ldsm_x4(ah[mt][0], ah[mt][1], ah[mt][2], ah[mt][3], st + off);
            }
#pragma unroll
            for (int nt = 0; nt < 4; ++nt) {
                uint32_t off = (rowB + nt * 8) * 128 + ((((ks << 1) + unB) ^ rB7) << 4);
                ldsm_x2(bh[nt][0], bh[nt][1], st + 16384 + off);
            }
#pragma unroll
            for (int nt = 0; nt < 4; ++nt)
#pragma unroll
                for (int mt = 0; mt < 2; ++mt)
                    mma16816h(cf[mt][nt][0], cf[mt][nt][1], cf[mt][nt][2], cf[mt][nt][3],
                              ah[mt][0], ah[mt][1], ah[mt][2], ah[mt][3], bh[nt][0], bh[nt][1]);
        }
    }

#pragma unroll
    for (int mt = 0; mt < 2; ++mt) {
        const int r0 = row0 + wm + mt * 16 + (lane >> 2);
#pragma unroll
        for (int nt = 0; nt < 4; ++nt) {
            const int ccol = col0 + wn + nt * 8 + ((lane & 3) << 1);
            const float2 bvv = *(const float2*)&bias[ccol];
            float2 v0 = make_float2(cf[mt][nt][0] + bvv.x, cf[mt][nt][1] + bvv.y);
            float2 v1 = make_float2(cf[mt][nt][2] + bvv.x, cf[mt][nt][3] + bvv.y);
            size_t o0 = (size_t)r0 * 1024 + ccol;
            size_t o1 = o0 + 8 * 1024;
            hsplit2(Hd, Ld, o0, v0);
            hsplit2(Hd, Ld, o1, v1);
        }
    }
}

// =====================================================================
// K2: kvouter via fp16 mma. P = sk^T @ V, sk = elu(Kh+Kl)+1 (exact),
//     split fp16 hi/lo; Z col-sums exact fp32.
// smem: skh 32K | skl 32K | sv 32K | zsm 8K = 106496
// =====================================================================
__global__ __launch_bounds__(256, 1) void k_kvouter_mma()
{
    extern __shared__ __align__(16) char km[];
    char* skh = km;
    char* skl = km + 32768;
    char* sv  = km + 65536;
    float* zsm = (float*)(km + 98304);
    const uint32_t aH = smem_u32(skh), aL = smem_u32(skl), aV = smem_u32(sv);

    const int idx = blockIdx.x;                  // b*128 + h*16 + seg
    const int b = idx >> 7, h = (idx >> 4) & 7, seg = idx & 15;
    const int tid = threadIdx.x, lane = tid & 31, wid = tid >> 5;
    const int wm = (wid & 3) * 32, wn = (wid >> 2) * 64;
    const int krow = b * 8192 + seg * 512;
    const int hc = h * 128;

    const int rLa = (lane & 7) + ((lane >> 4) & 1) * 8;
    const int uAd = (lane >> 3) & 1;
    const int rKt = (lane & 7) + ((lane >> 3) & 1) * 8;
    const int tr = tid >> 4, tu = tid & 15;

    float acc[2][8][4];
#pragma unroll
    for (int mt = 0; mt < 2; ++mt)
#pragma unroll
        for (int nt = 0; nt < 8; ++nt)
#pragma unroll
            for (int q = 0; q < 4; ++q) acc[mt][nt][q] = 0.f;
    float zacc[8] = {0.f,0.f,0.f,0.f,0.f,0.f,0.f,0.f};

    for (int ch = 0; ch < 4; ++ch) {
        __syncthreads();
#pragma unroll
        for (int it = 0; it < 8; ++it) {
            int i2 = it * 256 + tid;
            int r = i2 >> 4, u = i2 & 15;
            cpa16(aV + r * 256 + (swu(u, r) << 4),
                  g_Vh + (size_t)(krow + ch * 128 + r) * 1024 + hc + u * 8);
        }
        CP_COMMIT();
#pragma unroll
        for (int half = 0; half < 2; ++half) {
            uint4 kh[4], kl[4];
#pragma unroll
            for (int it = 0; it < 4; ++it) {
                int r = tr + (half * 4 + it) * 16;
                size_t gs = (size_t)(krow + ch * 128 + r) * 1024 + hc + tu * 8;
                kh[it] = *(const uint4*)(g_Kh + gs);
                kl[it] = *(const uint4*)(g_Kl + gs);
            }
#pragma unroll
            for (int it = 0; it < 4; ++it) {
                int r = tr + (half * 4 + it) * 16;
                uint4 oh, ol;
                uint32_t* ph = (uint32_t*)&kh[it];
                uint32_t* pl = (uint32_t*)&kl[it];
                uint32_t* qh = (uint32_t*)&oh;
                uint32_t* ql = (uint32_t*)&ol;
#pragma unroll
                for (int w2 = 0; w2 < 4; ++w2) {
                    float2 fh = __half22float2(*(__half2*)&ph[w2]);
                    float2 fl = __half22float2(*(__half2*)&pl[w2]);
                    float s0 = elup1(fh.x + fl.x);
                    float s1 = elup1(fh.y + fl.y);
                    zacc[w2 * 2]     += s0;
                    zacc[w2 * 2 + 1] += s1;
                    __half h0 = __float2half_rn(s0), h1 = __float2half_rn(s1);
                    __half l0 = __float2half_rn(s0 - __half2float(h0));
                    __half l1 = __float2half_rn(s1 - __half2float(h1));
                    qh[w2] = (uint32_t)(*(uint16_t*)&h0) | ((uint32_t)(*(uint16_t*)&h1) << 16);
                    ql[w2] = (uint32_t)(*(uint16_t*)&l0) | ((uint32_t)(*(uint16_t*)&l1) << 16);
                }
                uint32_t so = r * 256 + (swu(tu, r) << 4);
                *(uint4*)(skh + so) = oh;
                *(uint4*)(skl + so) = ol;
            }
        }
        CP_WAIT0();
        __syncthreads();
        for (int pass = 0; pass < 2; ++pass) {
            const uint32_t Ab = pass ? aL : aH;
#pragma unroll
            for (int ks = 0; ks < 8; ++ks) {
                uint32_t af[2][4], bf[8][2];
#pragma unroll
                for (int mt = 0; mt < 2; ++mt) {
                    int rr = ks * 16 + rLa;
                    int uu = ((wm + mt * 16) >> 3) + uAd;
                    ldsm_x4t(af[mt][0], af[mt][1], af[mt][2], af[mt][3],
                             Ab + rr * 256 + (swu(uu, rr) << 4));
                }
                int rB = ks * 16 + rKt;
#pragma unroll
                for (int nt = 0; nt < 8; ++nt)
                    ldsm_x2t(bf[nt][0], bf[nt][1],
                             aV + rB * 256 + (swu((wn >> 3) + nt, rB) << 4));
#pragma unroll
                for (int nt = 0; nt < 8; ++nt)
#pragma unroll
                    for (int mt = 0; mt < 2; ++mt)
                        mma16816h(acc[mt][nt][0], acc[mt][nt][1], acc[mt][nt][2], acc[mt][nt][3],
                                  af[mt][0], af[mt][1], af[mt][2], af[mt][3],
                                  bf[nt][0], bf[nt][1]);
            }
        }
    }

    const size_t pbase = (size_t)idx * 16384;
#pragma unroll
    for (int mt = 0; mt < 2; ++mt) {
        int r0 = wm + mt * 16 + (lane >> 2);
#pragma unroll
        for (int nt = 0; nt < 8; ++nt) {
            int col = wn + nt * 8 + ((lane & 3) << 1);
            *(float2*)&g_P[pbase + (size_t)r0 * 128 + col]       = make_float2(acc[mt][nt][0], acc[mt][nt][1]);
            *(float2*)&g_P[pbase + (size_t)(r0 + 8) * 128 + col] = make_float2(acc[mt][nt][2], acc[mt][nt][3]);
        }
    }
#pragma unroll
    for (int j = 0; j < 8; ++j) zsm[tr * 128 + tu * 8 + j] = zacc[j];
    __syncthreads();
    if (tid < 128) {
        float s = 0.f;
#pragma unroll
        for (int g = 0; g < 16; ++g) s += zsm[g * 128 + tid];
        g_Zseg[idx * 128 + tid] = 512.f * s;
    }
}

// =====================================================================
// K3: inclusive prefix over seg; writes fp16 hi/lo Mem splits + Z
// =====================================================================
__global__ __launch_bounds__(256) void k_prefix()
{
    const int bh = blockIdx.x;
    const int tid = threadIdx.x;
    float acc[64];
#pragma unroll
    for (int u = 0; u < 64; ++u) acc[u] = 0.f;
    float zacc = 0.f;
    for (int seg = 0; seg < 16; ++seg) {
        const size_t base = ((size_t)bh * 16 + seg) * 16384;
#pragma unroll
        for (int u = 0; u < 64; ++u) {
            acc[u] += g_P[base + u * 256 + tid];
            float v = acc[u];
            __half h = __float2half_rn(v);
            __half l = __float2half_rn(v - __half2float(h));
            g_Memh[base + u * 256 + tid] = h;
            g_Meml[base + u * 256 + tid] = l;
        }
        if (tid < 128) {
            zacc += g_Zseg[(bh * 16 + seg) * 128 + tid];
            g_Z[(bh * 16 + seg) * 128 + tid] = zacc;
        }
    }
}

// =====================================================================
// K4: fp16 mma attention, cp.async double-buffered tiles.
// =====================================================================
__global__ __launch_bounds__(256, 1) void k_attn_mma(const float* __restrict__ beta,
                                                     float* __restrict__ out)
{
    extern __shared__ __align__(16) char smraw[];
    float* Sc = (float*)smraw;                       // 132096
    char* sAh = smraw + 132096;
    char* sAl = sAh + 16384;
    char* sB0 = sAl + 16384;
    char* sB1 = sB0 + 32768;
    float* zs  = (float*)(sB1 + 32768);              // 128
    float* rs  = zs + 128;                           // 64
    float* den = rs + 64;                            // 64
    const uint32_t aAh = smem_u32(sAh), aAl = smem_u32(sAl);
    const uint32_t aB0 = smem_u32(sB0), aB1 = smem_u32(sB1);

    const int idx = blockIdx.x;                      // b*128 + seg*8 + qt
    const int b = idx >> 7, seg = (idx >> 3) & 15, qt = idx & 7;
    const int tid = threadIdx.x, lane = tid & 31, wid = tid >> 5;
    const int wm2 = (wid >> 2) * 32, wn2 = (wid & 3) * 32;
    const int qrow0 = b * 8192 + seg * 512 + qt * 64;
    const int krow0 = b * 8192 + seg * 512;
    const float bsig = 1.f / (1.f + __expf(-beta[0]));
    const float bsig8 = bsig * 0.125f, obsig8 = (1.f - bsig) * 0.125f;
    const float scale = 0.088388347648318447f;

    const int rowA0 = wm2 + (lane & 15);
    const int unA = lane >> 4;
    const int rowBn = wn2 + (lane & 7);
    const int unB = (lane >> 3) & 1;
    const int rowKt = (lane & 7) + ((lane >> 3) & 1) * 8;
    const int srow = tid >> 2, spart = tid & 3;

    auto issue_tile = [&](uint32_t dst, const __half* src, int rowbase, int hcc) {
#pragma unroll
        for (int it = 0; it < 8; ++it) {
            int i2 = it * 256 + tid;
            int r = i2 >> 4, u = i2 & 15;
            cpa16(dst + r * 256 + (swu(u, r) << 4),
                  src + (size_t)(rowbase + r) * 1024 + hcc + u * 8);
        }
    };

    float facc[2][4][4];
#pragma unroll
    for (int mt = 0; mt < 2; ++mt)
#pragma unroll
        for (int nt = 0; nt < 4; ++nt)
#pragma unroll
            for (int q = 0; q < 4; ++q) facc[mt][nt][q] = 0.f;

    for (int h = 0; h < 8; ++h) {
        const int hc = h * 128;
        __syncthreads();
        issue_tile(aB0, g_Kh, krow0, hc);
        CP_COMMIT();
#pragma unroll
        for (int it = 0; it < 4; ++it) {
            int i2 = it * 256 + tid;
            int r = i2 >> 4, u = i2 & 15;
            size_t gs = (size_t)(qrow0 + r) * 1024 + hc + u * 8;
            uint32_t so = r * 256 + (swu(u, r) << 4);
            *(uint4*)(sAh + so) = *(const uint4*)(g_Qh + gs);
            *(uint4*)(sAl + so) = *(const uint4*)(g_Ql + gs);
        }
        if (tid < 128)
            zs[tid] = g_Z[((size_t)(b * 8 + h) * 16 + seg) * 128 + tid];

        for (int kc = 0; kc < 4; ++kc) {
            CP_WAIT0();
            __syncthreads();
            if (kc < 3) { issue_tile((kc & 1) ? aB0 : aB1, g_Kh, krow0 + (kc + 1) * 128, hc); CP_COMMIT(); }
            else {
#pragma unroll
                for (int it = 0; it < 8; ++it) {
                    int i2 = it * 256 + tid;
                    int r = i2 >> 4, u = i2 & 15;
                    size_t ms = ((size_t)(b * 8 + h) * 16 + seg) * 16384 + r * 128 + u * 8;
                    cpa16(aB0 + r * 256 + (swu(u, r) << 4), g_Memh + ms);
                }
                CP_COMMIT();
            }
            const uint32_t Bb = (kc & 1) ? aB1 : aB0;
            float acc[2][4][4];
#pragma unroll
            for (int mt = 0; mt < 2; ++mt)
#pragma unroll
                for (int nt = 0; nt < 4; ++nt)
#pragma unroll
                    for (int q = 0; q < 4; ++q) acc[mt][nt][q] = 0.f;
            for (int pass = 0; pass < 2; ++pass) {
                const uint32_t Ab = pass ? aAl : aAh;
#pragma unroll
                for (int ks = 0; ks < 8; ++ks) {
                    uint32_t af[2][4], bfr[4][2];
#pragma unroll
                    for (int mt = 0; mt < 2; ++mt)
                        ldsm_x4(af[mt][0], af[mt][1], af[mt][2], af[mt][3],
                                Ab + (rowA0 + mt * 16) * 256 + (swu(ks * 2 + unA, rowA0) << 4));
#pragma unroll
                    for (int nt = 0; nt < 4; ++nt)
                        ldsm_x2(bfr[nt][0], bfr[nt][1],
                                Bb + (rowBn + nt * 8) * 256 + (swu(ks * 2 + unB, rowBn) << 4));
#pragma unroll
                    for (int nt = 0; nt < 4; ++nt)
#pragma unroll
                        for (int mt = 0; mt < 2; ++mt)
                            mma16816h(acc[mt][nt][0], acc[mt][nt][1], acc[mt][nt][2], acc[mt][nt][3],
                                      af[mt][0], af[mt][1], af[mt][2], af[mt][3],
                                      bfr[nt][0], bfr[nt][1]);
                }
            }
#pragma unroll
            for (int mt = 0; mt < 2; ++mt) {
                int r0 = wm2 + mt * 16 + (lane >> 2);
#pragma unroll
                for (int nt = 0; nt < 4; ++nt) {
                    int cc = kc * 128 + wn2 + nt * 8 + ((lane & 3) << 1);
                    *(float2*)&Sc[r0 * 516 + cc]       = make_float2(acc[mt][nt][0] * scale, acc[mt][nt][1] * scale);
                    *(float2*)&Sc[(r0 + 8) * 516 + cc] = make_float2(acc[mt][nt][2] * scale, acc[mt][nt][3] * scale);
                }
            }
        }
        __syncthreads();
        issue_tile(aB1, g_Vh, krow0, hc);
        CP_COMMIT();
        {
            float* rowp = &Sc[srow * 516 + spart * 128];
            const int rot = spart * 8;
            float m = -1e30f;
#pragma unroll 8
            for (int j = 0; j < 128; ++j) m = fmaxf(m, rowp[(j + rot) & 127]);
            m = fmaxf(m, __shfl_xor_sync(0xffffffffu, m, 1));
            m = fmaxf(m, __shfl_xor_sync(0xffffffffu, m, 2));
            float s = 0.f;
#pragma unroll 8
            for (int j = 0; j < 128; ++j) {
                int jj = (j + rot) & 127;
                float e = __expf(rowp[jj] - m); rowp[jj] = e; s += e;
            }
            s += __shfl_xor_sync(0xffffffffu, s, 1);
            s += __shfl_xor_sync(0xffffffffu, s, 2);
            if (spart == 0) rs[srow] = s;
        }
        {
            float da = 0.f;
#pragma unroll 4
            for (int j = 0; j < 32; ++j) {
                int c = spart * 32 + j;
                uint32_t bo = srow * 256 + (swu(c >> 3, srow) << 4) + ((c & 7) << 1);
                float qh = __half2float(*(__half*)(sAh + bo));
                float ql = __half2float(*(__half*)(sAl + bo));
                float sq = elup1(qh + ql);
                da += sq * zs[c];
                __half hh = __float2half_rn(sq);
                __half ll = __float2half_rn(sq - __half2float(hh));
                *(__half*)(sAh + bo) = hh;
                *(__half*)(sAl + bo) = ll;
            }
            da += __shfl_xor_sync(0xffffffffu, da, 1);
            da += __shfl_xor_sync(0xffffffffu, da, 2);
            if (spart == 0) den[srow] = da;
        }
        CP_WAIT1();
        __syncthreads();
        {
            float acc[2][4][4];
#pragma unroll
            for (int mt = 0; mt < 2; ++mt)
#pragma unroll
                for (int nt = 0; nt < 4; ++nt)
#pragma unroll
                    for (int q = 0; q < 4; ++q) acc[mt][nt][q] = 0.f;
            for (int pass = 0; pass < 2; ++pass) {
                const uint32_t Ab = pass ? aAl : aAh;
#pragma unroll
                for (int ks = 0; ks < 8; ++ks) {
                    uint32_t af[2][4], bfr[4][2];
#pragma unroll
                    for (int mt = 0; mt < 2; ++mt)
                        ldsm_x4(af[mt][0], af[mt][1], af[mt][2], af[mt][3],
                                Ab + (rowA0 + mt * 16) * 256 + (swu(ks * 2 + unA, rowA0) << 4));
                    int rK = ks * 16 + rowKt;
#pragma unroll
                    for (int nt = 0; nt < 4; ++nt)
                        ldsm_x2t(bfr[nt][0], bfr[nt][1],
                                 aB0 + rK * 256 + (swu((wn2 >> 3) + nt, rK) << 4));
#pragma unroll
                    for (int nt = 0; nt < 4; ++nt)
#pragma unroll
                        for (int mt = 0; mt < 2; ++mt)
                            mma16816h(acc[mt][nt][0], acc[mt][nt][1], acc[mt][nt][2], acc[mt][nt][3],
                                      af[mt][0], af[mt][1], af[mt][2], af[mt][3],
                                      bfr[nt][0], bfr[nt][1]);
                }
            }
#pragma unroll
            for (int mt = 0; mt < 2; ++mt) {
                int r0 = wm2 + mt * 16 + (lane >> 2);
                float m0 = bsig8 / (den[r0] + 1e-5f);
                float m1 = bsig8 / (den[r0 + 8] + 1e-5f);
#pragma unroll
                for (int nt = 0; nt < 4; ++nt) {
                    facc[mt][nt][0] += acc[mt][nt][0] * m0;
                    facc[mt][nt][1] += acc[mt][nt][1] * m0;
                    facc[mt][nt][2] += acc[mt][nt][2] * m1;
                    facc[mt][nt][3] += acc[mt][nt][3] * m1;
                }
            }
        }
        float dacc[2][4][4];
#pragma unroll
        for (int mt = 0; mt < 2; ++mt)
#pragma unroll
            for (int nt = 0; nt < 4; ++nt)
#pragma unroll
                for (int q = 0; q < 4; ++q) dacc[mt][nt][q] = 0.f;
        for (int kc = 0; kc < 4; ++kc) {
            __syncthreads();
#pragma unroll
            for (int it = 0; it < 4; ++it) {
                int i2 = it * 256 + tid;
                int r = i2 >> 4, u = i2 & 15;
                const float* sp = &Sc[r * 516 + kc * 128 + u * 8];
                float4 p0 = *(const float4*)sp, p1 = *(const float4*)(sp + 4);
                uint4 hi;
                hi.x = packhf(p0.x, p0.y); hi.y = packhf(p0.z, p0.w);
                hi.z = packhf(p1.x, p1.y); hi.w = packhf(p1.z, p1.w);
                uint32_t so = r * 256 + (swu(u, r) << 4);
                *(uint4*)(sAh + so) = hi;
            }
            if (kc < 3) {
                issue_tile((kc & 1) ? aB1 : aB0, g_Vh, krow0 + (kc + 1) * 128, hc);
                CP_COMMIT();
                CP_WAIT1();
            } else {
                CP_WAIT0();
            }
            __syncthreads();
            const uint32_t vB = (kc & 1) ? aB0 : aB1;
#pragma unroll
            for (int ks = 0; ks < 8; ++ks) {
                uint32_t af[2][4], bfr[4][2];
#pragma unroll
                for (int mt = 0; mt < 2; ++mt)
                    ldsm_x4(af[mt][0], af[mt][1], af[mt][2], af[mt][3],
                            aAh + (rowA0 + mt * 16) * 256 + (swu(ks * 2 + unA, rowA0) << 4));
                int rK = ks * 16 + rowKt;
#pragma unroll
                for (int nt = 0; nt < 4; ++nt)
                    ldsm_x2t(bfr[nt][0], bfr[nt][1],
                             vB + rK * 256 + (swu((wn2 >> 3) + nt, rK) << 4));
#pragma unroll
                for (int nt = 0; nt < 4; ++nt)
#pragma unroll
                    for (int mt = 0; mt < 2; ++mt)
                        mma16816h(dacc[mt][nt][0], dacc[mt][nt][1], dacc[mt][nt][2], dacc[mt][nt][3],
                                  af[mt][0], af[mt][1], af[mt][2], af[mt][3],
                                  bfr[nt][0], bfr[nt][1]);
            }
        }
#pragma unroll
        for (int mt = 0; mt < 2; ++mt) {
            int r0 = wm2 + mt * 16 + (lane >> 2);
            float d0 = obsig8 / rs[r0];
            float d1 = obsig8 / rs[r0 + 8];
#pragma unroll
            for (int nt = 0; nt < 4; ++nt) {
                facc[mt][nt][0] += dacc[mt][nt][0] * d0;
                facc[mt][nt][1] += dacc[mt][nt][1] * d0;
                facc[mt][nt][2] += dacc[mt][nt][2] * d1;
                facc[mt][nt][3] += dacc[mt][nt][3] * d1;
            }
        }
    }

#pragma unroll
    for (int mt = 0; mt < 2; ++mt) {
        int r0 = wm2 + mt * 16 + (lane >> 2);
#pragma unroll
        for (int nt = 0; nt < 4; ++nt) {
            int col = wn2 + nt * 8 + ((lane & 3) << 1);
            *(float2*)&out[(size_t)(qrow0 + r0) * 128 + col]     = make_float2(facc[mt][nt][0], facc[mt][nt][1]);
            *(float2*)&out[(size_t)(qrow0 + r0 + 8) * 128 + col] = make_float2(facc[mt][nt][2], facc[mt][nt][3]);
        }
    }
}

// =====================================================================
extern "C" void kernel_launch(void* const* d_in, const int* in_sizes, int n_in,
                              void* d_out, int out_size)
{
    const float* x    = (const float*)d_in[0];
    const float* wq   = (const float*)d_in[1];
    const float* bq   = (const float*)d_in[2];
    const float* wk   = (const float*)d_in[3];
    const float* bk   = (const float*)d_in[4];
    const float* wv   = (const float*)d_in[5];
    const float* bv   = (const float*)d_in[6];
    const float* beta = (const float*)d_in[7];
    float* out = (float*)d_out;

    static int attr_set = 0;
    if (!attr_set) {
        cudaFuncSetAttribute(k_attn_mma, cudaFuncAttributeMaxDynamicSharedMemorySize, 231424);
        cudaFuncSetAttribute(k_proj_mma, cudaFuncAttributeMaxDynamicSharedMemorySize, 98304);
        cudaFuncSetAttribute(k_kvouter_mma, cudaFuncAttributeMaxDynamicSharedMemorySize, 106496);
        attr_set = 1;
    }

    k_splitX<<<32768, 256>>>(x);
    k_trW<<<dim3(32, 32), 256>>>(wq, 0);
    k_trW<<<dim3(32, 32), 256>>>(wk, 1);
    k_trW<<<dim3(32, 32), 256>>>(wv, 2);
    k_proj_mma<<<dim3(8, 256, 3), 512, 98304>>>(bq, bk, bv);
    k_kvouter_mma<<<512, 256, 106496>>>();
    k_prefix<<<32, 256>>>();
    k_attn_mma<<<512, 256, 231424>>>(beta, out);
}

// round 14
// speedup vs baseline: 1.9675x; 1.1288x over previous
#include <cuda_runtime.h>
#include <cuda_fp16.h>
#include <cstdint>

// ---------- helpers ----------
__device__ __forceinline__ float elup1(float x){ return x > 0.f ? x + 1.f : __expf(x); }
__device__ __forceinline__ uint32_t smem_u32(const void* p){
    uint32_t a;
    asm("{ .reg .u64 t; cvta.to.shared.u64 t, %1; cvt.u32.u64 %0, t; }" : "=r"(a) : "l"(p));
    return a;
}
__device__ __forceinline__ void cpa16(uint32_t smaddr, const void* g){
    asm volatile("cp.async.cg.shared.global [%0], [%1], 16;" :: "r"(smaddr), "l"(g));
}
#define CP_COMMIT() asm volatile("cp.async.commit_group;" ::: "memory")
#define CP_WAIT0()  asm volatile("cp.async.wait_group 0;" ::: "memory")
#define CP_WAIT1()  asm volatile("cp.async.wait_group 1;" ::: "memory")
__device__ __forceinline__ void ldsm_x4(uint32_t &r0, uint32_t &r1, uint32_t &r2, uint32_t &r3, uint32_t addr){
    asm volatile("ldmatrix.sync.aligned.m8n8.x4.shared.b16 {%0,%1,%2,%3}, [%4];"
        : "=r"(r0), "=r"(r1), "=r"(r2), "=r"(r3) : "r"(addr));
}
__device__ __forceinline__ void ldsm_x4t(uint32_t &r0, uint32_t &r1, uint32_t &r2, uint32_t &r3, uint32_t addr){
    asm volatile("ldmatrix.sync.aligned.m8n8.x4.trans.shared.b16 {%0,%1,%2,%3}, [%4];"
        : "=r"(r0), "=r"(r1), "=r"(r2), "=r"(r3) : "r"(addr));
}
__device__ __forceinline__ void ldsm_x2(uint32_t &r0, uint32_t &r1, uint32_t addr){
    asm volatile("ldmatrix.sync.aligned.m8n8.x2.shared.b16 {%0,%1}, [%2];"
        : "=r"(r0), "=r"(r1) : "r"(addr));
}
__device__ __forceinline__ void ldsm_x2t(uint32_t &r0, uint32_t &r1, uint32_t addr){
    asm volatile("ldmatrix.sync.aligned.m8n8.x2.trans.shared.b16 {%0,%1}, [%2];"
        : "=r"(r0), "=r"(r1) : "r"(addr));
}
__device__ __forceinline__ void mma16816h(float &c0, float &c1, float &c2, float &c3,
                                          uint32_t a0, uint32_t a1, uint32_t a2, uint32_t a3,
                                          uint32_t b0, uint32_t b1){
    asm volatile("mma.sync.aligned.m16n8k16.row.col.f32.f16.f16.f32 "
        "{%0,%1,%2,%3}, {%4,%5,%6,%7}, {%8,%9}, {%0,%1,%2,%3};"
        : "+f"(c0), "+f"(c1), "+f"(c2), "+f"(c3)
        : "r"(a0), "r"(a1), "r"(a2), "r"(a3), "r"(b0), "r"(b1));
}
__device__ __forceinline__ uint32_t swu(int u, int r){ return (uint32_t)((u & 8) | ((u & 7) ^ (r & 7))); }
__device__ __forceinline__ uint32_t packhf(float a, float b){
    __half2 t = __halves2half2(__float2half_rn(a), __float2half_rn(b));
    return *(uint32_t*)&t;
}

// ---------- dims: B=4, S=8192, D=1024, H=8, dk=dv=128, SEG=512, nseg=16 ----------

// ---------- device scratch ----------
__device__ float g_P[8388608];
__device__ float g_Zseg[65536];
__device__ float g_Z[65536];
__device__ __half g_Xh[33554432];
__device__ __half g_Wh[3145728];
__device__ __half g_Qh[33554432];
__device__ __half g_Kh[33554432];
__device__ __half g_Vh[33554432];
__device__ __half g_Memh[8388608];

// =====================================================================
// S1: X -> fp16
// =====================================================================
__global__ __launch_bounds__(256) void k_splitX(const float* __restrict__ x)
{
    size_t i = ((size_t)blockIdx.x * 256 + threadIdx.x) * 4;
    float4 v = *(const float4*)(x + i);
    *(__half2*)(g_Xh + i)     = __halves2half2(__float2half_rn(v.x), __float2half_rn(v.y));
    *(__half2*)(g_Xh + i + 2) = __halves2half2(__float2half_rn(v.z), __float2half_rn(v.w));
}

// =====================================================================
// S2: transpose W[k][n] -> Wt[n][k], fp16
// =====================================================================
__global__ __launch_bounds__(256) void k_trW(const float* __restrict__ w, int which)
{
    __shared__ float t[32][33];
    const int bx = blockIdx.x << 5, by = blockIdx.y << 5;
    const int tx = threadIdx.x & 31, ty = threadIdx.x >> 5;
#pragma unroll
    for (int r = 0; r < 4; ++r)
        t[ty * 4 + r][tx] = w[(size_t)(by + ty * 4 + r) * 1024 + bx + tx];
    __syncthreads();
    __half* Wt = g_Wh + (size_t)which * 1048576;
#pragma unroll
    for (int r = 0; r < 4; ++r) {
        int n = bx + ty * 4 + r, k = by + tx;
        Wt[(size_t)n * 1024 + k] = __float2half_rn(t[tx][ty * 4 + r]);
    }
}

// =====================================================================
// K1: fused projection GEMM, fp16 single-pass; fp16 output only.
// =====================================================================
__global__ __launch_bounds__(512, 1) void k_proj_mma(const float* __restrict__ bq,
                                                     const float* __restrict__ bk,
                                                     const float* __restrict__ bv)
{
    extern __shared__ __align__(128) char sm_raw[];
    const uint32_t smbase = smem_u32(sm_raw);

    const int which = blockIdx.z;
    const float* bias = (which == 0) ? bq : ((which == 1) ? bk : bv);
    __half* Hd = (which == 0) ? g_Qh : ((which == 1) ? g_Kh : g_Vh);
    const __half* Wt = g_Wh + (size_t)which * 1048576;

    const int tid = threadIdx.x, lane = tid & 31, wid = tid >> 5;
    const int wm = (wid >> 2) * 32, wn = (wid & 3) * 32;
    const int row0 = blockIdx.y << 7, col0 = blockIdx.x << 7;

    const int rowA = wm + (lane & 15);
    const int rA7 = rowA & 7;
    const int unA = lane >> 4;
    const int rowB = wn + (lane & 7);
    const int rB7 = lane & 7;
    const int unB = (lane >> 3) & 1;
    const int lr = tid >> 3, lu = tid & 7;

    float cf[2][4][4];
#pragma unroll
    for (int mt = 0; mt < 2; ++mt)
#pragma unroll
        for (int nt = 0; nt < 4; ++nt)
#pragma unroll
            for (int q = 0; q < 4; ++q) cf[mt][nt][q] = 0.f;

    auto load_chunk = [&](int c, int stage) {
        const int k0 = c << 6;
        const uint32_t st = smbase + stage * 32768;
#pragma unroll
        for (int it = 0; it < 2; ++it) {
            int r = lr + it * 64;
            size_t ga = (size_t)(row0 + r) * 1024 + k0 + lu * 8;
            size_t gb = (size_t)(col0 + r) * 1024 + k0 + lu * 8;
            uint32_t so = r * 128 + ((lu ^ (r & 7)) << 4);
            cpa16(st + so,         g_Xh + ga);
            cpa16(st + 16384 + so, Wt + gb);
        }
    };

    load_chunk(0, 0); CP_COMMIT();
    load_chunk(1, 1); CP_COMMIT();

    for (int c = 0; c < 16; ++c) {
        CP_WAIT1();
        __syncthreads();
        if (c + 2 < 16) load_chunk(c + 2, (c + 2) % 3);
        CP_COMMIT();
        const uint32_t st = smbase + (c % 3) * 32768;
#pragma unroll
        for (int ks = 0; ks < 4; ++ks) {
            uint32_t ah[2][4], bh[4][2];
#pragma unroll
            for (int mt = 0; mt < 2; ++mt) {
                uint32_t off = (rowA + mt * 16) * 128 + ((((ks << 1) + unA) ^ rA7) << 4);
                ldsm_x4(ah[mt][0], ah[mt][1], ah[mt][2], ah[mt][3], st + off);
            }
#pragma unroll
            for (int nt = 0; nt < 4; ++nt) {
                uint32_t off = (rowB + nt * 8) * 128 + ((((ks << 1) + unB) ^ rB7) << 4);
                ldsm_x2(bh[nt][0], bh[nt][1], st + 16384 + off);
            }
#pragma unroll
            for (int nt = 0; nt < 4; ++nt)
#pragma unroll
                for (int mt = 0; mt < 2; ++mt)
                    mma16816h(cf[mt][nt][0], cf[mt][nt][1], cf[mt][nt][2], cf[mt][nt][3],
                              ah[mt][0], ah[mt][1], ah[mt][2], ah[mt][3], bh[nt][0], bh[nt][1]);
        }
    }

#pragma unroll
    for (int mt = 0; mt < 2; ++mt) {
        const int r0 = row0 + wm + mt * 16 + (lane >> 2);
#pragma unroll
        for (int nt = 0; nt < 4; ++nt) {
            const int ccol = col0 + wn + nt * 8 + ((lane & 3) << 1);
            const float2 bvv = *(const float2*)&bias[ccol];
            size_t o0 = (size_t)r0 * 1024 + ccol;
            *(uint32_t*)(Hd + o0)            = packhf(cf[mt][nt][0] + bvv.x, cf[mt][nt][1] + bvv.y);
            *(uint32_t*)(Hd + o0 + 8 * 1024) = packhf(cf[mt][nt][2] + bvv.x, cf[mt][nt][3] + bvv.y);
        }
    }
}

// =====================================================================
// K2: kvouter fp16 mma, single pass. sk = elup1(Kh); Z exact fp32.
// smem: skh 32K | sv 32K | zsm 8K = 73728
// =====================================================================
__global__ __launch_bounds__(256, 1) void k_kvouter_mma()
{
    extern __shared__ __align__(16) char km[];
    char* skh = km;
    char* sv  = km + 32768;
    float* zsm = (float*)(km + 65536);
    const uint32_t aH = smem_u32(skh), aV = smem_u32(sv);

    const int idx = blockIdx.x;                  // b*128 + h*16 + seg
    const int b = idx >> 7, h = (idx >> 4) & 7, seg = idx & 15;
    const int tid = threadIdx.x, lane = tid & 31, wid = tid >> 5;
    const int wm = (wid & 3) * 32, wn = (wid >> 2) * 64;
    const int krow = b * 8192 + seg * 512;
    const int hc = h * 128;

    const int rLa = (lane & 7) + ((lane >> 4) & 1) * 8;
    const int uAd = (lane >> 3) & 1;
    const int rKt = (lane & 7) + ((lane >> 3) & 1) * 8;
    const int tr = tid >> 4, tu = tid & 15;

    float acc[2][8][4];
#pragma unroll
    for (int mt = 0; mt < 2; ++mt)
#pragma unroll
        for (int nt = 0; nt < 8; ++nt)
#pragma unroll
            for (int q = 0; q < 4; ++q) acc[mt][nt][q] = 0.f;
    float zacc[8] = {0.f,0.f,0.f,0.f,0.f,0.f,0.f,0.f};

    for (int ch = 0; ch < 4; ++ch) {
        __syncthreads();
#pragma unroll
        for (int it = 0; it < 8; ++it) {
            int i2 = it * 256 + tid;
            int r = i2 >> 4, u = i2 & 15;
            cpa16(aV + r * 256 + (swu(u, r) << 4),
                  g_Vh + (size_t)(krow + ch * 128 + r) * 1024 + hc + u * 8);
        }
        CP_COMMIT();
        {
            uint4 kh[8];
#pragma unroll
            for (int it = 0; it < 8; ++it) {
                int r = tr + it * 16;
                kh[it] = *(const uint4*)(g_Kh + (size_t)(krow + ch * 128 + r) * 1024 + hc + tu * 8);
            }
#pragma unroll
            for (int it = 0; it < 8; ++it) {
                int r = tr + it * 16;
                uint4 oh;
                uint32_t* ph = (uint32_t*)&kh[it];
                uint32_t* qh = (uint32_t*)&oh;
#pragma unroll
                for (int w2 = 0; w2 < 4; ++w2) {
                    float2 fh = __half22float2(*(__half2*)&ph[w2]);
                    float s0 = elup1(fh.x);
                    float s1 = elup1(fh.y);
                    zacc[w2 * 2]     += s0;
                    zacc[w2 * 2 + 1] += s1;
                    qh[w2] = packhf(s0, s1);
                }
                *(uint4*)(skh + r * 256 + (swu(tu, r) << 4)) = oh;
            }
        }
        CP_WAIT0();
        __syncthreads();
#pragma unroll
        for (int ks = 0; ks < 8; ++ks) {
            uint32_t af[2][4], bf[8][2];
#pragma unroll
            for (int mt = 0; mt < 2; ++mt) {
                int rr = ks * 16 + rLa;
                int uu = ((wm + mt * 16) >> 3) + uAd;
                ldsm_x4t(af[mt][0], af[mt][1], af[mt][2], af[mt][3],
                         aH + rr * 256 + (swu(uu, rr) << 4));
            }
            int rB = ks * 16 + rKt;
#pragma unroll
            for (int nt = 0; nt < 8; ++nt)
                ldsm_x2t(bf[nt][0], bf[nt][1],
                         aV + rB * 256 + (swu((wn >> 3) + nt, rB) << 4));
#pragma unroll
            for (int nt = 0; nt < 8; ++nt)
#pragma unroll
                for (int mt = 0; mt < 2; ++mt)
                    mma16816h(acc[mt][nt][0], acc[mt][nt][1], acc[mt][nt][2], acc[mt][nt][3],
                              af[mt][0], af[mt][1], af[mt][2], af[mt][3],
                              bf[nt][0], bf[nt][1]);
        }
    }

    const size_t pbase = (size_t)idx * 16384;
#pragma unroll
    for (int mt = 0; mt < 2; ++mt) {
        int r0 = wm + mt * 16 + (lane >> 2);
#pragma unroll
        for (int nt = 0; nt < 8; ++nt) {
            int col = wn + nt * 8 + ((lane & 3) << 1);
            *(float2*)&g_P[pbase + (size_t)r0 * 128 + col]       = make_float2(acc[mt][nt][0], acc[mt][nt][1]);
            *(float2*)&g_P[pbase + (size_t)(r0 + 8) * 128 + col] = make_float2(acc[mt][nt][2], acc[mt][nt][3]);
        }
    }
#pragma unroll
    for (int j = 0; j < 8; ++j) zsm[tr * 128 + tu * 8 + j] = zacc[j];
    __syncthreads();
    if (tid < 128) {
        float s = 0.f;
#pragma unroll
        for (int g = 0; g < 16; ++g) s += zsm[g * 128 + tid];
        g_Zseg[idx * 128 + tid] = 512.f * s;
    }
}

// =====================================================================
// K3: inclusive prefix over seg; writes fp16 Memh + Z
// =====================================================================
__global__ __launch_bounds__(256) void k_prefix()
{
    const int bh = blockIdx.x;
    const int tid = threadIdx.x;
    float acc[64];
#pragma unroll
    for (int u = 0; u < 64; ++u) acc[u] = 0.f;
    float zacc = 0.f;
    for (int seg = 0; seg < 16; ++seg) {
        const size_t base = ((size_t)bh * 16 + seg) * 16384;
#pragma unroll
        for (int u = 0; u < 64; ++u) {
            acc[u] += g_P[base + u * 256 + tid];
            g_Memh[base + u * 256 + tid] = __float2half_rn(acc[u]);
        }
        if (tid < 128) {
            zacc += g_Zseg[(bh * 16 + seg) * 128 + tid];
            g_Z[(bh * 16 + seg) * 128 + tid] = zacc;
        }
    }
}

// =====================================================================
// K4: fp16 mma attention, single-pass everywhere, double-buffered tiles.
// smem: Sc 132096 | sAh 16384 | sB0 32768 | sB1 32768 | ctl -> 215040
// =====================================================================
__global__ __launch_bounds__(256, 1) void k_attn_mma(const float* __restrict__ beta,
                                                     float* __restrict__ out)
{
    extern __shared__ __align__(16) char smraw[];
    float* Sc = (float*)smraw;                       // 132096
    char* sAh = smraw + 132096;
    char* sB0 = sAh + 16384;
    char* sB1 = sB0 + 32768;
    float* zs  = (float*)(sB1 + 32768);              // 128
    float* rs  = zs + 128;                           // 64
    float* den = rs + 64;                            // 64
    const uint32_t aAh = smem_u32(sAh);
    const uint32_t aB0 = smem_u32(sB0), aB1 = smem_u32(sB1);

    const int idx = blockIdx.x;                      // b*128 + seg*8 + qt
    const int b = idx >> 7, seg = (idx >> 3) & 15, qt = idx & 7;
    const int tid = threadIdx.x, lane = tid & 31, wid = tid >> 5;
    const int wm2 = (wid >> 2) * 32, wn2 = (wid & 3) * 32;
    const int qrow0 = b * 8192 + seg * 512 + qt * 64;
    const int krow0 = b * 8192 + seg * 512;
    const float bsig = 1.f / (1.f + __expf(-beta[0]));
    const float bsig8 = bsig * 0.125f, obsig8 = (1.f - bsig) * 0.125f;
    const float scale = 0.088388347648318447f;

    const int rowA0 = wm2 + (lane & 15);
    const int unA = lane >> 4;
    const int rowBn = wn2 + (lane & 7);
    const int unB = (lane >> 3) & 1;
    const int rowKt = (lane & 7) + ((lane >> 3) & 1) * 8;
    const int srow = tid >> 2, spart = tid & 3;

    auto issue_tile = [&](uint32_t dst, const __half* src, int rowbase, int hcc) {
#pragma unroll
        for (int it = 0; it < 8; ++it) {
            int i2 = it * 256 + tid;
            int r = i2 >> 4, u = i2 & 15;
            cpa16(dst + r * 256 + (swu(u, r) << 4),
                  src + (size_t)(rowbase + r) * 1024 + hcc + u * 8);
        }
    };

    float facc[2][4][4];
#pragma unroll
    for (int mt = 0; mt < 2; ++mt)
#pragma unroll
        for (int nt = 0; nt < 4; ++nt)
#pragma unroll
            for (int q = 0; q < 4; ++q) facc[mt][nt][q] = 0.f;

    for (int h = 0; h < 8; ++h) {
        const int hc = h * 128;
        __syncthreads();
        issue_tile(aB0, g_Kh, krow0, hc);
        CP_COMMIT();
        // Q load into sAh
#pragma unroll
        for (int it = 0; it < 4; ++it) {
            int i2 = it * 256 + tid;
            int r = i2 >> 4, u = i2 & 15;
            size_t gs = (size_t)(qrow0 + r) * 1024 + hc + u * 8;
            *(uint4*)(sAh + r * 256 + (swu(u, r) << 4)) = *(const uint4*)(g_Qh + gs);
        }
        if (tid < 128)
            zs[tid] = g_Z[((size_t)(b * 8 + h) * 16 + seg) * 128 + tid];

        // ---- scores: 4 chunks, double-buffered K; chunk3 prefetches Mem ----
        for (int kc = 0; kc < 4; ++kc) {
            CP_WAIT0();
            __syncthreads();
            if (kc < 3) { issue_tile((kc & 1) ? aB0 : aB1, g_Kh, krow0 + (kc + 1) * 128, hc); CP_COMMIT(); }
            else {
#pragma unroll
                for (int it = 0; it < 8; ++it) {
                    int i2 = it * 256 + tid;
                    int r = i2 >> 4, u = i2 & 15;
                    size_t ms = ((size_t)(b * 8 + h) * 16 + seg) * 16384 + r * 128 + u * 8;
                    cpa16(aB0 + r * 256 + (swu(u, r) << 4), g_Memh + ms);
                }
                CP_COMMIT();
            }
            const uint32_t Bb = (kc & 1) ? aB1 : aB0;
            float acc[2][4][4];
#pragma unroll
            for (int mt = 0; mt < 2; ++mt)
#pragma unroll
                for (int nt = 0; nt < 4; ++nt)
#pragma unroll
                    for (int q = 0; q < 4; ++q) acc[mt][nt][q] = 0.f;
#pragma unroll
            for (int ks = 0; ks < 8; ++ks) {
                uint32_t af[2][4], bfr[4][2];
#pragma unroll
                for (int mt = 0; mt < 2; ++mt)
                    ldsm_x4(af[mt][0], af[mt][1], af[mt][2], af[mt][3],
                            aAh + (rowA0 + mt * 16) * 256 + (swu(ks * 2 + unA, rowA0) << 4));
#pragma unroll
                for (int nt = 0; nt < 4; ++nt)
                    ldsm_x2(bfr[nt][0], bfr[nt][1],
                            Bb + (rowBn + nt * 8) * 256 + (swu(ks * 2 + unB, rowBn) << 4));
#pragma unroll
                for (int nt = 0; nt < 4; ++nt)
#pragma unroll
                    for (int mt = 0; mt < 2; ++mt)
                        mma16816h(acc[mt][nt][0], acc[mt][nt][1], acc[mt][nt][2], acc[mt][nt][3],
                                  af[mt][0], af[mt][1], af[mt][2], af[mt][3],
                                  bfr[nt][0], bfr[nt][1]);
            }
#pragma unroll
            for (int mt = 0; mt < 2; ++mt) {
                int r0 = wm2 + mt * 16 + (lane >> 2);
#pragma unroll
                for (int nt = 0; nt < 4; ++nt) {
                    int cc = kc * 128 + wn2 + nt * 8 + ((lane & 3) << 1);
                    *(float2*)&Sc[r0 * 516 + cc]       = make_float2(acc[mt][nt][0] * scale, acc[mt][nt][1] * scale);
                    *(float2*)&Sc[(r0 + 8) * 516 + cc] = make_float2(acc[mt][nt][2] * scale, acc[mt][nt][3] * scale);
                }
            }
        }
        __syncthreads();
        issue_tile(aB1, g_Vh, krow0, hc);
        CP_COMMIT();
        // ---- softmax (bank-rotated scan) ----
        {
            float* rowp = &Sc[srow * 516 + spart * 128];
            const int rot = spart * 8;
            float m = -1e30f;
#pragma unroll 8
            for (int j = 0; j < 128; ++j) m = fmaxf(m, rowp[(j + rot) & 127]);
            m = fmaxf(m, __shfl_xor_sync(0xffffffffu, m, 1));
            m = fmaxf(m, __shfl_xor_sync(0xffffffffu, m, 2));
            float s = 0.f;
#pragma unroll 8
            for (int j = 0; j < 128; ++j) {
                int jj = (j + rot) & 127;
                float e = __expf(rowp[jj] - m); rowp[jj] = e; s += e;
            }
            s += __shfl_xor_sync(0xffffffffu, s, 1);
            s += __shfl_xor_sync(0xffffffffu, s, 2);
            if (spart == 0) rs[srow] = s;
        }
        // ---- sq = elup1(qh) (single fp16) + exact den ----
        {
            float da = 0.f;
#pragma unroll 4
            for (int j = 0; j < 32; ++j) {
                int c = spart * 32 + j;
                uint32_t bo = srow * 256 + (swu(c >> 3, srow) << 4) + ((c & 7) << 1);
                float qh = __half2float(*(__half*)(sAh + bo));
                float sq = elup1(qh);
                da += sq * zs[c];
                *(__half*)(sAh + bo) = __float2half_rn(sq);
            }
            da += __shfl_xor_sync(0xffffffffu, da, 1);
            da += __shfl_xor_sync(0xffffffffu, da, 2);
            if (spart == 0) den[srow] = da;
        }
        CP_WAIT1();        // Mem complete
        __syncthreads();
        // ---- retrieval: single-pass sq x Memh (buf0) ----
        {
            float acc[2][4][4];
#pragma unroll
            for (int mt = 0; mt < 2; ++mt)
#pragma unroll
                for (int nt = 0; nt < 4; ++nt)
#pragma unroll
                    for (int q = 0; q < 4; ++q) acc[mt][nt][q] = 0.f;
#pragma unroll
            for (int ks = 0; ks < 8; ++ks) {
                uint32_t af[2][4], bfr[4][2];
#pragma unroll
                for (int mt = 0; mt < 2; ++mt)
                    ldsm_x4(af[mt][0], af[mt][1], af[mt][2], af[mt][3],
                            aAh + (rowA0 + mt * 16) * 256 + (swu(ks * 2 + unA, rowA0) << 4));
                int rK = ks * 16 + rowKt;
#pragma unroll
                for (int nt = 0; nt < 4; ++nt)
                    ldsm_x2t(bfr[nt][0], bfr[nt][1],
                             aB0 + rK * 256 + (swu((wn2 >> 3) + nt, rK) << 4));
#pragma unroll
                for (int nt = 0; nt < 4; ++nt)
#pragma unroll
                    for (int mt = 0; mt < 2; ++mt)
                        mma16816h(acc[mt][nt][0], acc[mt][nt][1], acc[mt][nt][2], acc[mt][nt][3],
                                  af[mt][0], af[mt][1], af[mt][2], af[mt][3],
                                  bfr[nt][0], bfr[nt][1]);
            }
#pragma unroll
            for (int mt = 0; mt < 2; ++mt) {
                int r0 = wm2 + mt * 16 + (lane >> 2);
                float m0 = bsig8 / (den[r0] + 1e-5f);
                float m1 = bsig8 / (den[r0 + 8] + 1e-5f);
#pragma unroll
                for (int nt = 0; nt < 4; ++nt) {
                    facc[mt][nt][0] += acc[mt][nt][0] * m0;
                    facc[mt][nt][1] += acc[mt][nt][1] * m0;
                    facc[mt][nt][2] += acc[mt][nt][2] * m1;
                    facc[mt][nt][3] += acc[mt][nt][3] * m1;
                }
            }
        }
        // ---- PV: double-buffered V, single-pass P x Vh ----
        float dacc[2][4][4];
#pragma unroll
        for (int mt = 0; mt < 2; ++mt)
#pragma unroll
            for (int nt = 0; nt < 4; ++nt)
#pragma unroll
                for (int q = 0; q < 4; ++q) dacc[mt][nt][q] = 0.f;
        for (int kc = 0; kc < 4; ++kc) {
            __syncthreads();
#pragma unroll
            for (int it = 0; it < 4; ++it) {
                int i2 = it * 256 + tid;
                int r = i2 >> 4, u = i2 & 15;
                const float* sp = &Sc[r * 516 + kc * 128 + u * 8];
                float4 p0 = *(const float4*)sp, p1 = *(const float4*)(sp + 4);
                uint4 hi;
                hi.x = packhf(p0.x, p0.y); hi.y = packhf(p0.z, p0.w);
                hi.z = packhf(p1.x, p1.y); hi.w = packhf(p1.z, p1.w);
                *(uint4*)(sAh + r * 256 + (swu(u, r) << 4)) = hi;
            }
            if (kc < 3) {
                issue_tile((kc & 1) ? aB1 : aB0, g_Vh, krow0 + (kc + 1) * 128, hc);
                CP_COMMIT();
                CP_WAIT1();
            } else {
                CP_WAIT0();
            }
            __syncthreads();
            const uint32_t vB = (kc & 1) ? aB0 : aB1;
#pragma unroll
            for (int ks = 0; ks < 8; ++ks) {
                uint32_t af[2][4], bfr[4][2];
#pragma unroll
                for (int mt = 0; mt < 2; ++mt)
                    ldsm_x4(af[mt][0], af[mt][1], af[mt][2], af[mt][3],
                            aAh + (rowA0 + mt * 16) * 256 + (swu(ks * 2 + unA, rowA0) << 4));
                int rK = ks * 16 + rowKt;
#pragma unroll
                for (int nt = 0; nt < 4; ++nt)
                    ldsm_x2t(bfr[nt][0], bfr[nt][1],
                             vB + rK * 256 + (swu((wn2 >> 3) + nt, rK) << 4));
#pragma unroll
                for (int nt = 0; nt < 4; ++nt)
#pragma unroll
                    for (int mt = 0; mt < 2; ++mt)
                        mma16816h(dacc[mt][nt][0], dacc[mt][nt][1], dacc[mt][nt][2], dacc[mt][nt][3],
                                  af[mt][0], af[mt][1], af[mt][2], af[mt][3],
                                  bfr[nt][0], bfr[nt][1]);
            }
        }
#pragma unroll
        for (int mt = 0; mt < 2; ++mt) {
            int r0 = wm2 + mt * 16 + (lane >> 2);
            float d0 = obsig8 / rs[r0];
            float d1 = obsig8 / rs[r0 + 8];
#pragma unroll
            for (int nt = 0; nt < 4; ++nt) {
                facc[mt][nt][0] += dacc[mt][nt][0] * d0;
                facc[mt][nt][1] += dacc[mt][nt][1] * d0;
                facc[mt][nt][2] += dacc[mt][nt][2] * d1;
                facc[mt][nt][3] += dacc[mt][nt][3] * d1;
            }
        }
    }

#pragma unroll
    for (int mt = 0; mt < 2; ++mt) {
        int r0 = wm2 + mt * 16 + (lane >> 2);
#pragma unroll
        for (int nt = 0; nt < 4; ++nt) {
            int col = wn2 + nt * 8 + ((lane & 3) << 1);
            *(float2*)&out[(size_t)(qrow0 + r0) * 128 + col]     = make_float2(facc[mt][nt][0], facc[mt][nt][1]);
            *(float2*)&out[(size_t)(qrow0 + r0 + 8) * 128 + col] = make_float2(facc[mt][nt][2], facc[mt][nt][3]);
        }
    }
}

// =====================================================================
extern "C" void kernel_launch(void* const* d_in, const int* in_sizes, int n_in,
                              void* d_out, int out_size)
{
    const float* x    = (const float*)d_in[0];
    const float* wq   = (const float*)d_in[1];
    const float* bq   = (const float*)d_in[2];
    const float* wk   = (const float*)d_in[3];
    const float* bk   = (const float*)d_in[4];
    const float* wv   = (const float*)d_in[5];
    const float* bv   = (const float*)d_in[6];
    const float* beta = (const float*)d_in[7];
    float* out = (float*)d_out;

    static int attr_set = 0;
    if (!attr_set) {
        cudaFuncSetAttribute(k_attn_mma, cudaFuncAttributeMaxDynamicSharedMemorySize, 215040);
        cudaFuncSetAttribute(k_proj_mma, cudaFuncAttributeMaxDynamicSharedMemorySize, 98304);
        cudaFuncSetAttribute(k_kvouter_mma, cudaFuncAttributeMaxDynamicSharedMemorySize, 73728);
        attr_set = 1;
    }

    k_splitX<<<32768, 256>>>(x);
    k_trW<<<dim3(32, 32), 256>>>(wq, 0);
    k_trW<<<dim3(32, 32), 256>>>(wk, 1);
    k_trW<<<dim3(32, 32), 256>>>(wv, 2);
    k_proj_mma<<<dim3(8, 256, 3), 512, 98304>>>(bq, bk, bv);
    k_kvouter_mma<<<512, 256, 73728>>>();
    k_prefix<<<32, 256>>>();
    k_attn_mma<<<512, 256, 215040>>>(beta, out);
}

// round 15
// speedup vs baseline: 2.4558x; 1.2482x over previous
#include <cuda_runtime.h>
#include <cuda_fp16.h>
#include <cstdint>

// ---------- helpers ----------
__device__ __forceinline__ float elup1(float x){ return x > 0.f ? x + 1.f : __expf(x); }
__device__ __forceinline__ uint32_t smem_u32(const void* p){
    uint32_t a;
    asm("{ .reg .u64 t; cvta.to.shared.u64 t, %1; cvt.u32.u64 %0, t; }" : "=r"(a) : "l"(p));
    return a;
}
__device__ __forceinline__ void cpa16(uint32_t smaddr, const void* g){
    asm volatile("cp.async.cg.shared.global [%0], [%1], 16;" :: "r"(smaddr), "l"(g));
}
#define CP_COMMIT() asm volatile("cp.async.commit_group;" ::: "memory")
#define CP_WAIT0()  asm volatile("cp.async.wait_group 0;" ::: "memory")
#define CP_WAIT1()  asm volatile("cp.async.wait_group 1;" ::: "memory")
__device__ __forceinline__ void ldsm_x4(uint32_t &r0, uint32_t &r1, uint32_t &r2, uint32_t &r3, uint32_t addr){
    asm volatile("ldmatrix.sync.aligned.m8n8.x4.shared.b16 {%0,%1,%2,%3}, [%4];"
        : "=r"(r0), "=r"(r1), "=r"(r2), "=r"(r3) : "r"(addr));
}
__device__ __forceinline__ void ldsm_x4t(uint32_t &r0, uint32_t &r1, uint32_t &r2, uint32_t &r3, uint32_t addr){
    asm volatile("ldmatrix.sync.aligned.m8n8.x4.trans.shared.b16 {%0,%1,%2,%3}, [%4];"
        : "=r"(r0), "=r"(r1), "=r"(r2), "=r"(r3) : "r"(addr));
}
__device__ __forceinline__ void ldsm_x2(uint32_t &r0, uint32_t &r1, uint32_t addr){
    asm volatile("ldmatrix.sync.aligned.m8n8.x2.shared.b16 {%0,%1}, [%2];"
        : "=r"(r0), "=r"(r1) : "r"(addr));
}
__device__ __forceinline__ void ldsm_x2t(uint32_t &r0, uint32_t &r1, uint32_t addr){
    asm volatile("ldmatrix.sync.aligned.m8n8.x2.trans.shared.b16 {%0,%1}, [%2];"
        : "=r"(r0), "=r"(r1) : "r"(addr));
}
__device__ __forceinline__ void mma16816h(float &c0, float &c1, float &c2, float &c3,
                                          uint32_t a0, uint32_t a1, uint32_t a2, uint32_t a3,
                                          uint32_t b0, uint32_t b1){
    asm volatile("mma.sync.aligned.m16n8k16.row.col.f32.f16.f16.f32 "
        "{%0,%1,%2,%3}, {%4,%5,%6,%7}, {%8,%9}, {%0,%1,%2,%3};"
        : "+f"(c0), "+f"(c1), "+f"(c2), "+f"(c3)
        : "r"(a0), "r"(a1), "r"(a2), "r"(a3), "r"(b0), "r"(b1));
}
__device__ __forceinline__ uint32_t swu(int u, int r){ return (uint32_t)((u & 8) | ((u & 7) ^ (r & 7))); }
__device__ __forceinline__ uint32_t packhf(float a, float b){
    __half2 t = __halves2half2(__float2half_rn(a), __float2half_rn(b));
    return *(uint32_t*)&t;
}

// ---------- dims: B=4, S=8192, D=1024, H=8, dk=dv=128, SEG=512, nseg=16 ----------

// ---------- device scratch ----------
__device__ float g_P[8388608];
__device__ float g_Zseg[65536];
__device__ float g_Z[65536];
__device__ __half g_Xh[33554432];
__device__ __half g_Wh[3145728];
__device__ __half g_Qh[33554432];
__device__ __half g_Kh[33554432];
__device__ __half g_Vh[33554432];
__device__ __half g_Memh[8388608];

// =====================================================================
// S1: X -> fp16
// =====================================================================
__global__ __launch_bounds__(256) void k_splitX(const float* __restrict__ x)
{
    size_t i = ((size_t)blockIdx.x * 256 + threadIdx.x) * 4;
    float4 v = *(const float4*)(x + i);
    *(__half2*)(g_Xh + i)     = __halves2half2(__float2half_rn(v.x), __float2half_rn(v.y));
    *(__half2*)(g_Xh + i + 2) = __halves2half2(__float2half_rn(v.z), __float2half_rn(v.w));
}

// =====================================================================
// S2: transpose W[k][n] -> Wt[n][k], fp16
// =====================================================================
__global__ __launch_bounds__(256) void k_trW(const float* __restrict__ w, int which)
{
    __shared__ float t[32][33];
    const int bx = blockIdx.x << 5, by = blockIdx.y << 5;
    const int tx = threadIdx.x & 31, ty = threadIdx.x >> 5;
#pragma unroll
    for (int r = 0; r < 4; ++r)
        t[ty * 4 + r][tx] = w[(size_t)(by + ty * 4 + r) * 1024 + bx + tx];
    __syncthreads();
    __half* Wt = g_Wh + (size_t)which * 1048576;
#pragma unroll
    for (int r = 0; r < 4; ++r) {
        int n = bx + ty * 4 + r, k = by + tx;
        Wt[(size_t)n * 1024 + k] = __float2half_rn(t[tx][ty * 4 + r]);
    }
}

// =====================================================================
// K1: fused projection GEMM, fp16 single-pass; fp16 output only.
// =====================================================================
__global__ __launch_bounds__(512, 1) void k_proj_mma(const float* __restrict__ bq,
                                                     const float* __restrict__ bk,
                                                     const float* __restrict__ bv)
{
    extern __shared__ __align__(128) char sm_raw[];
    const uint32_t smbase = smem_u32(sm_raw);

    const int which = blockIdx.z;
    const float* bias = (which == 0) ? bq : ((which == 1) ? bk : bv);
    __half* Hd = (which == 0) ? g_Qh : ((which == 1) ? g_Kh : g_Vh);
    const __half* Wt = g_Wh + (size_t)which * 1048576;

    const int tid = threadIdx.x, lane = tid & 31, wid = tid >> 5;
    const int wm = (wid >> 2) * 32, wn = (wid & 3) * 32;
    const int row0 = blockIdx.y << 7, col0 = blockIdx.x << 7;

    const int rowA = wm + (lane & 15);
    const int rA7 = rowA & 7;
    const int unA = lane >> 4;
    const int rowB = wn + (lane & 7);
    const int rB7 = lane & 7;
    const int unB = (lane >> 3) & 1;
    const int lr = tid >> 3, lu = tid & 7;

    float cf[2][4][4];
#pragma unroll
    for (int mt = 0; mt < 2; ++mt)
#pragma unroll
        for (int nt = 0; nt < 4; ++nt)
#pragma unroll
            for (int q = 0; q < 4; ++q) cf[mt][nt][q] = 0.f;

    auto load_chunk = [&](int c, int stage) {
        const int k0 = c << 6;
        const uint32_t st = smbase + stage * 32768;
#pragma unroll
        for (int it = 0; it < 2; ++it) {
            int r = lr + it * 64;
            size_t ga = (size_t)(row0 + r) * 1024 + k0 + lu * 8;
            size_t gb = (size_t)(col0 + r) * 1024 + k0 + lu * 8;
            uint32_t so = r * 128 + ((lu ^ (r & 7)) << 4);
            cpa16(st + so,         g_Xh + ga);
            cpa16(st + 16384 + so, Wt + gb);
        }
    };

    load_chunk(0, 0); CP_COMMIT();
    load_chunk(1, 1); CP_COMMIT();

    for (int c = 0; c < 16; ++c) {
        CP_WAIT1();
        __syncthreads();
        if (c + 2 < 16) load_chunk(c + 2, (c + 2) % 3);
        CP_COMMIT();
        const uint32_t st = smbase + (c % 3) * 32768;
#pragma unroll
        for (int ks = 0; ks < 4; ++ks) {
            uint32_t ah[2][4], bh[4][2];
#pragma unroll
            for (int mt = 0; mt < 2; ++mt) {
                uint32_t off = (rowA + mt * 16) * 128 + ((((ks << 1) + unA) ^ rA7) << 4);
                ldsm_x4(ah[mt][0], ah[mt][1], ah[mt][2], ah[mt][3], st + off);
            }
#pragma unroll
            for (int nt = 0; nt < 4; ++nt) {
                uint32_t off = (rowB + nt * 8) * 128 + ((((ks << 1) + unB) ^ rB7) << 4);
                ldsm_x2(bh[nt][0], bh[nt][1], st + 16384 + off);
            }
#pragma unroll
            for (int nt = 0; nt < 4; ++nt)
#pragma unroll
                for (int mt = 0; mt < 2; ++mt)
                    mma16816h(cf[mt][nt][0], cf[mt][nt][1], cf[mt][nt][2], cf[mt][nt][3],
                              ah[mt][0], ah[mt][1], ah[mt][2], ah[mt][3], bh[nt][0], bh[nt][1]);
        }
    }

#pragma unroll
    for (int mt = 0; mt < 2; ++mt) {
        const int r0 = row0 + wm + mt * 16 + (lane >> 2);
#pragma unroll
        for (int nt = 0; nt < 4; ++nt) {
            const int ccol = col0 + wn + nt * 8 + ((lane & 3) << 1);
            const float2 bvv = *(const float2*)&bias[ccol];
            size_t o0 = (size_t)r0 * 1024 + ccol;
            *(uint32_t*)(Hd + o0)            = packhf(cf[mt][nt][0] + bvv.x, cf[mt][nt][1] + bvv.y);
            *(uint32_t*)(Hd + o0 + 8 * 1024) = packhf(cf[mt][nt][2] + bvv.x, cf[mt][nt][3] + bvv.y);
        }
    }
}

// =====================================================================
// K2: kvouter fp16 mma, single pass. sk = elup1(Kh); Z exact fp32.
// =====================================================================
__global__ __launch_bounds__(256, 1) void k_kvouter_mma()
{
    extern __shared__ __align__(16) char km[];
    char* skh = km;
    char* sv  = km + 32768;
    float* zsm = (float*)(km + 65536);
    const uint32_t aH = smem_u32(skh), aV = smem_u32(sv);

    const int idx = blockIdx.x;                  // b*128 + h*16 + seg
    const int b = idx >> 7, h = (idx >> 4) & 7, seg = idx & 15;
    const int tid = threadIdx.x, lane = tid & 31, wid = tid >> 5;
    const int wm = (wid & 3) * 32, wn = (wid >> 2) * 64;
    const int krow = b * 8192 + seg * 512;
    const int hc = h * 128;

    const int rLa = (lane & 7) + ((lane >> 4) & 1) * 8;
    const int uAd = (lane >> 3) & 1;
    const int rKt = (lane & 7) + ((lane >> 3) & 1) * 8;
    const int tr = tid >> 4, tu = tid & 15;

    float acc[2][8][4];
#pragma unroll
    for (int mt = 0; mt < 2; ++mt)
#pragma unroll
        for (int nt = 0; nt < 8; ++nt)
#pragma unroll
            for (int q = 0; q < 4; ++q) acc[mt][nt][q] = 0.f;
    float zacc[8] = {0.f,0.f,0.f,0.f,0.f,0.f,0.f,0.f};

    for (int ch = 0; ch < 4; ++ch) {
        __syncthreads();
#pragma unroll
        for (int it = 0; it < 8; ++it) {
            int i2 = it * 256 + tid;
            int r = i2 >> 4, u = i2 & 15;
            cpa16(aV + r * 256 + (swu(u, r) << 4),
                  g_Vh + (size_t)(krow + ch * 128 + r) * 1024 + hc + u * 8);
        }
        CP_COMMIT();
        {
            uint4 kh[8];
#pragma unroll
            for (int it = 0; it < 8; ++it) {
                int r = tr + it * 16;
                kh[it] = *(const uint4*)(g_Kh + (size_t)(krow + ch * 128 + r) * 1024 + hc + tu * 8);
            }
#pragma unroll
            for (int it = 0; it < 8; ++it) {
                int r = tr + it * 16;
                uint4 oh;
                uint32_t* ph = (uint32_t*)&kh[it];
                uint32_t* qh = (uint32_t*)&oh;
#pragma unroll
                for (int w2 = 0; w2 < 4; ++w2) {
                    float2 fh = __half22float2(*(__half2*)&ph[w2]);
                    float s0 = elup1(fh.x);
                    float s1 = elup1(fh.y);
                    zacc[w2 * 2]     += s0;
                    zacc[w2 * 2 + 1] += s1;
                    qh[w2] = packhf(s0, s1);
                }
                *(uint4*)(skh + r * 256 + (swu(tu, r) << 4)) = oh;
            }
        }
        CP_WAIT0();
        __syncthreads();
#pragma unroll
        for (int ks = 0; ks < 8; ++ks) {
            uint32_t af[2][4], bf[8][2];
#pragma unroll
            for (int mt = 0; mt < 2; ++mt) {
                int rr = ks * 16 + rLa;
                int uu = ((wm + mt * 16) >> 3) + uAd;
                ldsm_x4t(af[mt][0], af[mt][1], af[mt][2], af[mt][3],
                         aH + rr * 256 + (swu(uu, rr) << 4));
            }
            int rB = ks * 16 + rKt;
#pragma unroll
            for (int nt = 0; nt < 8; ++nt)
                ldsm_x2t(bf[nt][0], bf[nt][1],
                         aV + rB * 256 + (swu((wn >> 3) + nt, rB) << 4));
#pragma unroll
            for (int nt = 0; nt < 8; ++nt)
#pragma unroll
                for (int mt = 0; mt < 2; ++mt)
                    mma16816h(acc[mt][nt][0], acc[mt][nt][1], acc[mt][nt][2], acc[mt][nt][3],
                              af[mt][0], af[mt][1], af[mt][2], af[mt][3],
                              bf[nt][0], bf[nt][1]);
        }
    }

    const size_t pbase = (size_t)idx * 16384;
#pragma unroll
    for (int mt = 0; mt < 2; ++mt) {
        int r0 = wm + mt * 16 + (lane >> 2);
#pragma unroll
        for (int nt = 0; nt < 8; ++nt) {
            int col = wn + nt * 8 + ((lane & 3) << 1);
            *(float2*)&g_P[pbase + (size_t)r0 * 128 + col]       = make_float2(acc[mt][nt][0], acc[mt][nt][1]);
            *(float2*)&g_P[pbase + (size_t)(r0 + 8) * 128 + col] = make_float2(acc[mt][nt][2], acc[mt][nt][3]);
        }
    }
#pragma unroll
    for (int j = 0; j < 8; ++j) zsm[tr * 128 + tu * 8 + j] = zacc[j];
    __syncthreads();
    if (tid < 128) {
        float s = 0.f;
#pragma unroll
        for (int g = 0; g < 16; ++g) s += zsm[g * 128 + tid];
        g_Zseg[idx * 128 + tid] = 512.f * s;
    }
}

// =====================================================================
// K3: inclusive prefix over seg (grid 256: bh x ugroup)
// =====================================================================
__global__ __launch_bounds__(256) void k_prefix()
{
    const int bh = blockIdx.x >> 3, ug = blockIdx.x & 7;
    const int tid = threadIdx.x;
    float acc[8] = {0.f,0.f,0.f,0.f,0.f,0.f,0.f,0.f};
    float zacc = 0.f;
    for (int seg = 0; seg < 16; ++seg) {
        const size_t base = ((size_t)bh * 16 + seg) * 16384;
#pragma unroll
        for (int uu = 0; uu < 8; ++uu) {
            int u = ug * 8 + uu;
            acc[uu] += g_P[base + u * 256 + tid];
            g_Memh[base + u * 256 + tid] = __float2half_rn(acc[uu]);
        }
        if (ug == 0 && tid < 128) {
            zacc += g_Zseg[(bh * 16 + seg) * 128 + tid];
            g_Z[(bh * 16 + seg) * 128 + tid] = zacc;
        }
    }
}

// =====================================================================
// K4: fp16 mma attention v2 — qt=32, 2 CTAs/SM.
// smem: Sc fp32 [32][516]=66048 | sAh 8192 | sB 32768 (2x16K) | ctl
// grid 1024 = b*256 + seg*16 + qt
// =====================================================================
__global__ __launch_bounds__(256, 2) void k_attn_mma(const float* __restrict__ beta,
                                                     float* __restrict__ out)
{
    extern __shared__ __align__(16) char smraw[];
    float* Sc = (float*)smraw;                       // 66048
    char* sAh = smraw + 66048;                       // 8192
    char* sB  = smraw + 74240;                       // 32768 (b0 @0, b1 @16384)
    float* zs  = (float*)(smraw + 107008);           // 128
    float* rs  = zs + 128;                           // 32
    float* den = rs + 32;                            // 32
    const uint32_t aAh = smem_u32(sAh);
    const uint32_t aB = smem_u32(sB);

    const int idx = blockIdx.x;
    const int b = idx >> 8, seg = (idx >> 4) & 15, qt = idx & 15;
    const int tid = threadIdx.x, lane = tid & 31, wid = tid >> 5;
    const int qrow0 = b * 8192 + seg * 512 + qt * 32;
    const int krow0 = b * 8192 + seg * 512;
    const float bsig = 1.f / (1.f + __expf(-beta[0]));
    const float bsig8 = bsig * 0.125f, obsig8 = (1.f - bsig) * 0.125f;
    const float scale = 0.088388347648318447f;

    // score phase: warp tile 16 rows x 16 cols (rows {0,16}, cols {0,16,32,48})
    const int wr = (wid >> 2) * 16, wc = (wid & 3) * 16;
    // retrieval/PV: warp tile 16 rows x 32 cols (rows {0,16}, cols {0,32,64,96})
    const int wn4 = (wid & 3) * 32;

    const int rowA0 = wr + (lane & 15);
    const int unA = lane >> 4;
    const int rowBn = wc + (lane & 7);
    const int unB = (lane >> 3) & 1;
    const int rowKt = (lane & 7) + ((lane >> 3) & 1) * 8;
    const int srow = tid >> 3, spart = tid & 7;

    float facc[4][4];
#pragma unroll
    for (int nt = 0; nt < 4; ++nt)
#pragma unroll
        for (int q = 0; q < 4; ++q) facc[nt][q] = 0.f;

    for (int h = 0; h < 8; ++h) {
        const int hc = h * 128;
        __syncthreads();   // prev head PV done: sAh, sB free
        // issue K chunk0 (64 rows) -> b0
#pragma unroll
        for (int it = 0; it < 4; ++it) {
            int i2 = it * 256 + tid;
            int r = i2 >> 4, u = i2 & 15;
            cpa16(aB + r * 256 + (swu(u, r) << 4),
                  g_Kh + (size_t)(krow0 + r) * 1024 + hc + u * 8);
        }
        CP_COMMIT();
        // Q load (32 rows)
#pragma unroll
        for (int it = 0; it < 2; ++it) {
            int i2 = it * 256 + tid;
            int r = i2 >> 4, u = i2 & 15;
            *(uint4*)(sAh + r * 256 + (swu(u, r) << 4)) =
                *(const uint4*)(g_Qh + (size_t)(qrow0 + r) * 1024 + hc + u * 8);
        }
        if (tid < 128)
            zs[tid] = g_Z[((size_t)(b * 8 + h) * 16 + seg) * 128 + tid];

        // ---- scores: 8 chunks of 64 keys, dual 16KB buffers ----
        for (int ch = 0; ch < 8; ++ch) {
            CP_WAIT0();
            __syncthreads();   // K_ch ready; Q visible (ch0); prev mma done
            if (ch < 7) {
                const uint32_t nb = aB + ((ch + 1) & 1) * 16384;
#pragma unroll
                for (int it = 0; it < 4; ++it) {
                    int i2 = it * 256 + tid;
                    int r = i2 >> 4, u = i2 & 15;
                    cpa16(nb + r * 256 + (swu(u, r) << 4),
                          g_Kh + (size_t)(krow0 + (ch + 1) * 64 + r) * 1024 + hc + u * 8);
                }
                CP_COMMIT();
            }
            const uint32_t Bb = aB + (ch & 1) * 16384;
            float acc[2][4];
#pragma unroll
            for (int nt = 0; nt < 2; ++nt)
#pragma unroll
                for (int q = 0; q < 4; ++q) acc[nt][q] = 0.f;
#pragma unroll
            for (int ks = 0; ks < 8; ++ks) {
                uint32_t af[4], bfr[2][2];
                ldsm_x4(af[0], af[1], af[2], af[3],
                        aAh + rowA0 * 256 + (swu(ks * 2 + unA, rowA0) << 4));
#pragma unroll
                for (int nt = 0; nt < 2; ++nt)
                    ldsm_x2(bfr[nt][0], bfr[nt][1],
                            Bb + (rowBn + nt * 8) * 256 + (swu(ks * 2 + unB, rowBn) << 4));
#pragma unroll
                for (int nt = 0; nt < 2; ++nt)
                    mma16816h(acc[nt][0], acc[nt][1], acc[nt][2], acc[nt][3],
                              af[0], af[1], af[2], af[3], bfr[nt][0], bfr[nt][1]);
            }
            {
                int r0 = wr + (lane >> 2);
#pragma unroll
                for (int nt = 0; nt < 2; ++nt) {
                    int cc = ch * 64 + wc + nt * 8 + ((lane & 3) << 1);
                    *(float2*)&Sc[r0 * 516 + cc]       = make_float2(acc[nt][0] * scale, acc[nt][1] * scale);
                    *(float2*)&Sc[(r0 + 8) * 516 + cc] = make_float2(acc[nt][2] * scale, acc[nt][3] * scale);
                }
            }
        }
        __syncthreads();   // Sc complete; chunk7 mma done -> sB free
        // issue Mem (128x128 = 32KB) into full sB; softmax hides the load
#pragma unroll
        for (int it = 0; it < 8; ++it) {
            int i2 = it * 256 + tid;
            int r = i2 >> 4, u = i2 & 15;
            size_t ms = ((size_t)(b * 8 + h) * 16 + seg) * 16384 + r * 128 + u * 8;
            cpa16(aB + r * 256 + (swu(u, r) << 4), g_Memh + ms);
        }
        CP_COMMIT();
        // ---- softmax: 8 threads/row, 64 elems each, rotated scan ----
        {
            float* rowp = &Sc[srow * 516];
            const int base = spart * 64, rot = spart * 8;
            float m = -1e30f;
#pragma unroll 8
            for (int j = 0; j < 64; ++j) m = fmaxf(m, rowp[base + ((j + rot) & 63)]);
            m = fmaxf(m, __shfl_xor_sync(0xffffffffu, m, 1));
            m = fmaxf(m, __shfl_xor_sync(0xffffffffu, m, 2));
            m = fmaxf(m, __shfl_xor_sync(0xffffffffu, m, 4));
            float s = 0.f;
#pragma unroll 8
            for (int j = 0; j < 64; ++j) {
                int jj = base + ((j + rot) & 63);
                float e = __expf(rowp[jj] - m); rowp[jj] = e; s += e;
            }
            s += __shfl_xor_sync(0xffffffffu, s, 1);
            s += __shfl_xor_sync(0xffffffffu, s, 2);
            s += __shfl_xor_sync(0xffffffffu, s, 4);
            if (spart == 0) rs[srow] = s;
        }
        // ---- sq = elup1(qh) in sAh + exact den ----
        {
            float da = 0.f;
#pragma unroll 4
            for (int j = 0; j < 16; ++j) {
                int c = spart * 16 + j;
                uint32_t bo = srow * 256 + (swu(c >> 3, srow) << 4) + ((c & 7) << 1);
                float qh = __half2float(*(__half*)(sAh + bo));
                float sq = elup1(qh);
                da += sq * zs[c];
                *(__half*)(sAh + bo) = __float2half_rn(sq);
            }
            da += __shfl_xor_sync(0xffffffffu, da, 1);
            da += __shfl_xor_sync(0xffffffffu, da, 2);
            da += __shfl_xor_sync(0xffffffffu, da, 4);
            if (spart == 0) den[srow] = da;
        }
        CP_WAIT0();
        __syncthreads();   // Mem ready + sq transform visible
        // ---- retrieval: sq x Memh ----
        {
            float acc[4][4];
#pragma unroll
            for (int nt = 0; nt < 4; ++nt)
#pragma unroll
                for (int q = 0; q < 4; ++q) acc[nt][q] = 0.f;
#pragma unroll
            for (int ks = 0; ks < 8; ++ks) {
                uint32_t af[4], bfr[4][2];
                ldsm_x4(af[0], af[1], af[2], af[3],
                        aAh + rowA0 * 256 + (swu(ks * 2 + unA, rowA0) << 4));
                int rK = ks * 16 + rowKt;
#pragma unroll
                for (int nt = 0; nt < 4; ++nt)
                    ldsm_x2t(bfr[nt][0], bfr[nt][1],
                             aB + rK * 256 + (swu((wn4 >> 3) + nt, rK) << 4));
#pragma unroll
                for (int nt = 0; nt < 4; ++nt)
                    mma16816h(acc[nt][0], acc[nt][1], acc[nt][2], acc[nt][3],
                              af[0], af[1], af[2], af[3], bfr[nt][0], bfr[nt][1]);
            }
            int r0 = wr + (lane >> 2);
            float m0 = bsig8 / (den[r0] + 1e-5f);
            float m1 = bsig8 / (den[r0 + 8] + 1e-5f);
#pragma unroll
            for (int nt = 0; nt < 4; ++nt) {
                facc[nt][0] += acc[nt][0] * m0;
                facc[nt][1] += acc[nt][1] * m0;
                facc[nt][2] += acc[nt][2] * m1;
                facc[nt][3] += acc[nt][3] * m1;
            }
        }
        // ---- PV: 4 chunks of 128 keys; V (32KB) into sB; P pack into sAh ----
        float dacc[4][4];
#pragma unroll
        for (int nt = 0; nt < 4; ++nt)
#pragma unroll
            for (int q = 0; q < 4; ++q) dacc[nt][q] = 0.f;
        for (int ch = 0; ch < 4; ++ch) {
            __syncthreads();   // prev mma / retrieval done: sB + sAh reusable
#pragma unroll
            for (int it = 0; it < 8; ++it) {
                int i2 = it * 256 + tid;
                int r = i2 >> 4, u = i2 & 15;
                cpa16(aB + r * 256 + (swu(u, r) << 4),
                      g_Vh + (size_t)(krow0 + ch * 128 + r) * 1024 + hc + u * 8);
            }
            CP_COMMIT();
            // pack P chunk (32 x 128) -> sAh
#pragma unroll
            for (int it = 0; it < 2; ++it) {
                int i2 = it * 256 + tid;
                int r = i2 >> 4, u = i2 & 15;
                const float* sp = &Sc[r * 516 + ch * 128 + u * 8];
                float4 p0 = *(const float4*)sp, p1 = *(const float4*)(sp + 4);
                uint4 hi;
                hi.x = packhf(p0.x, p0.y); hi.y = packhf(p0.z, p0.w);
                hi.z = packhf(p1.x, p1.y); hi.w = packhf(p1.z, p1.w);
                *(uint4*)(sAh + r * 256 + (swu(u, r) << 4)) = hi;
            }
            CP_WAIT0();
            __syncthreads();   // V + pack visible
#pragma unroll
            for (int ks = 0; ks < 8; ++ks) {
                uint32_t af[4], bfr[4][2];
                ldsm_x4(af[0], af[1], af[2], af[3],
                        aAh + rowA0 * 256 + (swu(ks * 2 + unA, rowA0) << 4));
                int rK = ks * 16 + rowKt;
#pragma unroll
                for (int nt = 0; nt < 4; ++nt)
                    ldsm_x2t(bfr[nt][0], bfr[nt][1],
                             aB + rK * 256 + (swu((wn4 >> 3) + nt, rK) << 4));
#pragma unroll
                for (int nt = 0; nt < 4; ++nt)
                    mma16816h(dacc[nt][0], dacc[nt][1], dacc[nt][2], dacc[nt][3],
                              af[0], af[1], af[2], af[3], bfr[nt][0], bfr[nt][1]);
            }
        }
        {
            int r0 = wr + (lane >> 2);
            float d0 = obsig8 / rs[r0];
            float d1 = obsig8 / rs[r0 + 8];
#pragma unroll
            for (int nt = 0; nt < 4; ++nt) {
                facc[nt][0] += dacc[nt][0] * d0;
                facc[nt][1] += dacc[nt][1] * d0;
                facc[nt][2] += dacc[nt][2] * d1;
                facc[nt][3] += dacc[nt][3] * d1;
            }
        }
    }

    {
        int r0 = wr + (lane >> 2);
#pragma unroll
        for (int nt = 0; nt < 4; ++nt) {
            int col = wn4 + nt * 8 + ((lane & 3) << 1);
            *(float2*)&out[(size_t)(qrow0 + r0) * 128 + col]     = make_float2(facc[nt][0], facc[nt][1]);
            *(float2*)&out[(size_t)(qrow0 + r0 + 8) * 128 + col] = make_float2(facc[nt][2], facc[nt][3]);
        }
    }
}

// =====================================================================
extern "C" void kernel_launch(void* const* d_in, const int* in_sizes, int n_in,
                              void* d_out, int out_size)
{
    const float* x    = (const float*)d_in[0];
    const float* wq   = (const float*)d_in[1];
    const float* bq   = (const float*)d_in[2];
    const float* wk   = (const float*)d_in[3];
    const float* bk   = (const float*)d_in[4];
    const float* wv   = (const float*)d_in[5];
    const float* bv   = (const float*)d_in[6];
    const float* beta = (const float*)d_in[7];
    float* out = (float*)d_out;

    static int attr_set = 0;
    if (!attr_set) {
        cudaFuncSetAttribute(k_attn_mma, cudaFuncAttributeMaxDynamicSharedMemorySize, 107776);
        cudaFuncSetAttribute(k_proj_mma, cudaFuncAttributeMaxDynamicSharedMemorySize, 98304);
        cudaFuncSetAttribute(k_kvouter_mma, cudaFuncAttributeMaxDynamicSharedMemorySize, 73728);
        attr_set = 1;
    }

    k_splitX<<<32768, 256>>>(x);
    k_trW<<<dim3(32, 32), 256>>>(wq, 0);
    k_trW<<<dim3(32, 32), 256>>>(wk, 1);
    k_trW<<<dim3(32, 32), 256>>>(wv, 2);
    k_proj_mma<<<dim3(8, 256, 3), 512, 98304>>>(bq, bk, bv);
    k_kvouter_mma<<<512, 256, 73728>>>();
    k_prefix<<<256, 256>>>();
    k_attn_mma<<<1024, 256, 107776>>>(beta, out);
}

// round 16
// speedup vs baseline: 2.8248x; 1.1503x over previous
#include <cuda_runtime.h>
#include <cuda_fp16.h>
#include <cstdint>

// ---------- helpers ----------
__device__ __forceinline__ float elup1(float x){ return x > 0.f ? x + 1.f : __expf(x); }
__device__ __forceinline__ uint32_t smem_u32(const void* p){
    uint32_t a;
    asm("{ .reg .u64 t; cvta.to.shared.u64 t, %1; cvt.u32.u64 %0, t; }" : "=r"(a) : "l"(p));
    return a;
}
__device__ __forceinline__ void cpa16(uint32_t smaddr, const void* g){
    asm volatile("cp.async.cg.shared.global [%0], [%1], 16;" :: "r"(smaddr), "l"(g));
}
#define CP_COMMIT() asm volatile("cp.async.commit_group;" ::: "memory")
#define CP_WAIT0()  asm volatile("cp.async.wait_group 0;" ::: "memory")
#define CP_WAIT1()  asm volatile("cp.async.wait_group 1;" ::: "memory")
__device__ __forceinline__ void ldsm_x4(uint32_t &r0, uint32_t &r1, uint32_t &r2, uint32_t &r3, uint32_t addr){
    asm volatile("ldmatrix.sync.aligned.m8n8.x4.shared.b16 {%0,%1,%2,%3}, [%4];"
        : "=r"(r0), "=r"(r1), "=r"(r2), "=r"(r3) : "r"(addr));
}
__device__ __forceinline__ void ldsm_x4t(uint32_t &r0, uint32_t &r1, uint32_t &r2, uint32_t &r3, uint32_t addr){
    asm volatile("ldmatrix.sync.aligned.m8n8.x4.trans.shared.b16 {%0,%1,%2,%3}, [%4];"
        : "=r"(r0), "=r"(r1), "=r"(r2), "=r"(r3) : "r"(addr));
}
__device__ __forceinline__ void ldsm_x2(uint32_t &r0, uint32_t &r1, uint32_t addr){
    asm volatile("ldmatrix.sync.aligned.m8n8.x2.shared.b16 {%0,%1}, [%2];"
        : "=r"(r0), "=r"(r1) : "r"(addr));
}
__device__ __forceinline__ void ldsm_x2t(uint32_t &r0, uint32_t &r1, uint32_t addr){
    asm volatile("ldmatrix.sync.aligned.m8n8.x2.trans.shared.b16 {%0,%1}, [%2];"
        : "=r"(r0), "=r"(r1) : "r"(addr));
}
__device__ __forceinline__ void mma16816h(float &c0, float &c1, float &c2, float &c3,
                                          uint32_t a0, uint32_t a1, uint32_t a2, uint32_t a3,
                                          uint32_t b0, uint32_t b1){
    asm volatile("mma.sync.aligned.m16n8k16.row.col.f32.f16.f16.f32 "
        "{%0,%1,%2,%3}, {%4,%5,%6,%7}, {%8,%9}, {%0,%1,%2,%3};"
        : "+f"(c0), "+f"(c1), "+f"(c2), "+f"(c3)
        : "r"(a0), "r"(a1), "r"(a2), "r"(a3), "r"(b0), "r"(b1));
}
__device__ __forceinline__ uint32_t swu(int u, int r){ return (uint32_t)((u & 8) | ((u & 7) ^ (r & 7))); }
__device__ __forceinline__ uint32_t packhf(float a, float b){
    __half2 t = __halves2half2(__float2half_rn(a), __float2half_rn(b));
    return *(uint32_t*)&t;
}

// ---------- dims: B=4, S=8192, D=1024, H=8, dk=dv=128, SEG=512, nseg=16 ----------

// ---------- device scratch ----------
__device__ float g_P[8388608];
__device__ float g_Zseg[65536];
__device__ float g_Z[65536];
__device__ __half g_Xh[33554432];
__device__ __half g_Wh[3145728];
__device__ __half g_Qh[33554432];
__device__ __half g_Kh[33554432];
__device__ __half g_Vh[33554432];
__device__ __half g_Memh[8388608];

// =====================================================================
// S1: X -> fp16
// =====================================================================
__global__ __launch_bounds__(256) void k_splitX(const float* __restrict__ x)
{
    size_t i = ((size_t)blockIdx.x * 256 + threadIdx.x) * 4;
    float4 v = *(const float4*)(x + i);
    *(__half2*)(g_Xh + i)     = __halves2half2(__float2half_rn(v.x), __float2half_rn(v.y));
    *(__half2*)(g_Xh + i + 2) = __halves2half2(__float2half_rn(v.z), __float2half_rn(v.w));
}

// =====================================================================
// S2: transpose W[k][n] -> Wt[n][k], fp16
// =====================================================================
__global__ __launch_bounds__(256) void k_trW(const float* __restrict__ w, int which)
{
    __shared__ float t[32][33];
    const int bx = blockIdx.x << 5, by = blockIdx.y << 5;
    const int tx = threadIdx.x & 31, ty = threadIdx.x >> 5;
#pragma unroll
    for (int r = 0; r < 4; ++r)
        t[ty * 4 + r][tx] = w[(size_t)(by + ty * 4 + r) * 1024 + bx + tx];
    __syncthreads();
    __half* Wt = g_Wh + (size_t)which * 1048576;
#pragma unroll
    for (int r = 0; r < 4; ++r) {
        int n = bx + ty * 4 + r, k = by + tx;
        Wt[(size_t)n * 1024 + k] = __float2half_rn(t[tx][ty * 4 + r]);
    }
}

// =====================================================================
// K1: fused projection GEMM, fp16 single-pass; fp16 output only.
// =====================================================================
__global__ __launch_bounds__(512, 1) void k_proj_mma(const float* __restrict__ bq,
                                                     const float* __restrict__ bk,
                                                     const float* __restrict__ bv)
{
    extern __shared__ __align__(128) char sm_raw[];
    const uint32_t smbase = smem_u32(sm_raw);

    const int which = blockIdx.z;
    const float* bias = (which == 0) ? bq : ((which == 1) ? bk : bv);
    __half* Hd = (which == 0) ? g_Qh : ((which == 1) ? g_Kh : g_Vh);
    const __half* Wt = g_Wh + (size_t)which * 1048576;

    const int tid = threadIdx.x, lane = tid & 31, wid = tid >> 5;
    const int wm = (wid >> 2) * 32, wn = (wid & 3) * 32;
    const int row0 = blockIdx.y << 7, col0 = blockIdx.x << 7;

    const int rowA = wm + (lane & 15);
    const int rA7 = rowA & 7;
    const int unA = lane >> 4;
    const int rowB = wn + (lane & 7);
    const int rB7 = lane & 7;
    const int unB = (lane >> 3) & 1;
    const int lr = tid >> 3, lu = tid & 7;

    float cf[2][4][4];
#pragma unroll
    for (int mt = 0; mt < 2; ++mt)
#pragma unroll
        for (int nt = 0; nt < 4; ++nt)
#pragma unroll
            for (int q = 0; q < 4; ++q) cf[mt][nt][q] = 0.f;

    auto load_chunk = [&](int c, int stage) {
        const int k0 = c << 6;
        const uint32_t st = smbase + stage * 32768;
#pragma unroll
        for (int it = 0; it < 2; ++it) {
            int r = lr + it * 64;
            size_t ga = (size_t)(row0 + r) * 1024 + k0 + lu * 8;
            size_t gb = (size_t)(col0 + r) * 1024 + k0 + lu * 8;
            uint32_t so = r * 128 + ((lu ^ (r & 7)) << 4);
            cpa16(st + so,         g_Xh + ga);
            cpa16(st + 16384 + so, Wt + gb);
        }
    };

    load_chunk(0, 0); CP_COMMIT();
    load_chunk(1, 1); CP_COMMIT();

    for (int c = 0; c < 16; ++c) {
        CP_WAIT1();
        __syncthreads();
        if (c + 2 < 16) load_chunk(c + 2, (c + 2) % 3);
        CP_COMMIT();
        const uint32_t st = smbase + (c % 3) * 32768;
#pragma unroll
        for (int ks = 0; ks < 4; ++ks) {
            uint32_t ah[2][4], bh[4][2];
#pragma unroll
            for (int mt = 0; mt < 2; ++mt) {
                uint32_t off = (rowA + mt * 16) * 128 + ((((ks << 1) + unA) ^ rA7) << 4);
                ldsm_x4(ah[mt][0], ah[mt][1], ah[mt][2], ah[mt][3], st + off);
            }
#pragma unroll
            for (int nt = 0; nt < 4; ++nt) {
                uint32_t off = (rowB + nt * 8) * 128 + ((((ks << 1) + unB) ^ rB7) << 4);
                ldsm_x2(bh[nt][0], bh[nt][1], st + 16384 + off);
            }
#pragma unroll
            for (int nt = 0; nt < 4; ++nt)
#pragma unroll
                for (int mt = 0; mt < 2; ++mt)
                    mma16816h(cf[mt][nt][0], cf[mt][nt][1], cf[mt][nt][2], cf[mt][nt][3],
                              ah[mt][0], ah[mt][1], ah[mt][2], ah[mt][3], bh[nt][0], bh[nt][1]);
        }
    }

#pragma unroll
    for (int mt = 0; mt < 2; ++mt) {
        const int r0 = row0 + wm + mt * 16 + (lane >> 2);
#pragma unroll
        for (int nt = 0; nt < 4; ++nt) {
            const int ccol = col0 + wn + nt * 8 + ((lane & 3) << 1);
            const float2 bvv = *(const float2*)&bias[ccol];
            size_t o0 = (size_t)r0 * 1024 + ccol;
            *(uint32_t*)(Hd + o0)            = packhf(cf[mt][nt][0] + bvv.x, cf[mt][nt][1] + bvv.y);
            *(uint32_t*)(Hd + o0 + 8 * 1024) = packhf(cf[mt][nt][2] + bvv.x, cf[mt][nt][3] + bvv.y);
        }
    }
}

// =====================================================================
// K2: kvouter fp16 mma, single pass, 2 CTAs/SM. sk = elup1(Kh).
// =====================================================================
__global__ __launch_bounds__(256, 2) void k_kvouter_mma()
{
    extern __shared__ __align__(16) char km[];
    char* skh = km;
    char* sv  = km + 32768;
    float* zsm = (float*)(km + 65536);
    const uint32_t aH = smem_u32(skh), aV = smem_u32(sv);

    const int idx = blockIdx.x;                  // b*128 + h*16 + seg
    const int b = idx >> 7, h = (idx >> 4) & 7, seg = idx & 15;
    const int tid = threadIdx.x, lane = tid & 31, wid = tid >> 5;
    const int wm = (wid & 3) * 32, wn = (wid >> 2) * 64;
    const int krow = b * 8192 + seg * 512;
    const int hc = h * 128;

    const int rLa = (lane & 7) + ((lane >> 4) & 1) * 8;
    const int uAd = (lane >> 3) & 1;
    const int rKt = (lane & 7) + ((lane >> 3) & 1) * 8;
    const int tr = tid >> 4, tu = tid & 15;

    float acc[2][8][4];
#pragma unroll
    for (int mt = 0; mt < 2; ++mt)
#pragma unroll
        for (int nt = 0; nt < 8; ++nt)
#pragma unroll
            for (int q = 0; q < 4; ++q) acc[mt][nt][q] = 0.f;
    float zacc[8] = {0.f,0.f,0.f,0.f,0.f,0.f,0.f,0.f};

    for (int ch = 0; ch < 4; ++ch) {
        __syncthreads();
#pragma unroll
        for (int it = 0; it < 8; ++it) {
            int i2 = it * 256 + tid;
            int r = i2 >> 4, u = i2 & 15;
            cpa16(aV + r * 256 + (swu(u, r) << 4),
                  g_Vh + (size_t)(krow + ch * 128 + r) * 1024 + hc + u * 8);
        }
        CP_COMMIT();
        {
            uint4 kh[8];
#pragma unroll
            for (int it = 0; it < 8; ++it) {
                int r = tr + it * 16;
                kh[it] = *(const uint4*)(g_Kh + (size_t)(krow + ch * 128 + r) * 1024 + hc + tu * 8);
            }
#pragma unroll
            for (int it = 0; it < 8; ++it) {
                int r = tr + it * 16;
                uint4 oh;
                uint32_t* ph = (uint32_t*)&kh[it];
                uint32_t* qh = (uint32_t*)&oh;
#pragma unroll
                for (int w2 = 0; w2 < 4; ++w2) {
                    float2 fh = __half22float2(*(__half2*)&ph[w2]);
                    float s0 = elup1(fh.x);
                    float s1 = elup1(fh.y);
                    zacc[w2 * 2]     += s0;
                    zacc[w2 * 2 + 1] += s1;
                    qh[w2] = packhf(s0, s1);
                }
                *(uint4*)(skh + r * 256 + (swu(tu, r) << 4)) = oh;
            }
        }
        CP_WAIT0();
        __syncthreads();
#pragma unroll
        for (int ks = 0; ks < 8; ++ks) {
            uint32_t af[2][4], bf[8][2];
#pragma unroll
            for (int mt = 0; mt < 2; ++mt) {
                int rr = ks * 16 + rLa;
                int uu = ((wm + mt * 16) >> 3) + uAd;
                ldsm_x4t(af[mt][0], af[mt][1], af[mt][2], af[mt][3],
                         aH + rr * 256 + (swu(uu, rr) << 4));
            }
            int rB = ks * 16 + rKt;
#pragma unroll
            for (int nt = 0; nt < 8; ++nt)
                ldsm_x2t(bf[nt][0], bf[nt][1],
                         aV + rB * 256 + (swu((wn >> 3) + nt, rB) << 4));
#pragma unroll
            for (int nt = 0; nt < 8; ++nt)
#pragma unroll
                for (int mt = 0; mt < 2; ++mt)
                    mma16816h(acc[mt][nt][0], acc[mt][nt][1], acc[mt][nt][2], acc[mt][nt][3],
                              af[mt][0], af[mt][1], af[mt][2], af[mt][3],
                              bf[nt][0], bf[nt][1]);
        }
    }

    const size_t pbase = (size_t)idx * 16384;
#pragma unroll
    for (int mt = 0; mt < 2; ++mt) {
        int r0 = wm + mt * 16 + (lane >> 2);
#pragma unroll
        for (int nt = 0; nt < 8; ++nt) {
            int col = wn + nt * 8 + ((lane & 3) << 1);
            *(float2*)&g_P[pbase + (size_t)r0 * 128 + col]       = make_float2(acc[mt][nt][0], acc[mt][nt][1]);
            *(float2*)&g_P[pbase + (size_t)(r0 + 8) * 128 + col] = make_float2(acc[mt][nt][2], acc[mt][nt][3]);
        }
    }
#pragma unroll
    for (int j = 0; j < 8; ++j) zsm[tr * 128 + tu * 8 + j] = zacc[j];
    __syncthreads();
    if (tid < 128) {
        float s = 0.f;
#pragma unroll
        for (int g = 0; g < 16; ++g) s += zsm[g * 128 + tid];
        g_Zseg[idx * 128 + tid] = 512.f * s;
    }
}

// =====================================================================
// K3: inclusive prefix over seg (grid 256: bh x ugroup)
// =====================================================================
__global__ __launch_bounds__(256) void k_prefix()
{
    const int bh = blockIdx.x >> 3, ug = blockIdx.x & 7;
    const int tid = threadIdx.x;
    float acc[8] = {0.f,0.f,0.f,0.f,0.f,0.f,0.f,0.f};
    float zacc = 0.f;
    for (int seg = 0; seg < 16; ++seg) {
        const size_t base = ((size_t)bh * 16 + seg) * 16384;
#pragma unroll
        for (int uu = 0; uu < 8; ++uu) {
            int u = ug * 8 + uu;
            acc[uu] += g_P[base + u * 256 + tid];
            g_Memh[base + u * 256 + tid] = __float2half_rn(acc[uu]);
        }
        if (ug == 0 && tid < 128) {
            zacc += g_Zseg[(bh * 16 + seg) * 128 + tid];
            g_Z[(bh * 16 + seg) * 128 + tid] = zacc;
        }
    }
}

// =====================================================================
// K4: fp16 mma attention v3 — qt=32, fp16 swizzled Sc tiles, 3 CTAs/SM.
// smem: Sc 4x8192=32768 | sAh 8192 | sB 32768 | ctl 768 -> 74496
// =====================================================================
__global__ __launch_bounds__(256, 3) void k_attn_mma(const float* __restrict__ beta,
                                                     float* __restrict__ out)
{
    extern __shared__ __align__(16) char smraw[];
    char* sSc = smraw;                               // 32768: 4 tiles [32][128] fp16
    char* sAh = smraw + 32768;                       // 8192
    char* sB  = smraw + 40960;                       // 32768 (dual 16K for K)
    float* zs  = (float*)(smraw + 73728);            // 128
    float* rs  = zs + 128;                           // 32
    float* den = rs + 32;                            // 32
    const uint32_t aSc = smem_u32(sSc);
    const uint32_t aAh = smem_u32(sAh);
    const uint32_t aB = smem_u32(sB);

    const int idx = blockIdx.x;
    const int b = idx >> 8, seg = (idx >> 4) & 15, qt = idx & 15;
    const int tid = threadIdx.x, lane = tid & 31, wid = tid >> 5;
    const int qrow0 = b * 8192 + seg * 512 + qt * 32;
    const int krow0 = b * 8192 + seg * 512;
    const float bsig = 1.f / (1.f + __expf(-beta[0]));
    const float bsig8 = bsig * 0.125f, obsig8 = (1.f - bsig) * 0.125f;
    const float scale = 0.088388347648318447f;

    const int wr = (wid >> 2) * 16, wc = (wid & 3) * 16;
    const int wn4 = (wid & 3) * 32;
    const int rowA0 = wr + (lane & 15);
    const int unA = lane >> 4;
    const int rowBn = wc + (lane & 7);
    const int unB = (lane >> 3) & 1;
    const int rowKt = (lane & 7) + ((lane >> 3) & 1) * 8;
    const int srow = tid >> 3, spart = tid & 7;

    float facc[4][4];
#pragma unroll
    for (int nt = 0; nt < 4; ++nt)
#pragma unroll
        for (int q = 0; q < 4; ++q) facc[nt][q] = 0.f;

    for (int h = 0; h < 8; ++h) {
        const int hc = h * 128;
        __syncthreads();   // prev head done: all smem free
        // K chunk0 (64 rows) -> b0
#pragma unroll
        for (int it = 0; it < 4; ++it) {
            int i2 = it * 256 + tid;
            int r = i2 >> 4, u = i2 & 15;
            cpa16(aB + r * 256 + (swu(u, r) << 4),
                  g_Kh + (size_t)(krow0 + r) * 1024 + hc + u * 8);
        }
        CP_COMMIT();
        // Q (32 rows) -> sAh
#pragma unroll
        for (int it = 0; it < 2; ++it) {
            int i2 = it * 256 + tid;
            int r = i2 >> 4, u = i2 & 15;
            *(uint4*)(sAh + r * 256 + (swu(u, r) << 4)) =
                *(const uint4*)(g_Qh + (size_t)(qrow0 + r) * 1024 + hc + u * 8);
        }
        if (tid < 128)
            zs[tid] = g_Z[((size_t)(b * 8 + h) * 16 + seg) * 128 + tid];

        // ---- scores: 8 chunks of 64 keys, dual 16KB buffers; fp16 out ----
        for (int ch = 0; ch < 8; ++ch) {
            CP_WAIT0();
            __syncthreads();
            if (ch < 7) {
                const uint32_t nb = aB + ((ch + 1) & 1) * 16384;
#pragma unroll
                for (int it = 0; it < 4; ++it) {
                    int i2 = it * 256 + tid;
                    int r = i2 >> 4, u = i2 & 15;
                    cpa16(nb + r * 256 + (swu(u, r) << 4),
                          g_Kh + (size_t)(krow0 + (ch + 1) * 64 + r) * 1024 + hc + u * 8);
                }
                CP_COMMIT();
            }
            const uint32_t Bb = aB + (ch & 1) * 16384;
            float acc[2][4];
#pragma unroll
            for (int nt = 0; nt < 2; ++nt)
#pragma unroll
                for (int q = 0; q < 4; ++q) acc[nt][q] = 0.f;
#pragma unroll
            for (int ks = 0; ks < 8; ++ks) {
                uint32_t af[4], bfr[2][2];
                ldsm_x4(af[0], af[1], af[2], af[3],
                        aAh + rowA0 * 256 + (swu(ks * 2 + unA, rowA0) << 4));
#pragma unroll
                for (int nt = 0; nt < 2; ++nt)
                    ldsm_x2(bfr[nt][0], bfr[nt][1],
                            Bb + (rowBn + nt * 8) * 256 + (swu(ks * 2 + unB, rowBn) << 4));
#pragma unroll
                for (int nt = 0; nt < 2; ++nt)
                    mma16816h(acc[nt][0], acc[nt][1], acc[nt][2], acc[nt][3],
                              af[0], af[1], af[2], af[3], bfr[nt][0], bfr[nt][1]);
            }
            {
                int r0 = wr + (lane >> 2);
                char* tp = sSc + (ch >> 1) * 8192;
#pragma unroll
                for (int nt = 0; nt < 2; ++nt) {
                    int col = ((ch & 1) << 6) + wc + nt * 8 + ((lane & 3) << 1);
                    *(uint32_t*)(tp + r0 * 256 + (swu(col >> 3, r0) << 4) + ((col & 7) << 1)) =
                        packhf(acc[nt][0] * scale, acc[nt][1] * scale);
                    *(uint32_t*)(tp + (r0 + 8) * 256 + (swu(col >> 3, r0 + 8) << 4) + ((col & 7) << 1)) =
                        packhf(acc[nt][2] * scale, acc[nt][3] * scale);
                }
            }
        }
        __syncthreads();   // Sc complete; sB free
        // issue Mem (32KB) into sB; softmax hides the load
#pragma unroll
        for (int it = 0; it < 8; ++it) {
            int i2 = it * 256 + tid;
            int r = i2 >> 4, u = i2 & 15;
            size_t ms = ((size_t)(b * 8 + h) * 16 + seg) * 16384 + r * 128 + u * 8;
            cpa16(aB + r * 256 + (swu(u, r) << 4), g_Memh + ms);
        }
        CP_COMMIT();
        // ---- softmax in fp16 tiles: 8 thr/row, 32 pairs each, rotated ----
        {
            float m = -1e30f;
#pragma unroll 8
            for (int j = 0; j < 32; ++j) {
                int c = spart * 64 + (((j + spart * 4) & 31) << 1);
                int tile = c >> 7, cin = c & 127;
                __half2 hv = *(__half2*)(sSc + tile * 8192 + srow * 256 +
                                         (swu(cin >> 3, srow) << 4) + ((cin & 7) << 1));
                float2 f = __half22float2(hv);
                m = fmaxf(m, fmaxf(f.x, f.y));
            }
            m = fmaxf(m, __shfl_xor_sync(0xffffffffu, m, 1));
            m = fmaxf(m, __shfl_xor_sync(0xffffffffu, m, 2));
            m = fmaxf(m, __shfl_xor_sync(0xffffffffu, m, 4));
            float s = 0.f;
#pragma unroll 8
            for (int j = 0; j < 32; ++j) {
                int c = spart * 64 + (((j + spart * 4) & 31) << 1);
                int tile = c >> 7, cin = c & 127;
                char* ap = sSc + tile * 8192 + srow * 256 +
                           (swu(cin >> 3, srow) << 4) + ((cin & 7) << 1);
                float2 f = __half22float2(*(__half2*)ap);
                float e0 = __expf(f.x - m), e1 = __expf(f.y - m);
                s += e0 + e1;
                *(uint32_t*)ap = packhf(e0, e1);
            }
            s += __shfl_xor_sync(0xffffffffu, s, 1);
            s += __shfl_xor_sync(0xffffffffu, s, 2);
            s += __shfl_xor_sync(0xffffffffu, s, 4);
            if (spart == 0) rs[srow] = s;
        }
        // ---- sq = elup1(qh) in sAh + exact den ----
        {
            float da = 0.f;
#pragma unroll 4
            for (int j = 0; j < 16; ++j) {
                int c = spart * 16 + j;
                uint32_t bo = srow * 256 + (swu(c >> 3, srow) << 4) + ((c & 7) << 1);
                float qh = __half2float(*(__half*)(sAh + bo));
                float sq = elup1(qh);
                da += sq * zs[c];
                *(__half*)(sAh + bo) = __float2half_rn(sq);
            }
            da += __shfl_xor_sync(0xffffffffu, da, 1);
            da += __shfl_xor_sync(0xffffffffu, da, 2);
            da += __shfl_xor_sync(0xffffffffu, da, 4);
            if (spart == 0) den[srow] = da;
        }
        CP_WAIT0();
        __syncthreads();   // Mem + sq + exp(P) visible
        // ---- retrieval: sq x Memh ----
        {
            float acc[4][4];
#pragma unroll
            for (int nt = 0; nt < 4; ++nt)
#pragma unroll
                for (int q = 0; q < 4; ++q) acc[nt][q] = 0.f;
#pragma unroll
            for (int ks = 0; ks < 8; ++ks) {
                uint32_t af[4], bfr[4][2];
                ldsm_x4(af[0], af[1], af[2], af[3],
                        aAh + rowA0 * 256 + (swu(ks * 2 + unA, rowA0) << 4));
                int rK = ks * 16 + rowKt;
#pragma unroll
                for (int nt = 0; nt < 4; ++nt)
                    ldsm_x2t(bfr[nt][0], bfr[nt][1],
                             aB + rK * 256 + (swu((wn4 >> 3) + nt, rK) << 4));
#pragma unroll
                for (int nt = 0; nt < 4; ++nt)
                    mma16816h(acc[nt][0], acc[nt][1], acc[nt][2], acc[nt][3],
                              af[0], af[1], af[2], af[3], bfr[nt][0], bfr[nt][1]);
            }
            int r0 = wr + (lane >> 2);
            float m0 = bsig8 / (den[r0] + 1e-5f);
            float m1 = bsig8 / (den[r0 + 8] + 1e-5f);
#pragma unroll
            for (int nt = 0; nt < 4; ++nt) {
                facc[nt][0] += acc[nt][0] * m0;
                facc[nt][1] += acc[nt][1] * m0;
                facc[nt][2] += acc[nt][2] * m1;
                facc[nt][3] += acc[nt][3] * m1;
            }
        }
        // ---- PV: 4 chunks of 128 keys; A directly from Sc tiles ----
        float dacc[4][4];
#pragma unroll
        for (int nt = 0; nt < 4; ++nt)
#pragma unroll
            for (int q = 0; q < 4; ++q) dacc[nt][q] = 0.f;
        for (int ch = 0; ch < 4; ++ch) {
            __syncthreads();   // prev mma done: sB free
#pragma unroll
            for (int it = 0; it < 8; ++it) {
                int i2 = it * 256 + tid;
                int r = i2 >> 4, u = i2 & 15;
                cpa16(aB + r * 256 + (swu(u, r) << 4),
                      g_Vh + (size_t)(krow0 + ch * 128 + r) * 1024 + hc + u * 8);
            }
            CP_COMMIT();
            CP_WAIT0();
            __syncthreads();
            const uint32_t aP = aSc + ch * 8192;
#pragma unroll
            for (int ks = 0; ks < 8; ++ks) {
                uint32_t af[4], bfr[4][2];
                ldsm_x4(af[0], af[1], af[2], af[3],
                        aP + rowA0 * 256 + (swu(ks * 2 + unA, rowA0) << 4));
                int rK = ks * 16 + rowKt;
#pragma unroll
                for (int nt = 0; nt < 4; ++nt)
                    ldsm_x2t(bfr[nt][0], bfr[nt][1],
                             aB + rK * 256 + (swu((wn4 >> 3) + nt, rK) << 4));
#pragma unroll
                for (int nt = 0; nt < 4; ++nt)
                    mma16816h(dacc[nt][0], dacc[nt][1], dacc[nt][2], dacc[nt][3],
                              af[0], af[1], af[2], af[3], bfr[nt][0], bfr[nt][1]);
            }
        }
        {
            int r0 = wr + (lane >> 2);
            float d0 = obsig8 / rs[r0];
            float d1 = obsig8 / rs[r0 + 8];
#pragma unroll
            for (int nt = 0; nt < 4; ++nt) {
                facc[nt][0] += dacc[nt][0] * d0;
                facc[nt][1] += dacc[nt][1] * d0;
                facc[nt][2] += dacc[nt][2] * d1;
                facc[nt][3] += dacc[nt][3] * d1;
            }
        }
    }

    {
        int r0 = wr + (lane >> 2);
#pragma unroll
        for (int nt = 0; nt < 4; ++nt) {
            int col = wn4 + nt * 8 + ((lane & 3) << 1);
            *(float2*)&out[(size_t)(qrow0 + r0) * 128 + col]     = make_float2(facc[nt][0], facc[nt][1]);
            *(float2*)&out[(size_t)(qrow0 + r0 + 8) * 128 + col] = make_float2(facc[nt][2], facc[nt][3]);
        }
    }
}

// =====================================================================
extern "C" void kernel_launch(void* const* d_in, const int* in_sizes, int n_in,
                              void* d_out, int out_size)
{
    const float* x    = (const float*)d_in[0];
    const float* wq   = (const float*)d_in[1];
    const float* bq   = (const float*)d_in[2];
    const float* wk   = (const float*)d_in[3];
    const float* bk   = (const float*)d_in[4];
    const float* wv   = (const float*)d_in[5];
    const float* bv   = (const float*)d_in[6];
    const float* beta = (const float*)d_in[7];
    float* out = (float*)d_out;

    static int attr_set = 0;
    if (!attr_set) {
        cudaFuncSetAttribute(k_attn_mma, cudaFuncAttributeMaxDynamicSharedMemorySize, 74496);
        cudaFuncSetAttribute(k_proj_mma, cudaFuncAttributeMaxDynamicSharedMemorySize, 98304);
        cudaFuncSetAttribute(k_kvouter_mma, cudaFuncAttributeMaxDynamicSharedMemorySize, 73728);
        attr_set = 1;
    }

    k_splitX<<<32768, 256>>>(x);
    k_trW<<<dim3(32, 32), 256>>>(wq, 0);
    k_trW<<<dim3(32, 32), 256>>>(wk, 1);
    k_trW<<<dim3(32, 32), 256>>>(wv, 2);
    k_proj_mma<<<dim3(8, 256, 3), 512, 98304>>>(bq, bk, bv);
    k_kvouter_mma<<<512, 256, 73728>>>();
    k_prefix<<<256, 256>>>();
    k_attn_mma<<<1024, 256, 74496>>>(beta, out);
}

// round 17
// speedup vs baseline: 2.8316x; 1.0024x over previous
#include <cuda_runtime.h>
#include <cuda_fp16.h>
#include <cstdint>

// ---------- helpers ----------
__device__ __forceinline__ float elup1(float x){ return x > 0.f ? x + 1.f : __expf(x); }
__device__ __forceinline__ uint32_t smem_u32(const void* p){
    uint32_t a;
    asm("{ .reg .u64 t; cvta.to.shared.u64 t, %1; cvt.u32.u64 %0, t; }" : "=r"(a) : "l"(p));
    return a;
}
__device__ __forceinline__ void cpa16(uint32_t smaddr, const void* g){
    asm volatile("cp.async.cg.shared.global [%0], [%1], 16;" :: "r"(smaddr), "l"(g));
}
#define CP_COMMIT() asm volatile("cp.async.commit_group;" ::: "memory")
#define CP_WAIT0()  asm volatile("cp.async.wait_group 0;" ::: "memory")
#define CP_WAIT1()  asm volatile("cp.async.wait_group 1;" ::: "memory")
__device__ __forceinline__ void ldsm_x4(uint32_t &r0, uint32_t &r1, uint32_t &r2, uint32_t &r3, uint32_t addr){
    asm volatile("ldmatrix.sync.aligned.m8n8.x4.shared.b16 {%0,%1,%2,%3}, [%4];"
        : "=r"(r0), "=r"(r1), "=r"(r2), "=r"(r3) : "r"(addr));
}
__device__ __forceinline__ void ldsm_x4t(uint32_t &r0, uint32_t &r1, uint32_t &r2, uint32_t &r3, uint32_t addr){
    asm volatile("ldmatrix.sync.aligned.m8n8.x4.trans.shared.b16 {%0,%1,%2,%3}, [%4];"
        : "=r"(r0), "=r"(r1), "=r"(r2), "=r"(r3) : "r"(addr));
}
__device__ __forceinline__ void ldsm_x2(uint32_t &r0, uint32_t &r1, uint32_t addr){
    asm volatile("ldmatrix.sync.aligned.m8n8.x2.shared.b16 {%0,%1}, [%2];"
        : "=r"(r0), "=r"(r1) : "r"(addr));
}
__device__ __forceinline__ void ldsm_x2t(uint32_t &r0, uint32_t &r1, uint32_t addr){
    asm volatile("ldmatrix.sync.aligned.m8n8.x2.trans.shared.b16 {%0,%1}, [%2];"
        : "=r"(r0), "=r"(r1) : "r"(addr));
}
__device__ __forceinline__ void mma16816h(float &c0, float &c1, float &c2, float &c3,
                                          uint32_t a0, uint32_t a1, uint32_t a2, uint32_t a3,
                                          uint32_t b0, uint32_t b1){
    asm volatile("mma.sync.aligned.m16n8k16.row.col.f32.f16.f16.f32 "
        "{%0,%1,%2,%3}, {%4,%5,%6,%7}, {%8,%9}, {%0,%1,%2,%3};"
        : "+f"(c0), "+f"(c1), "+f"(c2), "+f"(c3)
        : "r"(a0), "r"(a1), "r"(a2), "r"(a3), "r"(b0), "r"(b1));
}
__device__ __forceinline__ uint32_t swu(int u, int r){ return (uint32_t)((u & 8) | ((u & 7) ^ (r & 7))); }
__device__ __forceinline__ uint32_t packhf(float a, float b){
    __half2 t = __halves2half2(__float2half_rn(a), __float2half_rn(b));
    return *(uint32_t*)&t;
}

// ---------- dims: B=4, S=8192, D=1024, H=8, dk=dv=128, SEG=512, nseg=16 ----------

// ---------- device scratch ----------
__device__ float g_P[8388608];
__device__ float g_Zseg[65536];
__device__ float g_Z[65536];
__device__ __half g_Xh[33554432];
__device__ __half g_Wh[3145728];
__device__ __half g_Qh[33554432];
__device__ __half g_Kh[33554432];
__device__ __half g_Vh[33554432];
__device__ __half g_Memh[8388608];

// =====================================================================
// S1: X -> fp16
// =====================================================================
__global__ __launch_bounds__(256) void k_splitX(const float* __restrict__ x)
{
    size_t i = ((size_t)blockIdx.x * 256 + threadIdx.x) * 4;
    float4 v = *(const float4*)(x + i);
    *(__half2*)(g_Xh + i)     = __halves2half2(__float2half_rn(v.x), __float2half_rn(v.y));
    *(__half2*)(g_Xh + i + 2) = __halves2half2(__float2half_rn(v.z), __float2half_rn(v.w));
}

// =====================================================================
// S2: transpose W[k][n] -> Wt[n][k], fp16 (fused: which = blockIdx.z)
// =====================================================================
__global__ __launch_bounds__(256) void k_trW(const float* __restrict__ wq,
                                             const float* __restrict__ wk,
                                             const float* __restrict__ wv)
{
    __shared__ float t[32][33];
    const int which = blockIdx.z;
    const float* w = (which == 0) ? wq : ((which == 1) ? wk : wv);
    const int bx = blockIdx.x << 5, by = blockIdx.y << 5;
    const int tx = threadIdx.x & 31, ty = threadIdx.x >> 5;
#pragma unroll
    for (int r = 0; r < 4; ++r)
        t[ty * 4 + r][tx] = w[(size_t)(by + ty * 4 + r) * 1024 + bx + tx];
    __syncthreads();
    __half* Wt = g_Wh + (size_t)which * 1048576;
#pragma unroll
    for (int r = 0; r < 4; ++r) {
        int n = bx + ty * 4 + r, k = by + tx;
        Wt[(size_t)n * 1024 + k] = __float2half_rn(t[tx][ty * 4 + r]);
    }
}

// =====================================================================
// K1: fused projection GEMM, fp16 single-pass; fp16 output only.
// =====================================================================
__global__ __launch_bounds__(512, 1) void k_proj_mma(const float* __restrict__ bq,
                                                     const float* __restrict__ bk,
                                                     const float* __restrict__ bv)
{
    extern __shared__ __align__(128) char sm_raw[];
    const uint32_t smbase = smem_u32(sm_raw);

    const int which = blockIdx.z;
    const float* bias = (which == 0) ? bq : ((which == 1) ? bk : bv);
    __half* Hd = (which == 0) ? g_Qh : ((which == 1) ? g_Kh : g_Vh);
    const __half* Wt = g_Wh + (size_t)which * 1048576;

    const int tid = threadIdx.x, lane = tid & 31, wid = tid >> 5;
    const int wm = (wid >> 2) * 32, wn = (wid & 3) * 32;
    const int row0 = blockIdx.y << 7, col0 = blockIdx.x << 7;

    const int rowA = wm + (lane & 15);
    const int rA7 = rowA & 7;
    const int unA = lane >> 4;
    const int rowB = wn + (lane & 7);
    const int rB7 = lane & 7;
    const int unB = (lane >> 3) & 1;
    const int lr = tid >> 3, lu = tid & 7;

    float cf[2][4][4];
#pragma unroll
    for (int mt = 0; mt < 2; ++mt)
#pragma unroll
        for (int nt = 0; nt < 4; ++nt)
#pragma unroll
            for (int q = 0; q < 4; ++q) cf[mt][nt][q] = 0.f;

    auto load_chunk = [&](int c, int stage) {
        const int k0 = c << 6;
        const uint32_t st = smbase + stage * 32768;
#pragma unroll
        for (int it = 0; it < 2; ++it) {
            int r = lr + it * 64;
            size_t ga = (size_t)(row0 + r) * 1024 + k0 + lu * 8;
            size_t gb = (size_t)(col0 + r) * 1024 + k0 + lu * 8;
            uint32_t so = r * 128 + ((lu ^ (r & 7)) << 4);
            cpa16(st + so,         g_Xh + ga);
            cpa16(st + 16384 + so, Wt + gb);
        }
    };

    load_chunk(0, 0); CP_COMMIT();
    load_chunk(1, 1); CP_COMMIT();

    for (int c = 0; c < 16; ++c) {
        CP_WAIT1();
        __syncthreads();
        if (c + 2 < 16) load_chunk(c + 2, (c + 2) % 3);
        CP_COMMIT();
        const uint32_t st = smbase + (c % 3) * 32768;
#pragma unroll
        for (int ks = 0; ks < 4; ++ks) {
            uint32_t ah[2][4], bh[4][2];
#pragma unroll
            for (int mt = 0; mt < 2; ++mt) {
                uint32_t off = (rowA + mt * 16) * 128 + ((((ks << 1) + unA) ^ rA7) << 4);
                ldsm_x4(ah[mt][0], ah[mt][1], ah[mt][2], ah[mt][3], st + off);
            }
#pragma unroll
            for (int nt = 0; nt < 4; ++nt) {
                uint32_t off = (rowB + nt * 8) * 128 + ((((ks << 1) + unB) ^ rB7) << 4);
                ldsm_x2(bh[nt][0], bh[nt][1], st + 16384 + off);
            }
#pragma unroll
            for (int nt = 0; nt < 4; ++nt)
#pragma unroll
                for (int mt = 0; mt < 2; ++mt)
                    mma16816h(cf[mt][nt][0], cf[mt][nt][1], cf[mt][nt][2], cf[mt][nt][3],
                              ah[mt][0], ah[mt][1], ah[mt][2], ah[mt][3], bh[nt][0], bh[nt][1]);
        }
    }

#pragma unroll
    for (int mt = 0; mt < 2; ++mt) {
        const int r0 = row0 + wm + mt * 16 + (lane >> 2);
#pragma unroll
        for (int nt = 0; nt < 4; ++nt) {
            const int ccol = col0 + wn + nt * 8 + ((lane & 3) << 1);
            const float2 bvv = *(const float2*)&bias[ccol];
            size_t o0 = (size_t)r0 * 1024 + ccol;
            *(uint32_t*)(Hd + o0)            = packhf(cf[mt][nt][0] + bvv.x, cf[mt][nt][1] + bvv.y);
            *(uint32_t*)(Hd + o0 + 8 * 1024) = packhf(cf[mt][nt][2] + bvv.x, cf[mt][nt][3] + bvv.y);
        }
    }
}

// =====================================================================
// K2: kvouter fp16 mma, single pass, 2 CTAs/SM. sk = elup1(Kh).
// =====================================================================
__global__ __launch_bounds__(256, 2) void k_kvouter_mma()
{
    extern __shared__ __align__(16) char km[];
    char* skh = km;
    char* sv  = km + 32768;
    float* zsm = (float*)(km + 65536);
    const uint32_t aH = smem_u32(skh), aV = smem_u32(sv);

    const int idx = blockIdx.x;                  // b*128 + h*16 + seg
    const int b = idx >> 7, h = (idx >> 4) & 7, seg = idx & 15;
    const int tid = threadIdx.x, lane = tid & 31, wid = tid >> 5;
    const int wm = (wid & 3) * 32, wn = (wid >> 2) * 64;
    const int krow = b * 8192 + seg * 512;
    const int hc = h * 128;

    const int rLa = (lane & 7) + ((lane >> 4) & 1) * 8;
    const int uAd = (lane >> 3) & 1;
    const int rKt = (lane & 7) + ((lane >> 3) & 1) * 8;
    const int tr = tid >> 4, tu = tid & 15;

    float acc[2][8][4];
#pragma unroll
    for (int mt = 0; mt < 2; ++mt)
#pragma unroll
        for (int nt = 0; nt < 8; ++nt)
#pragma unroll
            for (int q = 0; q < 4; ++q) acc[mt][nt][q] = 0.f;
    float zacc[8] = {0.f,0.f,0.f,0.f,0.f,0.f,0.f,0.f};

    for (int ch = 0; ch < 4; ++ch) {
        __syncthreads();
#pragma unroll
        for (int it = 0; it < 8; ++it) {
            int i2 = it * 256 + tid;
            int r = i2 >> 4, u = i2 & 15;
            cpa16(aV + r * 256 + (swu(u, r) << 4),
                  g_Vh + (size_t)(krow + ch * 128 + r) * 1024 + hc + u * 8);
        }
        CP_COMMIT();
        {
            uint4 kh[8];
#pragma unroll
            for (int it = 0; it < 8; ++it) {
                int r = tr + it * 16;
                kh[it] = *(const uint4*)(g_Kh + (size_t)(krow + ch * 128 + r) * 1024 + hc + tu * 8);
            }
#pragma unroll
            for (int it = 0; it < 8; ++it) {
                int r = tr + it * 16;
                uint4 oh;
                uint32_t* ph = (uint32_t*)&kh[it];
                uint32_t* qh = (uint32_t*)&oh;
#pragma unroll
                for (int w2 = 0; w2 < 4; ++w2) {
                    float2 fh = __half22float2(*(__half2*)&ph[w2]);
                    float s0 = elup1(fh.x);
                    float s1 = elup1(fh.y);
                    zacc[w2 * 2]     += s0;
                    zacc[w2 * 2 + 1] += s1;
                    qh[w2] = packhf(s0, s1);
                }
                *(uint4*)(skh + r * 256 + (swu(tu, r) << 4)) = oh;
            }
        }
        CP_WAIT0();
        __syncthreads();
#pragma unroll
        for (int ks = 0; ks < 8; ++ks) {
            uint32_t af[2][4], bf[8][2];
#pragma unroll
            for (int mt = 0; mt < 2; ++mt) {
                int rr = ks * 16 + rLa;
                int uu = ((wm + mt * 16) >> 3) + uAd;
                ldsm_x4t(af[mt][0], af[mt][1], af[mt][2], af[mt][3],
                         aH + rr * 256 + (swu(uu, rr) << 4));
            }
            int rB = ks * 16 + rKt;
#pragma unroll
            for (int nt = 0; nt < 8; ++nt)
                ldsm_x2t(bf[nt][0], bf[nt][1],
                         aV + rB * 256 + (swu((wn >> 3) + nt, rB) << 4));
#pragma unroll
            for (int nt = 0; nt < 8; ++nt)
#pragma unroll
                for (int mt = 0; mt < 2; ++mt)
                    mma16816h(acc[mt][nt][0], acc[mt][nt][1], acc[mt][nt][2], acc[mt][nt][3],
                              af[mt][0], af[mt][1], af[mt][2], af[mt][3],
                              bf[nt][0], bf[nt][1]);
        }
    }

    const size_t pbase = (size_t)idx * 16384;
#pragma unroll
    for (int mt = 0; mt < 2; ++mt) {
        int r0 = wm + mt * 16 + (lane >> 2);
#pragma unroll
        for (int nt = 0; nt < 8; ++nt) {
            int col = wn + nt * 8 + ((lane & 3) << 1);
            *(float2*)&g_P[pbase + (size_t)r0 * 128 + col]       = make_float2(acc[mt][nt][0], acc[mt][nt][1]);
            *(float2*)&g_P[pbase + (size_t)(r0 + 8) * 128 + col] = make_float2(acc[mt][nt][2], acc[mt][nt][3]);
        }
    }
#pragma unroll
    for (int j = 0; j < 8; ++j) zsm[tr * 128 + tu * 8 + j] = zacc[j];
    __syncthreads();
    if (tid < 128) {
        float s = 0.f;
#pragma unroll
        for (int g = 0; g < 16; ++g) s += zsm[g * 128 + tid];
        g_Zseg[idx * 128 + tid] = 512.f * s;
    }
}

// =====================================================================
// K3: inclusive prefix over seg (grid 256: bh x ugroup)
// =====================================================================
__global__ __launch_bounds__(256) void k_prefix()
{
    const int bh = blockIdx.x >> 3, ug = blockIdx.x & 7;
    const int tid = threadIdx.x;
    float acc[8] = {0.f,0.f,0.f,0.f,0.f,0.f,0.f,0.f};
    float zacc = 0.f;
    for (int seg = 0; seg < 16; ++seg) {
        const size_t base = ((size_t)bh * 16 + seg) * 16384;
#pragma unroll
        for (int uu = 0; uu < 8; ++uu) {
            int u = ug * 8 + uu;
            acc[uu] += g_P[base + u * 256 + tid];
            g_Memh[base + u * 256 + tid] = __float2half_rn(acc[uu]);
        }
        if (ug == 0 && tid < 128) {
            zacc += g_Zseg[(bh * 16 + seg) * 128 + tid];
            g_Z[(bh * 16 + seg) * 128 + tid] = zacc;
        }
    }
}

// =====================================================================
// K4: fp16 mma attention v4 — qt=32, register-resident Q/sq fragments.
// smem: Sc 4x8192=32768 | sAh 8192 | sB 32768 | ctl -> 74368
// =====================================================================
__global__ __launch_bounds__(256, 3) void k_attn_mma(const float* __restrict__ beta,
                                                     float* __restrict__ out)
{
    extern __shared__ __align__(16) char smraw[];
    char* sSc = smraw;                               // 32768: 4 tiles [32][128] fp16
    char* sAh = smraw + 32768;                       // 8192 (Q staging)
    char* sB  = smraw + 40960;                       // 32768 (dual 16K for K)
    float* zs  = (float*)(smraw + 73728);            // 128
    float* rs  = zs + 128;                           // 32
    const uint32_t aSc = smem_u32(sSc);
    const uint32_t aAh = smem_u32(sAh);
    const uint32_t aB = smem_u32(sB);

    const int idx = blockIdx.x;
    const int b = idx >> 8, seg = (idx >> 4) & 15, qt = idx & 15;
    const int tid = threadIdx.x, lane = tid & 31, wid = tid >> 5;
    const int qrow0 = b * 8192 + seg * 512 + qt * 32;
    const int krow0 = b * 8192 + seg * 512;
    const float bsig = 1.f / (1.f + __expf(-beta[0]));
    const float bsig8 = bsig * 0.125f, obsig8 = (1.f - bsig) * 0.125f;
    const float scale = 0.088388347648318447f;

    const int wr = (wid >> 2) * 16, wc = (wid & 3) * 16;
    const int wn4 = (wid & 3) * 32;
    const int rowA0 = wr + (lane & 15);
    const int unA = lane >> 4;
    const int rowBn = wc + (lane & 7);
    const int unB = (lane >> 3) & 1;
    const int rowKt = (lane & 7) + ((lane >> 3) & 1) * 8;
    const int srow = tid >> 3, spart = tid & 7;
    const int t4 = lane & 3;

    float facc[4][4];
#pragma unroll
    for (int nt = 0; nt < 4; ++nt)
#pragma unroll
        for (int q = 0; q < 4; ++q) facc[nt][q] = 0.f;

    for (int h = 0; h < 8; ++h) {
        const int hc = h * 128;
        __syncthreads();   // prev head done: all smem free
        // K chunk0 (64 rows) -> b0
#pragma unroll
        for (int it = 0; it < 4; ++it) {
            int i2 = it * 256 + tid;
            int r = i2 >> 4, u = i2 & 15;
            cpa16(aB + r * 256 + (swu(u, r) << 4),
                  g_Kh + (size_t)(krow0 + r) * 1024 + hc + u * 8);
        }
        CP_COMMIT();
        // Q (32 rows) -> sAh staging
#pragma unroll
        for (int it = 0; it < 2; ++it) {
            int i2 = it * 256 + tid;
            int r = i2 >> 4, u = i2 & 15;
            *(uint4*)(sAh + r * 256 + (swu(u, r) << 4)) =
                *(const uint4*)(g_Qh + (size_t)(qrow0 + r) * 1024 + hc + u * 8);
        }
        if (tid < 128)
            zs[tid] = g_Z[((size_t)(b * 8 + h) * 16 + seg) * 128 + tid];

        uint32_t qf[8][4];   // Q A-fragments, later overwritten with sq
        // ---- scores: 8 chunks of 64 keys, dual 16KB buffers; fp16 out ----
        for (int ch = 0; ch < 8; ++ch) {
            CP_WAIT0();
            __syncthreads();
            if (ch == 0) {
#pragma unroll
                for (int ks = 0; ks < 8; ++ks)
                    ldsm_x4(qf[ks][0], qf[ks][1], qf[ks][2], qf[ks][3],
                            aAh + rowA0 * 256 + (swu(ks * 2 + unA, rowA0) << 4));
            }
            if (ch < 7) {
                const uint32_t nb = aB + ((ch + 1) & 1) * 16384;
#pragma unroll
                for (int it = 0; it < 4; ++it) {
                    int i2 = it * 256 + tid;
                    int r = i2 >> 4, u = i2 & 15;
                    cpa16(nb + r * 256 + (swu(u, r) << 4),
                          g_Kh + (size_t)(krow0 + (ch + 1) * 64 + r) * 1024 + hc + u * 8);
                }
                CP_COMMIT();
            }
            const uint32_t Bb = aB + (ch & 1) * 16384;
            float acc[2][4];
#pragma unroll
            for (int nt = 0; nt < 2; ++nt)
#pragma unroll
                for (int q = 0; q < 4; ++q) acc[nt][q] = 0.f;
#pragma unroll
            for (int ks = 0; ks < 8; ++ks) {
                uint32_t bfr[2][2];
#pragma unroll
                for (int nt = 0; nt < 2; ++nt)
                    ldsm_x2(bfr[nt][0], bfr[nt][1],
                            Bb + (rowBn + nt * 8) * 256 + (swu(ks * 2 + unB, rowBn) << 4));
#pragma unroll
                for (int nt = 0; nt < 2; ++nt)
                    mma16816h(acc[nt][0], acc[nt][1], acc[nt][2], acc[nt][3],
                              qf[ks][0], qf[ks][1], qf[ks][2], qf[ks][3],
                              bfr[nt][0], bfr[nt][1]);
            }
            {
                int r0 = wr + (lane >> 2);
                char* tp = sSc + (ch >> 1) * 8192;
#pragma unroll
                for (int nt = 0; nt < 2; ++nt) {
                    int col = ((ch & 1) << 6) + wc + nt * 8 + ((lane & 3) << 1);
                    *(uint32_t*)(tp + r0 * 256 + (swu(col >> 3, r0) << 4) + ((col & 7) << 1)) =
                        packhf(acc[nt][0] * scale, acc[nt][1] * scale);
                    *(uint32_t*)(tp + (r0 + 8) * 256 + (swu(col >> 3, r0 + 8) << 4) + ((col & 7) << 1)) =
                        packhf(acc[nt][2] * scale, acc[nt][3] * scale);
                }
            }
        }
        __syncthreads();   // Sc complete; sB free
        // issue Mem (32KB) into sB; softmax hides the load
#pragma unroll
        for (int it = 0; it < 8; ++it) {
            int i2 = it * 256 + tid;
            int r = i2 >> 4, u = i2 & 15;
            size_t ms = ((size_t)(b * 8 + h) * 16 + seg) * 16384 + r * 128 + u * 8;
            cpa16(aB + r * 256 + (swu(u, r) << 4), g_Memh + ms);
        }
        CP_COMMIT();
        // ---- softmax in fp16 tiles ----
        {
            float m = -1e30f;
#pragma unroll 8
            for (int j = 0; j < 32; ++j) {
                int c = spart * 64 + (((j + spart * 4) & 31) << 1);
                int tile = c >> 7, cin = c & 127;
                __half2 hv = *(__half2*)(sSc + tile * 8192 + srow * 256 +
                                         (swu(cin >> 3, srow) << 4) + ((cin & 7) << 1));
                float2 f = __half22float2(hv);
                m = fmaxf(m, fmaxf(f.x, f.y));
            }
            m = fmaxf(m, __shfl_xor_sync(0xffffffffu, m, 1));
            m = fmaxf(m, __shfl_xor_sync(0xffffffffu, m, 2));
            m = fmaxf(m, __shfl_xor_sync(0xffffffffu, m, 4));
            float s = 0.f;
#pragma unroll 8
            for (int j = 0; j < 32; ++j) {
                int c = spart * 64 + (((j + spart * 4) & 31) << 1);
                int tile = c >> 7, cin = c & 127;
                char* ap = sSc + tile * 8192 + srow * 256 +
                           (swu(cin >> 3, srow) << 4) + ((cin & 7) << 1);
                float2 f = __half22float2(*(__half2*)ap);
                float e0 = __expf(f.x - m), e1 = __expf(f.y - m);
                s += e0 + e1;
                *(uint32_t*)ap = packhf(e0, e1);
            }
            s += __shfl_xor_sync(0xffffffffu, s, 1);
            s += __shfl_xor_sync(0xffffffffu, s, 2);
            s += __shfl_xor_sync(0xffffffffu, s, 4);
            if (spart == 0) rs[srow] = s;
        }
        // ---- sq = elup1(Q) in registers + den via fragment shuffle ----
        float da0 = 0.f, da1 = 0.f;
#pragma unroll
        for (int ks = 0; ks < 8; ++ks) {
#pragma unroll
            for (int p = 0; p < 4; ++p) {
                float2 f = __half22float2(*(__half2*)&qf[ks][p]);
                f.x = elup1(f.x); f.y = elup1(f.y);
                int kb = ks * 16 + t4 * 2 + ((p & 2) ? 8 : 0);
                float d = f.x * zs[kb] + f.y * zs[kb + 1];
                if ((p & 1) == 0) da0 += d; else da1 += d;
                qf[ks][p] = packhf(f.x, f.y);
            }
        }
        da0 += __shfl_xor_sync(0xffffffffu, da0, 1);
        da0 += __shfl_xor_sync(0xffffffffu, da0, 2);
        da1 += __shfl_xor_sync(0xffffffffu, da1, 1);
        da1 += __shfl_xor_sync(0xffffffffu, da1, 2);
        CP_WAIT0();
        __syncthreads();   // Mem + exp(P) visible
        // ---- retrieval: sq (regs) x Memh ----
        {
            float acc[4][4];
#pragma unroll
            for (int nt = 0; nt < 4; ++nt)
#pragma unroll
                for (int q = 0; q < 4; ++q) acc[nt][q] = 0.f;
#pragma unroll
            for (int ks = 0; ks < 8; ++ks) {
                uint32_t bfr[4][2];
                int rK = ks * 16 + rowKt;
#pragma unroll
                for (int nt = 0; nt < 4; ++nt)
                    ldsm_x2t(bfr[nt][0], bfr[nt][1],
                             aB + rK * 256 + (swu((wn4 >> 3) + nt, rK) << 4));
#pragma unroll
                for (int nt = 0; nt < 4; ++nt)
                    mma16816h(acc[nt][0], acc[nt][1], acc[nt][2], acc[nt][3],
                              qf[ks][0], qf[ks][1], qf[ks][2], qf[ks][3],
                              bfr[nt][0], bfr[nt][1]);
            }
            float m0 = bsig8 / (da0 + 1e-5f);
            float m1 = bsig8 / (da1 + 1e-5f);
#pragma unroll
            for (int nt = 0; nt < 4; ++nt) {
                facc[nt][0] += acc[nt][0] * m0;
                facc[nt][1] += acc[nt][1] * m0;
                facc[nt][2] += acc[nt][2] * m1;
                facc[nt][3] += acc[nt][3] * m1;
            }
        }
        // ---- PV: 4 chunks of 128 keys; A directly from Sc tiles ----
        float dacc[4][4];
#pragma unroll
        for (int nt = 0; nt < 4; ++nt)
#pragma unroll
            for (int q = 0; q < 4; ++q) dacc[nt][q] = 0.f;
        for (int ch = 0; ch < 4; ++ch) {
            __syncthreads();   // prev mma done: sB free
#pragma unroll
            for (int it = 0; it < 8; ++it) {
                int i2 = it * 256 + tid;
                int r = i2 >> 4, u = i2 & 15;
                cpa16(aB + r * 256 + (swu(u, r) << 4),
                      g_Vh + (size_t)(krow0 + ch * 128 + r) * 1024 + hc + u * 8);
            }
            CP_COMMIT();
            CP_WAIT0();
            __syncthreads();
            const uint32_t aP = aSc + ch * 8192;
#pragma unroll
            for (int ks = 0; ks < 8; ++ks) {
                uint32_t af[4], bfr[4][2];
                ldsm_x4(af[0], af[1], af[2], af[3],
                        aP + rowA0 * 256 + (swu(ks * 2 + unA, rowA0) << 4));
                int rK = ks * 16 + rowKt;
#pragma unroll
                for (int nt = 0; nt < 4; ++nt)
                    ldsm_x2t(bfr[nt][0], bfr[nt][1],
                             aB + rK * 256 + (swu((wn4 >> 3) + nt, rK) << 4));
#pragma unroll
                for (int nt = 0; nt < 4; ++nt)
                    mma16816h(dacc[nt][0], dacc[nt][1], dacc[nt][2], dacc[nt][3],
                              af[0], af[1], af[2], af[3], bfr[nt][0], bfr[nt][1]);
            }
        }
        {
            int r0 = wr + (lane >> 2);
            float d0 = obsig8 / rs[r0];
            float d1 = obsig8 / rs[r0 + 8];
#pragma unroll
            for (int nt = 0; nt < 4; ++nt) {
                facc[nt][0] += dacc[nt][0] * d0;
                facc[nt][1] += dacc[nt][1] * d0;
                facc[nt][2] += dacc[nt][2] * d1;
                facc[nt][3] += dacc[nt][3] * d1;
            }
        }
    }

    {
        int r0 = wr + (lane >> 2);
#pragma unroll
        for (int nt = 0; nt < 4; ++nt) {
            int col = wn4 + nt * 8 + ((lane & 3) << 1);
            *(float2*)&out[(size_t)(qrow0 + r0) * 128 + col]     = make_float2(facc[nt][0], facc[nt][1]);
            *(float2*)&out[(size_t)(qrow0 + r0 + 8) * 128 + col] = make_float2(facc[nt][2], facc[nt][3]);
        }
    }
}

// =====================================================================
extern "C" void kernel_launch(void* const* d_in, const int* in_sizes, int n_in,
                              void* d_out, int out_size)
{
    const float* x    = (const float*)d_in[0];
    const float* wq   = (const float*)d_in[1];
    const float* bq   = (const float*)d_in[2];
    const float* wk   = (const float*)d_in[3];
    const float* bk   = (const float*)d_in[4];
    const float* wv   = (const float*)d_in[5];
    const float* bv   = (const float*)d_in[6];
    const float* beta = (const float*)d_in[7];
    float* out = (float*)d_out;

    static int attr_set = 0;
    if (!attr_set) {
        cudaFuncSetAttribute(k_attn_mma, cudaFuncAttributeMaxDynamicSharedMemorySize, 74368);
        cudaFuncSetAttribute(k_proj_mma, cudaFuncAttributeMaxDynamicSharedMemorySize, 98304);
        cudaFuncSetAttribute(k_kvouter_mma, cudaFuncAttributeMaxDynamicSharedMemorySize, 73728);
        attr_set = 1;
    }

    k_splitX<<<32768, 256>>>(x);
    k_trW<<<dim3(32, 32, 3), 256>>>(wq, wk, wv);
    k_proj_mma<<<dim3(8, 256, 3), 512, 98304>>>(bq, bk, bv);
    k_kvouter_mma<<<512, 256, 73728>>>();
    k_prefix<<<256, 256>>>();
    k_attn_mma<<<1024, 256, 74368>>>(beta, out);
}